// round 9
// baseline (speedup 1.0000x reference)
#include <cuda_runtime.h>
#include <cuda_bf16.h>
#include <stdint.h>
#include <cstdint>
#include <math.h>

#define NB 2
#define NS 2048
#define NHID 1024
#define NHEADS 16
#define HDIM 64
#define MM (NB * NS)   // 4096

// ---------------- scratch (static device globals; no allocation) ----------
__device__ float g_cos[NS * 32];                 // rope tables [s][d]
__device__ float g_sin[NS * 32];

// split-bf16 operands
__device__ __nv_bfloat16 g_xh[MM * NHID];
__device__ __nv_bfloat16 g_xl[MM * NHID];
__device__ __nv_bfloat16 g_wh[4 * NHID * NHID];  // Wq,Wk,Wv,Wo
__device__ __nv_bfloat16 g_wl[4 * NHID * NHID];
__device__ __nv_bfloat16 g_aoh[MM * NHID];       // attention output, split
__device__ __nv_bfloat16 g_aol[MM * NHID];
// rope-rotated, split q/k (q pre-scaled by 0.125*log2e) + split v, [b,h,s,d]
__device__ __nv_bfloat16 g_qh[NB * NHEADS * NS * HDIM];
__device__ __nv_bfloat16 g_ql[NB * NHEADS * NS * HDIM];
__device__ __nv_bfloat16 g_kh[NB * NHEADS * NS * HDIM];
__device__ __nv_bfloat16 g_kl[NB * NHEADS * NS * HDIM];
__device__ __nv_bfloat16 g_vh[NB * NHEADS * NS * HDIM];
__device__ __nv_bfloat16 g_vl[NB * NHEADS * NS * HDIM];

// Q pre-scale: 0.125 * log2(e)  (softmax runs in exp2 domain)
#define QSCALE 0.18033688011112043f

// ---------------- mma.sync helpers (base sm_103 ISA) ------------------------
__device__ __forceinline__ uint32_t smem_u32(const void* p) {
    uint32_t a;
    asm("{ .reg .u64 t; cvta.to.shared.u64 t, %1; cvt.u32.u64 %0, t; }"
        : "=r"(a) : "l"(p));
    return a;
}
#define LDSM4(r0, r1, r2, r3, addr)                                          \
    asm volatile("ldmatrix.sync.aligned.m8n8.x4.shared.b16 {%0,%1,%2,%3}, [%4];" \
                 : "=r"(r0), "=r"(r1), "=r"(r2), "=r"(r3) : "r"(addr))
#define LDSM4T(r0, r1, r2, r3, addr)                                         \
    asm volatile(                                                            \
        "ldmatrix.sync.aligned.m8n8.x4.trans.shared.b16 {%0,%1,%2,%3}, [%4];" \
        : "=r"(r0), "=r"(r1), "=r"(r2), "=r"(r3) : "r"(addr))

__device__ __forceinline__ void mma_bf16(float* d, const uint32_t* a,
                                         const uint32_t* b) {
    asm volatile(
        "mma.sync.aligned.m16n8k16.row.col.f32.bf16.bf16.f32 "
        "{%0,%1,%2,%3}, {%4,%5,%6,%7}, {%8,%9}, {%0,%1,%2,%3};"
        : "+f"(d[0]), "+f"(d[1]), "+f"(d[2]), "+f"(d[3])
        : "r"(a[0]), "r"(a[1]), "r"(a[2]), "r"(a[3]), "r"(b[0]), "r"(b[1]));
}

__device__ __forceinline__ uint32_t pkbf(float a, float b) {
    __nv_bfloat162 t = __floats2bfloat162_rn(a, b);
    return *(uint32_t*)&t;
}
__device__ __forceinline__ void splitf(float v, __nv_bfloat16& h,
                                       __nv_bfloat16& l) {
    h = __float2bfloat16(v);
    l = __float2bfloat16(v - __bfloat162float(h));
}
__device__ __forceinline__ float ex2f(float x) {
    float y;
    asm("ex2.approx.ftz.f32 %0, %1;" : "=f"(y) : "f"(x));
    return y;
}

// ---------------- cp.async helpers -----------------------------------------
__device__ __forceinline__ void cpa16(uint32_t dst, const void* src) {
    asm volatile("cp.async.cg.shared.global [%0], [%1], 16;"
                 :: "r"(dst), "l"(src));
}
#define CP_COMMIT() asm volatile("cp.async.commit_group;" ::: "memory")
#define CP_WAIT1() asm volatile("cp.async.wait_group 1;" ::: "memory")
#define CP_WAIT2() asm volatile("cp.async.wait_group 2;" ::: "memory")
#define CP_WAIT0() asm volatile("cp.async.wait_group 0;" ::: "memory")

// ---------------------------------------------------------------------------
// Merged split conversion: x then Wq,Wk,Wv,Wo in one launch.
// ---------------------------------------------------------------------------
__global__ __launch_bounds__(256) void cvt_all(const float* __restrict__ x,
                                               const float* __restrict__ Wq,
                                               const float* __restrict__ Wk,
                                               const float* __restrict__ Wv,
                                               const float* __restrict__ Wo) {
    const size_t i = 4ull * ((size_t)blockIdx.x * blockDim.x + threadIdx.x);
    const size_t XN = (size_t)MM * NHID;     // 4M
    const size_t WN = (size_t)NHID * NHID;   // 1M (2^20)
    const float* s;
    __nv_bfloat16 *h, *l;
    size_t o;
    if (i < XN) {
        s = x;
        o = i;
        h = g_xh;
        l = g_xl;
    } else {
        const size_t j = i - XN;
        const int w = (int)(j >> 20);
        o = j & (WN - 1);
        s = (w == 0) ? Wq : (w == 1) ? Wk : (w == 2) ? Wv : Wo;
        h = g_wh + (size_t)w * WN;
        l = g_wl + (size_t)w * WN;
    }
    float4 v = *(const float4*)(s + o);
    __nv_bfloat16 h0, h1, h2, h3, l0, l1, l2, l3;
    splitf(v.x, h0, l0);
    splitf(v.y, h1, l1);
    splitf(v.z, h2, l2);
    splitf(v.w, h3, l3);
    *(__nv_bfloat162*)(h + o)     = __nv_bfloat162(h0, h1);
    *(__nv_bfloat162*)(h + o + 2) = __nv_bfloat162(h2, h3);
    *(__nv_bfloat162*)(l + o)     = __nv_bfloat162(l0, l1);
    *(__nv_bfloat162*)(l + o + 2) = __nv_bfloat162(l2, l3);
}

// ---------------------------------------------------------------------------
// RoPE cos/sin table (fp64, 65536 entries)
// ---------------------------------------------------------------------------
__global__ void rope_table() {
    const int t = blockIdx.x * blockDim.x + threadIdx.x;
    const int d = t & 31;
    const int s = t >> 5;
    const double inv = exp2(-(double)d * 0.41524101186092029);
    double sd, cd;
    sincos((double)s * inv, &sd, &cd);
    g_cos[t] = (float)cd;
    g_sin[t] = (float)sd;
}

// ---------------------------------------------------------------------------
// HMMA GEMM, 3-stage cp.async pipeline. C = A*W^T + bias, split-bf16 3-pass.
// PROJ=0: z=0/1 -> rope+split epilogue to g_qh/ql | g_kh/kl,
//         z=2   -> split V direct to g_vh/g_vl.
// PROJ=1: out projection from g_aoh/g_aol to Cout fp32.
// ---------------------------------------------------------------------------
#define KC2 32
#define NKC2 (NHID / KC2)   // 32
#define GSTR 40
#define GSTAGE (4 * 128 * GSTR)     // bf16 elems per stage
#define NSTG 3

template <int PROJ>
__global__ __launch_bounds__(256) void gemm_mma(const float* __restrict__ b0p,
                                                const float* __restrict__ b1p,
                                                const float* __restrict__ b2p,
                                                float* __restrict__ Cout) {
    extern __shared__ __nv_bfloat16 sb[];

    const int tid = threadIdx.x;
    const int wid = tid >> 5;
    const int lane = tid & 31;
    const int wr = wid >> 2;
    const int wc = wid & 3;

    const int n0 = blockIdx.x * 128;
    const int m0 = blockIdx.y * 128;
    const int z = PROJ ? 3 : blockIdx.z;

    const __nv_bfloat16* Ah = PROJ ? g_aoh : g_xh;
    const __nv_bfloat16* Al = PROJ ? g_aol : g_xl;
    const __nv_bfloat16* Wh = g_wh + (size_t)z * NHID * NHID;
    const __nv_bfloat16* Wl = g_wl + (size_t)z * NHID * NHID;
    const float* bias = PROJ ? b0p : (z == 0 ? b0p : (z == 1 ? b1p : b2p));

    const __nv_bfloat16* gsrc[4] = {Ah + (size_t)m0 * NHID, Al + (size_t)m0 * NHID,
                                    Wh + (size_t)n0 * NHID, Wl + (size_t)n0 * NHID};

    float acc[4][4][4];
#pragma unroll
    for (int mt = 0; mt < 4; mt++)
#pragma unroll
        for (int nt = 0; nt < 4; nt++)
#pragma unroll
            for (int e = 0; e < 4; e++) acc[mt][nt][e] = 0.0f;

    const uint32_t uS = smem_u32(sb);

    auto load_chunk = [&](int c, int stage) {
        const int kc = c * KC2;
        const uint32_t sdst = uS + 2u * (uint32_t)(stage * GSTAGE);
#pragma unroll
        for (int t = 0; t < 4; t++) {
            const uint32_t db = sdst + 2u * (uint32_t)(t * 128 * GSTR);
            const __nv_bfloat16* src = gsrc[t];
#pragma unroll
            for (int i = 0; i < 2; i++) {
                const int idx = tid + 256 * i;
                const int row = idx >> 2;
                const int seg = idx & 3;
                cpa16(db + 2u * (uint32_t)(row * GSTR + seg * 8),
                      src + (size_t)row * NHID + kc + seg * 8);
            }
        }
    };

    const int a_row = lane & 15;
    const int a_koff = (lane >> 4) * 8;
    const int b_row = (lane & 7) + ((lane >> 4) & 1) * 8;
    const int b_koff = ((lane >> 3) & 1) * 8;

    load_chunk(0, 0);
    CP_COMMIT();
    load_chunk(1, 1);
    CP_COMMIT();
    load_chunk(2, 2);
    CP_COMMIT();

    int stage = 0;
    for (int c = 0; c < NKC2; c++) {
        CP_WAIT2();
        __syncthreads();

        const uint32_t sstage = uS + 2u * (uint32_t)(stage * GSTAGE);
        const uint32_t uAh = sstage;
        const uint32_t uAl = sstage + 2u * (128 * GSTR);
        const uint32_t uWh = sstage + 2u * (2 * 128 * GSTR);
        const uint32_t uWl = sstage + 2u * (3 * 128 * GSTR);

#pragma unroll
        for (int k16 = 0; k16 < 2; k16++) {
            const int kel = k16 * 16;
            uint32_t ah[4][4], al[4][4], bh[8], bl[8];
#pragma unroll
            for (int mt = 0; mt < 4; mt++) {
                const uint32_t off =
                    2u * ((64 * wr + 16 * mt + a_row) * GSTR + kel + a_koff);
                LDSM4(ah[mt][0], ah[mt][1], ah[mt][2], ah[mt][3], uAh + off);
                LDSM4(al[mt][0], al[mt][1], al[mt][2], al[mt][3], uAl + off);
            }
#pragma unroll
            for (int np = 0; np < 2; np++) {
                const uint32_t off =
                    2u * ((32 * wc + 16 * np + b_row) * GSTR + kel + b_koff);
                LDSM4(bh[4 * np], bh[4 * np + 1], bh[4 * np + 2], bh[4 * np + 3],
                      uWh + off);
                LDSM4(bl[4 * np], bl[4 * np + 1], bl[4 * np + 2], bl[4 * np + 3],
                      uWl + off);
            }
#pragma unroll
            for (int mt = 0; mt < 4; mt++)
#pragma unroll
                for (int nt = 0; nt < 4; nt++) {
                    const uint32_t* bt_h = &bh[4 * (nt >> 1) + 2 * (nt & 1)];
                    const uint32_t* bt_l = &bl[4 * (nt >> 1) + 2 * (nt & 1)];
                    mma_bf16(acc[mt][nt], ah[mt], bt_h);
                    mma_bf16(acc[mt][nt], ah[mt], bt_l);
                    mma_bf16(acc[mt][nt], al[mt], bt_h);
                }
        }
        __syncthreads();
        if (c + 3 < NKC2) load_chunk(c + 3, stage);
        CP_COMMIT();
        stage = (stage == NSTG - 1) ? 0 : stage + 1;
    }

    // ---- epilogue ----
    const int mrow = (lane >> 2);
    const int ncol = (lane & 3) * 2;

    if (PROJ || z == 2) {
#pragma unroll
        for (int mt = 0; mt < 4; mt++) {
#pragma unroll
            for (int half = 0; half < 2; half++) {
                const int m = m0 + 64 * wr + 16 * mt + mrow + 8 * half;
#pragma unroll
                for (int nt = 0; nt < 4; nt++) {
                    const int n = n0 + 32 * wc + 8 * nt + ncol;
                    float v0 = acc[mt][nt][2 * half] + bias[n];
                    float v1 = acc[mt][nt][2 * half + 1] + bias[n + 1];
                    if (PROJ) {
                        *(float2*)&Cout[(size_t)m * NHID + n] =
                            make_float2(v0, v1);
                    } else {
                        const int bb = m >> 11;
                        const int s = m & (NS - 1);
                        const int h = n >> 6;
                        const int d = n & (HDIM - 1);
                        const size_t o =
                            (((size_t)(bb * NHEADS + h) * NS + s) * HDIM + d);
                        __nv_bfloat16 h0, h1, l0, l1;
                        splitf(v0, h0, l0);
                        splitf(v1, h1, l1);
                        *(__nv_bfloat162*)&g_vh[o] = __nv_bfloat162(h0, h1);
                        *(__nv_bfloat162*)&g_vl[o] = __nv_bfloat162(l0, l1);
                    }
                }
            }
        }
    } else {
        // ---- q/k: stage fp32 tile to smem, rope-rotate, split, store ----
        CP_WAIT0();
        __syncthreads();
        float* Dt = (float*)sb;   // [128][132]
        const int DTS = 132;
#pragma unroll
        for (int mt = 0; mt < 4; mt++)
#pragma unroll
            for (int half = 0; half < 2; half++) {
                const int row = 64 * wr + 16 * mt + mrow + 8 * half;
#pragma unroll
                for (int nt = 0; nt < 4; nt++) {
                    const int col = 32 * wc + 8 * nt + ncol;
                    Dt[row * DTS + col] =
                        acc[mt][nt][2 * half] + bias[n0 + col];
                    Dt[row * DTS + col + 1] =
                        acc[mt][nt][2 * half + 1] + bias[n0 + col + 1];
                }
            }
        __syncthreads();

        const int row = tid >> 1;
        const int hb = tid & 1;
        const int m = m0 + row;
        const int bb = m >> 11;
        const int s = m & (NS - 1);
        const int hidx = (n0 + hb * 64) >> 6;
        const float* srcr = &Dt[row * DTS + hb * 64];
        const float qsc = (z == 0) ? QSCALE : 1.0f;
        const size_t dsto = ((size_t)(bb * NHEADS + hidx) * NS + s) * HDIM;
        __nv_bfloat16* dh = (z == 0 ? g_qh : g_kh) + dsto;
        __nv_bfloat16* dl = (z == 0 ? g_ql : g_kl) + dsto;
#pragma unroll
        for (int dg = 0; dg < 8; dg++) {
            float4 x1 = *(const float4*)(srcr + dg * 4);
            float4 x2 = *(const float4*)(srcr + 32 + dg * 4);
            float4 c4 = *(const float4*)&g_cos[s * 32 + dg * 4];
            float4 s4 = *(const float4*)&g_sin[s * 32 + dg * 4];
            float4 r1, r2;
            r1.x = (x1.x * c4.x - x2.x * s4.x) * qsc;
            r2.x = (x2.x * c4.x + x1.x * s4.x) * qsc;
            r1.y = (x1.y * c4.y - x2.y * s4.y) * qsc;
            r2.y = (x2.y * c4.y + x1.y * s4.y) * qsc;
            r1.z = (x1.z * c4.z - x2.z * s4.z) * qsc;
            r2.z = (x2.z * c4.z + x1.z * s4.z) * qsc;
            r1.w = (x1.w * c4.w - x2.w * s4.w) * qsc;
            r2.w = (x2.w * c4.w + x1.w * s4.w) * qsc;
            __nv_bfloat16 h0, h1, h2, h3, l0, l1, l2, l3;
            splitf(r1.x, h0, l0); splitf(r1.y, h1, l1);
            splitf(r1.z, h2, l2); splitf(r1.w, h3, l3);
            *(__nv_bfloat162*)(dh + dg * 4)     = __nv_bfloat162(h0, h1);
            *(__nv_bfloat162*)(dh + dg * 4 + 2) = __nv_bfloat162(h2, h3);
            *(__nv_bfloat162*)(dl + dg * 4)     = __nv_bfloat162(l0, l1);
            *(__nv_bfloat162*)(dl + dg * 4 + 2) = __nv_bfloat162(l2, l3);
            splitf(r2.x, h0, l0); splitf(r2.y, h1, l1);
            splitf(r2.z, h2, l2); splitf(r2.w, h3, l3);
            *(__nv_bfloat162*)(dh + 32 + dg * 4)     = __nv_bfloat162(h0, h1);
            *(__nv_bfloat162*)(dh + 32 + dg * 4 + 2) = __nv_bfloat162(h2, h3);
            *(__nv_bfloat162*)(dl + 32 + dg * 4)     = __nv_bfloat162(l0, l1);
            *(__nv_bfloat162*)(dl + 32 + dg * 4 + 2) = __nv_bfloat162(l2, l3);
        }
    }
}

// ---------------------------------------------------------------------------
// Flash attention via HMMA, cp.async double-buffered K/V, exp2-domain softmax.
// CTA = (b, h, 128-row q tile); 8 warps x 16 q-rows; K/V tiles of 64.
// ---------------------------------------------------------------------------
#define BQ 128
#define BK 64
#define KSTR 72
#define KVSTAGE (4 * 64 * KSTR)   // bf16 elems per stage (kh,kl,vh,vl)

__global__ __launch_bounds__(256, 2) void attn_mma() {
    extern __shared__ __nv_bfloat16 sa_[];
    __nv_bfloat16* sQh = sa_;                    // 128*72
    __nv_bfloat16* sQl = sa_ + 128 * KSTR;
    __nv_bfloat16* sKV = sa_ + 2 * 128 * KSTR;   // 2 stages

    const int qt = (int)(gridDim.x - 1) - (int)blockIdx.x;   // big tiles first
    const int h = blockIdx.y;
    const int b = blockIdx.z;
    const int tid = threadIdx.x;
    const int wid = tid >> 5;
    const int lane = tid & 31;

    const size_t bhoff = (size_t)(b * NHEADS + h) * NS * HDIM;
    const __nv_bfloat16* kvsrc[4] = {g_kh + bhoff, g_kl + bhoff,
                                     g_vh + bhoff, g_vl + bhoff};

    const uint32_t uQh = smem_u32(sQh);
    const uint32_t uQl = smem_u32(sQl);
    const uint32_t uKV = smem_u32(sKV);

    auto load_tile = [&](int kt, int stage) {
        const uint32_t sdst = uKV + 2u * (uint32_t)(stage * KVSTAGE);
        const size_t gb = (size_t)kt * BK * HDIM;
#pragma unroll
        for (int t = 0; t < 4; t++) {
            const __nv_bfloat16* src = kvsrc[t] + gb;
            const uint32_t db = sdst + 2u * (uint32_t)(t * 64 * KSTR);
#pragma unroll
            for (int i = 0; i < 2; i++) {
                const int idx = tid + 256 * i;
                const int row = idx >> 3;
                const int seg = idx & 7;
                cpa16(db + 2u * (uint32_t)(row * KSTR + seg * 8),
                      src + row * HDIM + seg * 8);
            }
        }
    };

    // ---- load Q tile (pre-scaled incl log2e, pre-split) ----
    {
        const int row = tid >> 1;
        const int c0 = (tid & 1) * 32;
        const __nv_bfloat16* sh = g_qh + bhoff + ((size_t)qt * BQ + row) * HDIM + c0;
        const __nv_bfloat16* sl = g_ql + bhoff + ((size_t)qt * BQ + row) * HDIM + c0;
        __nv_bfloat16* dh = sQh + row * KSTR + c0;
        __nv_bfloat16* dl = sQl + row * KSTR + c0;
#pragma unroll
        for (int j = 0; j < 4; j++) {
            *(uint4*)(dh + 8 * j) = *(const uint4*)(sh + 8 * j);
            *(uint4*)(dl + 8 * j) = *(const uint4*)(sl + 8 * j);
        }
    }

    const int a_row = lane & 15;
    const int a_koff = (lane >> 4) * 8;
    const int b_row = (lane & 7) + ((lane >> 4) & 1) * 8;
    const int b_koff = ((lane >> 3) & 1) * 8;
    const int v_kr = (lane & 7) + 8 * ((lane >> 3) & 1);
    const int v_nc = 8 * (lane >> 4);

    float o[8][4];
#pragma unroll
    for (int j = 0; j < 8; j++)
#pragma unroll
        for (int e = 0; e < 4; e++) o[j][e] = 0.0f;
    float mi0 = -1e30f, mi1 = -1e30f, li0 = 0.0f, li1 = 0.0f;

    const int qrow0 = qt * BQ + wid * 16 + (lane >> 2);
    const int qrow1 = qrow0 + 8;
    const int kcbase = 2 * (lane & 3);

    const int ktmax = 2 * qt + 1;   // >= 1 always
    load_tile(0, 0);
    CP_COMMIT();
    load_tile(1, 1);
    CP_COMMIT();

    for (int kt = 0; kt <= ktmax; kt++) {
        CP_WAIT1();
        __syncthreads();

        const uint32_t sstage = uKV + 2u * (uint32_t)((kt & 1) * KVSTAGE);
        const uint32_t uKh = sstage;
        const uint32_t uKl = sstage + 2u * (64 * KSTR);
        const uint32_t uVh = sstage + 2u * (2 * 64 * KSTR);
        const uint32_t uVl = sstage + 2u * (3 * 64 * KSTR);

        // ---- S = Q @ K^T (exp2 domain) ----
        float s[8][4];
#pragma unroll
        for (int j = 0; j < 8; j++)
#pragma unroll
            for (int e = 0; e < 4; e++) s[j][e] = 0.0f;

#pragma unroll
        for (int k16 = 0; k16 < 4; k16++) {
            const int kel = 16 * k16;
            uint32_t qh[4], ql[4], kh[4][4], kl[4][4];
            {
                const uint32_t off =
                    2u * ((wid * 16 + a_row) * KSTR + kel + a_koff);
                LDSM4(qh[0], qh[1], qh[2], qh[3], uQh + off);
                LDSM4(ql[0], ql[1], ql[2], ql[3], uQl + off);
            }
#pragma unroll
            for (int ng = 0; ng < 4; ng++) {
                const uint32_t off =
                    2u * ((16 * ng + b_row) * KSTR + kel + b_koff);
                LDSM4(kh[ng][0], kh[ng][1], kh[ng][2], kh[ng][3], uKh + off);
                LDSM4(kl[ng][0], kl[ng][1], kl[ng][2], kl[ng][3], uKl + off);
            }
#pragma unroll
            for (int j = 0; j < 8; j++) {
                const uint32_t* bh = &kh[j >> 1][2 * (j & 1)];
                const uint32_t* bl = &kl[j >> 1][2 * (j & 1)];
                mma_bf16(s[j], qh, bh);
                mma_bf16(s[j], qh, bl);
                mma_bf16(s[j], ql, bh);
            }
        }

        // ---- causal mask ----
        if (kt * BK + BK - 1 > qrow0) {
#pragma unroll
            for (int j = 0; j < 8; j++) {
                const int kc = kt * BK + 8 * j + kcbase;
                if (kc > qrow0) s[j][0] = -1e30f;
                if (kc + 1 > qrow0) s[j][1] = -1e30f;
            }
        }
        if (kt * BK + BK - 1 > qrow1) {
#pragma unroll
            for (int j = 0; j < 8; j++) {
                const int kc = kt * BK + 8 * j + kcbase;
                if (kc > qrow1) s[j][2] = -1e30f;
                if (kc + 1 > qrow1) s[j][3] = -1e30f;
            }
        }

        // ---- online softmax (exp2) ----
        float mx0 = s[0][0], mx1 = s[0][2];
#pragma unroll
        for (int j = 0; j < 8; j++) {
            mx0 = fmaxf(mx0, fmaxf(s[j][0], s[j][1]));
            mx1 = fmaxf(mx1, fmaxf(s[j][2], s[j][3]));
        }
        mx0 = fmaxf(mx0, __shfl_xor_sync(0xffffffffu, mx0, 1));
        mx0 = fmaxf(mx0, __shfl_xor_sync(0xffffffffu, mx0, 2));
        mx1 = fmaxf(mx1, __shfl_xor_sync(0xffffffffu, mx1, 1));
        mx1 = fmaxf(mx1, __shfl_xor_sync(0xffffffffu, mx1, 2));

        const float mn0 = fmaxf(mi0, mx0);
        const float mn1 = fmaxf(mi1, mx1);
        const float cr0 = ex2f(mi0 - mn0);
        const float cr1 = ex2f(mi1 - mn1);

        float rs0 = 0.0f, rs1 = 0.0f;
#pragma unroll
        for (int j = 0; j < 8; j++) {
            s[j][0] = ex2f(s[j][0] - mn0);
            s[j][1] = ex2f(s[j][1] - mn0);
            s[j][2] = ex2f(s[j][2] - mn1);
            s[j][3] = ex2f(s[j][3] - mn1);
            rs0 += s[j][0] + s[j][1];
            rs1 += s[j][2] + s[j][3];
        }
        rs0 += __shfl_xor_sync(0xffffffffu, rs0, 1);
        rs0 += __shfl_xor_sync(0xffffffffu, rs0, 2);
        rs1 += __shfl_xor_sync(0xffffffffu, rs1, 1);
        rs1 += __shfl_xor_sync(0xffffffffu, rs1, 2);
        li0 = li0 * cr0 + rs0;
        li1 = li1 * cr1 + rs1;
        mi0 = mn0;
        mi1 = mn1;

#pragma unroll
        for (int j = 0; j < 8; j++) {
            o[j][0] *= cr0;
            o[j][1] *= cr0;
            o[j][2] *= cr1;
            o[j][3] *= cr1;
        }

        // ---- O += P @ V ----
#pragma unroll
        for (int t = 0; t < 4; t++) {
            uint32_t ph[4], pl[4];
            {
                const float* p0 = s[2 * t];
                const float* p1 = s[2 * t + 1];
                __nv_bfloat16 hh, ll;
                float hf[8], lf[8];
#pragma unroll
                for (int e = 0; e < 4; e++) {
                    splitf(p0[e], hh, ll);
                    hf[e] = __bfloat162float(hh);
                    lf[e] = __bfloat162float(ll);
                    splitf(p1[e], hh, ll);
                    hf[4 + e] = __bfloat162float(hh);
                    lf[4 + e] = __bfloat162float(ll);
                }
                ph[0] = pkbf(hf[0], hf[1]);
                ph[1] = pkbf(hf[2], hf[3]);
                ph[2] = pkbf(hf[4], hf[5]);
                ph[3] = pkbf(hf[6], hf[7]);
                pl[0] = pkbf(lf[0], lf[1]);
                pl[1] = pkbf(lf[2], lf[3]);
                pl[2] = pkbf(lf[4], lf[5]);
                pl[3] = pkbf(lf[6], lf[7]);
            }
            const int kel = 16 * t;
            uint32_t vh[4][4], vl[4][4];
#pragma unroll
            for (int ng = 0; ng < 4; ng++) {
                const uint32_t off =
                    2u * ((kel + v_kr) * KSTR + 16 * ng + v_nc);
                LDSM4T(vh[ng][0], vh[ng][1], vh[ng][2], vh[ng][3], uVh + off);
                LDSM4T(vl[ng][0], vl[ng][1], vl[ng][2], vl[ng][3], uVl + off);
            }
#pragma unroll
            for (int j = 0; j < 8; j++) {
                const uint32_t* bvh = &vh[j >> 1][2 * (j & 1)];
                const uint32_t* bvl = &vl[j >> 1][2 * (j & 1)];
                mma_bf16(o[j], ph, bvh);
                mma_bf16(o[j], ph, bvl);
                mma_bf16(o[j], pl, bvh);
            }
        }

        __syncthreads();
        if (kt + 2 <= ktmax) load_tile(kt + 2, kt & 1);
        CP_COMMIT();
    }

    // ---- normalize + store SPLIT to g_aoh/g_aol [b, s, h*64+d] ----
    const float inv0 = 1.0f / li0;
    const float inv1 = 1.0f / li1;
    const size_t o0 = ((size_t)b * NS + qrow0) * NHID + h * HDIM;
    const size_t o1 = ((size_t)b * NS + qrow1) * NHID + h * HDIM;
#pragma unroll
    for (int j = 0; j < 8; j++) {
        const int d = 8 * j + kcbase;
        __nv_bfloat16 h0, h1, l0, l1;
        splitf(o[j][0] * inv0, h0, l0);
        splitf(o[j][1] * inv0, h1, l1);
        *(__nv_bfloat162*)&g_aoh[o0 + d] = __nv_bfloat162(h0, h1);
        *(__nv_bfloat162*)&g_aol[o0 + d] = __nv_bfloat162(l0, l1);
        splitf(o[j][2] * inv1, h0, l0);
        splitf(o[j][3] * inv1, h1, l1);
        *(__nv_bfloat162*)&g_aoh[o1 + d] = __nv_bfloat162(h0, h1);
        *(__nv_bfloat162*)&g_aol[o1 + d] = __nv_bfloat162(l0, l1);
    }
}

// ---------------------------------------------------------------------------
extern "C" void kernel_launch(void* const* d_in, const int* in_sizes, int n_in,
                              void* d_out, int out_size) {
    const float* x  = (const float*)d_in[0];
    const float* Wq = (const float*)d_in[1];
    const float* bq = (const float*)d_in[2];
    const float* Wk = (const float*)d_in[3];
    const float* bk = (const float*)d_in[4];
    const float* Wv = (const float*)d_in[5];
    const float* bv = (const float*)d_in[6];
    const float* Wo = (const float*)d_in[7];
    const float* bo = (const float*)d_in[8];
    float* out = (float*)d_out;

    const int GEMM_SMEM = NSTG * GSTAGE * 2;                    // 122880 B
    const int ATTN_SMEM = (2 * 128 * KSTR + 2 * KVSTAGE) * 2;   // 110592 B
    cudaFuncSetAttribute(gemm_mma<0>, cudaFuncAttributeMaxDynamicSharedMemorySize,
                         GEMM_SMEM);
    cudaFuncSetAttribute(gemm_mma<1>, cudaFuncAttributeMaxDynamicSharedMemorySize,
                         GEMM_SMEM);
    cudaFuncSetAttribute(attn_mma, cudaFuncAttributeMaxDynamicSharedMemorySize,
                         ATTN_SMEM);

    rope_table<<<NS * 32 / 256, 256>>>();

    // 4M (x) + 4x1M (weights) elems, 4 per thread
    cvt_all<<<(MM * NHID + 4 * NHID * NHID) / 1024, 256>>>(x, Wq, Wk, Wv, Wo);

    gemm_mma<0><<<dim3(NHID / 128, MM / 128, 3), 256, GEMM_SMEM>>>(bq, bk, bv,
                                                                   nullptr);

    attn_mma<<<dim3(NS / BQ, NHEADS, NB), 256, ATTN_SMEM>>>();

    gemm_mma<1><<<dim3(NHID / 128, MM / 128), 256, GEMM_SMEM>>>(bo, nullptr,
                                                                nullptr, out);
}

// round 10
// speedup vs baseline: 1.0888x; 1.0888x over previous
#include <cuda_runtime.h>
#include <cuda_bf16.h>
#include <stdint.h>
#include <cstdint>
#include <math.h>

#define NB 2
#define NS 2048
#define NHID 1024
#define NHEADS 16
#define HDIM 64
#define MM (NB * NS)   // 4096

// ---------------- scratch (static device globals; no allocation) ----------
__device__ float g_cos[NS * 32];                 // rope tables [s][d]
__device__ float g_sin[NS * 32];

// split-bf16 operands
__device__ __nv_bfloat16 g_xh[MM * NHID];
__device__ __nv_bfloat16 g_xl[MM * NHID];
__device__ __nv_bfloat16 g_wh[4 * NHID * NHID];  // Wq,Wk,Wv,Wo
__device__ __nv_bfloat16 g_wl[4 * NHID * NHID];
__device__ __nv_bfloat16 g_aoh[MM * NHID];       // attention output, split
__device__ __nv_bfloat16 g_aol[MM * NHID];
// rope-rotated, split q/k (q pre-scaled by 0.125*log2e) + split v, [b,h,s,d]
__device__ __nv_bfloat16 g_qh[NB * NHEADS * NS * HDIM];
__device__ __nv_bfloat16 g_ql[NB * NHEADS * NS * HDIM];
__device__ __nv_bfloat16 g_kh[NB * NHEADS * NS * HDIM];
__device__ __nv_bfloat16 g_kl[NB * NHEADS * NS * HDIM];
__device__ __nv_bfloat16 g_vh[NB * NHEADS * NS * HDIM];
__device__ __nv_bfloat16 g_vl[NB * NHEADS * NS * HDIM];

// Q pre-scale: 0.125 * log2(e)  (softmax runs in exp2 domain)
#define QSCALE 0.18033688011112043f

// ---------------- mma.sync helpers (base sm_103 ISA) ------------------------
__device__ __forceinline__ uint32_t smem_u32(const void* p) {
    uint32_t a;
    asm("{ .reg .u64 t; cvta.to.shared.u64 t, %1; cvt.u32.u64 %0, t; }"
        : "=r"(a) : "l"(p));
    return a;
}
#define LDSM4(r0, r1, r2, r3, addr)                                          \
    asm volatile("ldmatrix.sync.aligned.m8n8.x4.shared.b16 {%0,%1,%2,%3}, [%4];" \
                 : "=r"(r0), "=r"(r1), "=r"(r2), "=r"(r3) : "r"(addr))
#define LDSM4T(r0, r1, r2, r3, addr)                                         \
    asm volatile(                                                            \
        "ldmatrix.sync.aligned.m8n8.x4.trans.shared.b16 {%0,%1,%2,%3}, [%4];" \
        : "=r"(r0), "=r"(r1), "=r"(r2), "=r"(r3) : "r"(addr))

__device__ __forceinline__ void mma_bf16(float* d, const uint32_t* a,
                                         const uint32_t* b) {
    asm volatile(
        "mma.sync.aligned.m16n8k16.row.col.f32.bf16.bf16.f32 "
        "{%0,%1,%2,%3}, {%4,%5,%6,%7}, {%8,%9}, {%0,%1,%2,%3};"
        : "+f"(d[0]), "+f"(d[1]), "+f"(d[2]), "+f"(d[3])
        : "r"(a[0]), "r"(a[1]), "r"(a[2]), "r"(a[3]), "r"(b[0]), "r"(b[1]));
}

__device__ __forceinline__ uint32_t pkbf(float a, float b) {
    __nv_bfloat162 t = __floats2bfloat162_rn(a, b);
    return *(uint32_t*)&t;
}
__device__ __forceinline__ void splitf(float v, __nv_bfloat16& h,
                                       __nv_bfloat16& l) {
    h = __float2bfloat16(v);
    l = __float2bfloat16(v - __bfloat162float(h));
}
__device__ __forceinline__ float ex2f(float x) {
    float y;
    asm("ex2.approx.ftz.f32 %0, %1;" : "=f"(y) : "f"(x));
    return y;
}

// ---------------- cp.async helpers -----------------------------------------
__device__ __forceinline__ void cpa16(uint32_t dst, const void* src) {
    asm volatile("cp.async.cg.shared.global [%0], [%1], 16;"
                 :: "r"(dst), "l"(src));
}
#define CP_COMMIT() asm volatile("cp.async.commit_group;" ::: "memory")
#define CP_WAIT1() asm volatile("cp.async.wait_group 1;" ::: "memory")
#define CP_WAIT0() asm volatile("cp.async.wait_group 0;" ::: "memory")

// ---------------------------------------------------------------------------
// Merged split conversion: x then Wq,Wk,Wv,Wo in one launch.
// ---------------------------------------------------------------------------
__global__ __launch_bounds__(256) void cvt_all(const float* __restrict__ x,
                                               const float* __restrict__ Wq,
                                               const float* __restrict__ Wk,
                                               const float* __restrict__ Wv,
                                               const float* __restrict__ Wo) {
    const size_t i = 4ull * ((size_t)blockIdx.x * blockDim.x + threadIdx.x);
    const size_t XN = (size_t)MM * NHID;     // 4M
    const size_t WN = (size_t)NHID * NHID;   // 1M (2^20)
    const float* s;
    __nv_bfloat16 *h, *l;
    size_t o;
    if (i < XN) {
        s = x;
        o = i;
        h = g_xh;
        l = g_xl;
    } else {
        const size_t j = i - XN;
        const int w = (int)(j >> 20);
        o = j & (WN - 1);
        s = (w == 0) ? Wq : (w == 1) ? Wk : (w == 2) ? Wv : Wo;
        h = g_wh + (size_t)w * WN;
        l = g_wl + (size_t)w * WN;
    }
    float4 v = *(const float4*)(s + o);
    __nv_bfloat16 h0, h1, h2, h3, l0, l1, l2, l3;
    splitf(v.x, h0, l0);
    splitf(v.y, h1, l1);
    splitf(v.z, h2, l2);
    splitf(v.w, h3, l3);
    *(__nv_bfloat162*)(h + o)     = __nv_bfloat162(h0, h1);
    *(__nv_bfloat162*)(h + o + 2) = __nv_bfloat162(h2, h3);
    *(__nv_bfloat162*)(l + o)     = __nv_bfloat162(l0, l1);
    *(__nv_bfloat162*)(l + o + 2) = __nv_bfloat162(l2, l3);
}

// ---------------------------------------------------------------------------
// RoPE cos/sin table (fp64, 65536 entries)
// ---------------------------------------------------------------------------
__global__ void rope_table() {
    const int t = blockIdx.x * blockDim.x + threadIdx.x;
    const int d = t & 31;
    const int s = t >> 5;
    const double inv = exp2(-(double)d * 0.41524101186092029);
    double sd, cd;
    sincos((double)s * inv, &sd, &cd);
    g_cos[t] = (float)cd;
    g_sin[t] = (float)sd;
}

// ---------------------------------------------------------------------------
// HMMA GEMM, 2-stage cp.async pipeline (2 CTAs/SM). C = A*W^T + bias,
// split-bf16 3-pass.
// PROJ=0: z=0/1 -> rope+split epilogue to g_qh/ql | g_kh/kl,
//         z=2   -> split V direct to g_vh/g_vl.
// PROJ=1: out projection from g_aoh/g_aol to Cout fp32.
// ---------------------------------------------------------------------------
#define KC2 32
#define NKC2 (NHID / KC2)   // 32
#define GSTR 40
#define GSTAGE (4 * 128 * GSTR)     // bf16 elems per stage

template <int PROJ>
__global__ __launch_bounds__(256) void gemm_mma(const float* __restrict__ b0p,
                                                const float* __restrict__ b1p,
                                                const float* __restrict__ b2p,
                                                float* __restrict__ Cout) {
    extern __shared__ __nv_bfloat16 sb[];

    const int tid = threadIdx.x;
    const int wid = tid >> 5;
    const int lane = tid & 31;
    const int wr = wid >> 2;
    const int wc = wid & 3;

    const int n0 = blockIdx.x * 128;
    const int m0 = blockIdx.y * 128;
    const int z = PROJ ? 3 : blockIdx.z;

    const __nv_bfloat16* Ah = PROJ ? g_aoh : g_xh;
    const __nv_bfloat16* Al = PROJ ? g_aol : g_xl;
    const __nv_bfloat16* Wh = g_wh + (size_t)z * NHID * NHID;
    const __nv_bfloat16* Wl = g_wl + (size_t)z * NHID * NHID;
    const float* bias = PROJ ? b0p : (z == 0 ? b0p : (z == 1 ? b1p : b2p));

    const __nv_bfloat16* gsrc[4] = {Ah + (size_t)m0 * NHID, Al + (size_t)m0 * NHID,
                                    Wh + (size_t)n0 * NHID, Wl + (size_t)n0 * NHID};

    float acc[4][4][4];
#pragma unroll
    for (int mt = 0; mt < 4; mt++)
#pragma unroll
        for (int nt = 0; nt < 4; nt++)
#pragma unroll
            for (int e = 0; e < 4; e++) acc[mt][nt][e] = 0.0f;

    const uint32_t uS = smem_u32(sb);

    auto load_chunk = [&](int c, int stage) {
        const int kc = c * KC2;
        const uint32_t sdst = uS + 2u * (uint32_t)(stage * GSTAGE);
#pragma unroll
        for (int t = 0; t < 4; t++) {
            const uint32_t db = sdst + 2u * (uint32_t)(t * 128 * GSTR);
            const __nv_bfloat16* src = gsrc[t];
#pragma unroll
            for (int i = 0; i < 2; i++) {
                const int idx = tid + 256 * i;
                const int row = idx >> 2;
                const int seg = idx & 3;
                cpa16(db + 2u * (uint32_t)(row * GSTR + seg * 8),
                      src + (size_t)row * NHID + kc + seg * 8);
            }
        }
    };

    const int a_row = lane & 15;
    const int a_koff = (lane >> 4) * 8;
    const int b_row = (lane & 7) + ((lane >> 4) & 1) * 8;
    const int b_koff = ((lane >> 3) & 1) * 8;

    load_chunk(0, 0);
    CP_COMMIT();
    load_chunk(1, 1);
    CP_COMMIT();

    for (int c = 0; c < NKC2; c++) {
        CP_WAIT1();
        __syncthreads();

        const uint32_t sstage = uS + 2u * (uint32_t)((c & 1) * GSTAGE);
        const uint32_t uAh = sstage;
        const uint32_t uAl = sstage + 2u * (128 * GSTR);
        const uint32_t uWh = sstage + 2u * (2 * 128 * GSTR);
        const uint32_t uWl = sstage + 2u * (3 * 128 * GSTR);

#pragma unroll
        for (int k16 = 0; k16 < 2; k16++) {
            const int kel = k16 * 16;
            uint32_t ah[4][4], al[4][4], bh[8], bl[8];
#pragma unroll
            for (int mt = 0; mt < 4; mt++) {
                const uint32_t off =
                    2u * ((64 * wr + 16 * mt + a_row) * GSTR + kel + a_koff);
                LDSM4(ah[mt][0], ah[mt][1], ah[mt][2], ah[mt][3], uAh + off);
                LDSM4(al[mt][0], al[mt][1], al[mt][2], al[mt][3], uAl + off);
            }
#pragma unroll
            for (int np = 0; np < 2; np++) {
                const uint32_t off =
                    2u * ((32 * wc + 16 * np + b_row) * GSTR + kel + b_koff);
                LDSM4(bh[4 * np], bh[4 * np + 1], bh[4 * np + 2], bh[4 * np + 3],
                      uWh + off);
                LDSM4(bl[4 * np], bl[4 * np + 1], bl[4 * np + 2], bl[4 * np + 3],
                      uWl + off);
            }
#pragma unroll
            for (int mt = 0; mt < 4; mt++)
#pragma unroll
                for (int nt = 0; nt < 4; nt++) {
                    const uint32_t* bt_h = &bh[4 * (nt >> 1) + 2 * (nt & 1)];
                    const uint32_t* bt_l = &bl[4 * (nt >> 1) + 2 * (nt & 1)];
                    mma_bf16(acc[mt][nt], ah[mt], bt_h);
                    mma_bf16(acc[mt][nt], ah[mt], bt_l);
                    mma_bf16(acc[mt][nt], al[mt], bt_h);
                }
        }
        __syncthreads();
        if (c + 2 < NKC2) load_chunk(c + 2, c & 1);
        CP_COMMIT();
    }

    // ---- epilogue ----
    const int mrow = (lane >> 2);
    const int ncol = (lane & 3) * 2;

    if (PROJ || z == 2) {
#pragma unroll
        for (int mt = 0; mt < 4; mt++) {
#pragma unroll
            for (int half = 0; half < 2; half++) {
                const int m = m0 + 64 * wr + 16 * mt + mrow + 8 * half;
#pragma unroll
                for (int nt = 0; nt < 4; nt++) {
                    const int n = n0 + 32 * wc + 8 * nt + ncol;
                    float v0 = acc[mt][nt][2 * half] + bias[n];
                    float v1 = acc[mt][nt][2 * half + 1] + bias[n + 1];
                    if (PROJ) {
                        *(float2*)&Cout[(size_t)m * NHID + n] =
                            make_float2(v0, v1);
                    } else {
                        const int bb = m >> 11;
                        const int s = m & (NS - 1);
                        const int h = n >> 6;
                        const int d = n & (HDIM - 1);
                        const size_t o =
                            (((size_t)(bb * NHEADS + h) * NS + s) * HDIM + d);
                        __nv_bfloat16 h0, h1, l0, l1;
                        splitf(v0, h0, l0);
                        splitf(v1, h1, l1);
                        *(__nv_bfloat162*)&g_vh[o] = __nv_bfloat162(h0, h1);
                        *(__nv_bfloat162*)&g_vl[o] = __nv_bfloat162(l0, l1);
                    }
                }
            }
        }
    } else {
        // ---- q/k: stage fp32 tile to smem, rope-rotate, split, store ----
        CP_WAIT0();
        __syncthreads();
        float* Dt = (float*)sb;   // [128][132] floats = 67584 B <= 80 KB
        const int DTS = 132;
#pragma unroll
        for (int mt = 0; mt < 4; mt++)
#pragma unroll
            for (int half = 0; half < 2; half++) {
                const int row = 64 * wr + 16 * mt + mrow + 8 * half;
#pragma unroll
                for (int nt = 0; nt < 4; nt++) {
                    const int col = 32 * wc + 8 * nt + ncol;
                    Dt[row * DTS + col] =
                        acc[mt][nt][2 * half] + bias[n0 + col];
                    Dt[row * DTS + col + 1] =
                        acc[mt][nt][2 * half + 1] + bias[n0 + col + 1];
                }
            }
        __syncthreads();

        const int row = tid >> 1;
        const int hb = tid & 1;
        const int m = m0 + row;
        const int bb = m >> 11;
        const int s = m & (NS - 1);
        const int hidx = (n0 + hb * 64) >> 6;
        const float* srcr = &Dt[row * DTS + hb * 64];
        const float qsc = (z == 0) ? QSCALE : 1.0f;
        const size_t dsto = ((size_t)(bb * NHEADS + hidx) * NS + s) * HDIM;
        __nv_bfloat16* dh = (z == 0 ? g_qh : g_kh) + dsto;
        __nv_bfloat16* dl = (z == 0 ? g_ql : g_kl) + dsto;
#pragma unroll
        for (int dg = 0; dg < 8; dg++) {
            float4 x1 = *(const float4*)(srcr + dg * 4);
            float4 x2 = *(const float4*)(srcr + 32 + dg * 4);
            float4 c4 = *(const float4*)&g_cos[s * 32 + dg * 4];
            float4 s4 = *(const float4*)&g_sin[s * 32 + dg * 4];
            float4 r1, r2;
            r1.x = (x1.x * c4.x - x2.x * s4.x) * qsc;
            r2.x = (x2.x * c4.x + x1.x * s4.x) * qsc;
            r1.y = (x1.y * c4.y - x2.y * s4.y) * qsc;
            r2.y = (x2.y * c4.y + x1.y * s4.y) * qsc;
            r1.z = (x1.z * c4.z - x2.z * s4.z) * qsc;
            r2.z = (x2.z * c4.z + x1.z * s4.z) * qsc;
            r1.w = (x1.w * c4.w - x2.w * s4.w) * qsc;
            r2.w = (x2.w * c4.w + x1.w * s4.w) * qsc;
            __nv_bfloat16 h0, h1, h2, h3, l0, l1, l2, l3;
            splitf(r1.x, h0, l0); splitf(r1.y, h1, l1);
            splitf(r1.z, h2, l2); splitf(r1.w, h3, l3);
            *(__nv_bfloat162*)(dh + dg * 4)     = __nv_bfloat162(h0, h1);
            *(__nv_bfloat162*)(dh + dg * 4 + 2) = __nv_bfloat162(h2, h3);
            *(__nv_bfloat162*)(dl + dg * 4)     = __nv_bfloat162(l0, l1);
            *(__nv_bfloat162*)(dl + dg * 4 + 2) = __nv_bfloat162(l2, l3);
            splitf(r2.x, h0, l0); splitf(r2.y, h1, l1);
            splitf(r2.z, h2, l2); splitf(r2.w, h3, l3);
            *(__nv_bfloat162*)(dh + 32 + dg * 4)     = __nv_bfloat162(h0, h1);
            *(__nv_bfloat162*)(dh + 32 + dg * 4 + 2) = __nv_bfloat162(h2, h3);
            *(__nv_bfloat162*)(dl + 32 + dg * 4)     = __nv_bfloat162(l0, l1);
            *(__nv_bfloat162*)(dl + 32 + dg * 4 + 2) = __nv_bfloat162(l2, l3);
        }
    }
}

// ---------------------------------------------------------------------------
// Flash attention via HMMA, cp.async double-buffered K/V, exp2-domain softmax.
// CTA = (b, h, 128-row q tile); 8 warps x 16 q-rows; K/V tiles of 64.
// ---------------------------------------------------------------------------
#define BQ 128
#define BK 64
#define KSTR 72
#define KVSTAGE (4 * 64 * KSTR)   // bf16 elems per stage (kh,kl,vh,vl)

__global__ __launch_bounds__(256, 2) void attn_mma() {
    extern __shared__ __nv_bfloat16 sa_[];
    __nv_bfloat16* sQh = sa_;                    // 128*72
    __nv_bfloat16* sQl = sa_ + 128 * KSTR;
    __nv_bfloat16* sKV = sa_ + 2 * 128 * KSTR;   // 2 stages

    const int qt = (int)(gridDim.x - 1) - (int)blockIdx.x;   // big tiles first
    const int h = blockIdx.y;
    const int b = blockIdx.z;
    const int tid = threadIdx.x;
    const int wid = tid >> 5;
    const int lane = tid & 31;

    const size_t bhoff = (size_t)(b * NHEADS + h) * NS * HDIM;
    const __nv_bfloat16* kvsrc[4] = {g_kh + bhoff, g_kl + bhoff,
                                     g_vh + bhoff, g_vl + bhoff};

    const uint32_t uQh = smem_u32(sQh);
    const uint32_t uQl = smem_u32(sQl);
    const uint32_t uKV = smem_u32(sKV);

    auto load_tile = [&](int kt, int stage) {
        const uint32_t sdst = uKV + 2u * (uint32_t)(stage * KVSTAGE);
        const size_t gb = (size_t)kt * BK * HDIM;
#pragma unroll
        for (int t = 0; t < 4; t++) {
            const __nv_bfloat16* src = kvsrc[t] + gb;
            const uint32_t db = sdst + 2u * (uint32_t)(t * 64 * KSTR);
#pragma unroll
            for (int i = 0; i < 2; i++) {
                const int idx = tid + 256 * i;
                const int row = idx >> 3;
                const int seg = idx & 7;
                cpa16(db + 2u * (uint32_t)(row * KSTR + seg * 8),
                      src + row * HDIM + seg * 8);
            }
        }
    };

    // ---- load Q tile (pre-scaled incl log2e, pre-split) ----
    {
        const int row = tid >> 1;
        const int c0 = (tid & 1) * 32;
        const __nv_bfloat16* sh = g_qh + bhoff + ((size_t)qt * BQ + row) * HDIM + c0;
        const __nv_bfloat16* sl = g_ql + bhoff + ((size_t)qt * BQ + row) * HDIM + c0;
        __nv_bfloat16* dh = sQh + row * KSTR + c0;
        __nv_bfloat16* dl = sQl + row * KSTR + c0;
#pragma unroll
        for (int j = 0; j < 4; j++) {
            *(uint4*)(dh + 8 * j) = *(const uint4*)(sh + 8 * j);
            *(uint4*)(dl + 8 * j) = *(const uint4*)(sl + 8 * j);
        }
    }

    const int a_row = lane & 15;
    const int a_koff = (lane >> 4) * 8;
    const int b_row = (lane & 7) + ((lane >> 4) & 1) * 8;
    const int b_koff = ((lane >> 3) & 1) * 8;
    const int v_kr = (lane & 7) + 8 * ((lane >> 3) & 1);
    const int v_nc = 8 * (lane >> 4);

    float o[8][4];
#pragma unroll
    for (int j = 0; j < 8; j++)
#pragma unroll
        for (int e = 0; e < 4; e++) o[j][e] = 0.0f;
    float mi0 = -1e30f, mi1 = -1e30f, li0 = 0.0f, li1 = 0.0f;

    const int qrow0 = qt * BQ + wid * 16 + (lane >> 2);
    const int qrow1 = qrow0 + 8;
    const int kcbase = 2 * (lane & 3);

    const int ktmax = 2 * qt + 1;   // >= 1 always
    load_tile(0, 0);
    CP_COMMIT();
    load_tile(1, 1);
    CP_COMMIT();

    for (int kt = 0; kt <= ktmax; kt++) {
        CP_WAIT1();
        __syncthreads();

        const uint32_t sstage = uKV + 2u * (uint32_t)((kt & 1) * KVSTAGE);
        const uint32_t uKh = sstage;
        const uint32_t uKl = sstage + 2u * (64 * KSTR);
        const uint32_t uVh = sstage + 2u * (2 * 64 * KSTR);
        const uint32_t uVl = sstage + 2u * (3 * 64 * KSTR);

        // ---- S = Q @ K^T (exp2 domain) ----
        float s[8][4];
#pragma unroll
        for (int j = 0; j < 8; j++)
#pragma unroll
            for (int e = 0; e < 4; e++) s[j][e] = 0.0f;

#pragma unroll
        for (int k16 = 0; k16 < 4; k16++) {
            const int kel = 16 * k16;
            uint32_t qh[4], ql[4], kh[4][4], kl[4][4];
            {
                const uint32_t off =
                    2u * ((wid * 16 + a_row) * KSTR + kel + a_koff);
                LDSM4(qh[0], qh[1], qh[2], qh[3], uQh + off);
                LDSM4(ql[0], ql[1], ql[2], ql[3], uQl + off);
            }
#pragma unroll
            for (int ng = 0; ng < 4; ng++) {
                const uint32_t off =
                    2u * ((16 * ng + b_row) * KSTR + kel + b_koff);
                LDSM4(kh[ng][0], kh[ng][1], kh[ng][2], kh[ng][3], uKh + off);
                LDSM4(kl[ng][0], kl[ng][1], kl[ng][2], kl[ng][3], uKl + off);
            }
#pragma unroll
            for (int j = 0; j < 8; j++) {
                const uint32_t* bh = &kh[j >> 1][2 * (j & 1)];
                const uint32_t* bl = &kl[j >> 1][2 * (j & 1)];
                mma_bf16(s[j], qh, bh);
                mma_bf16(s[j], qh, bl);
                mma_bf16(s[j], ql, bh);
            }
        }

        // ---- causal mask ----
        if (kt * BK + BK - 1 > qrow0) {
#pragma unroll
            for (int j = 0; j < 8; j++) {
                const int kc = kt * BK + 8 * j + kcbase;
                if (kc > qrow0) s[j][0] = -1e30f;
                if (kc + 1 > qrow0) s[j][1] = -1e30f;
            }
        }
        if (kt * BK + BK - 1 > qrow1) {
#pragma unroll
            for (int j = 0; j < 8; j++) {
                const int kc = kt * BK + 8 * j + kcbase;
                if (kc > qrow1) s[j][2] = -1e30f;
                if (kc + 1 > qrow1) s[j][3] = -1e30f;
            }
        }

        // ---- online softmax (exp2) ----
        float mx0 = s[0][0], mx1 = s[0][2];
#pragma unroll
        for (int j = 0; j < 8; j++) {
            mx0 = fmaxf(mx0, fmaxf(s[j][0], s[j][1]));
            mx1 = fmaxf(mx1, fmaxf(s[j][2], s[j][3]));
        }
        mx0 = fmaxf(mx0, __shfl_xor_sync(0xffffffffu, mx0, 1));
        mx0 = fmaxf(mx0, __shfl_xor_sync(0xffffffffu, mx0, 2));
        mx1 = fmaxf(mx1, __shfl_xor_sync(0xffffffffu, mx1, 1));
        mx1 = fmaxf(mx1, __shfl_xor_sync(0xffffffffu, mx1, 2));

        const float mn0 = fmaxf(mi0, mx0);
        const float mn1 = fmaxf(mi1, mx1);
        const float cr0 = ex2f(mi0 - mn0);
        const float cr1 = ex2f(mi1 - mn1);

        float rs0 = 0.0f, rs1 = 0.0f;
#pragma unroll
        for (int j = 0; j < 8; j++) {
            s[j][0] = ex2f(s[j][0] - mn0);
            s[j][1] = ex2f(s[j][1] - mn0);
            s[j][2] = ex2f(s[j][2] - mn1);
            s[j][3] = ex2f(s[j][3] - mn1);
            rs0 += s[j][0] + s[j][1];
            rs1 += s[j][2] + s[j][3];
        }
        rs0 += __shfl_xor_sync(0xffffffffu, rs0, 1);
        rs0 += __shfl_xor_sync(0xffffffffu, rs0, 2);
        rs1 += __shfl_xor_sync(0xffffffffu, rs1, 1);
        rs1 += __shfl_xor_sync(0xffffffffu, rs1, 2);
        li0 = li0 * cr0 + rs0;
        li1 = li1 * cr1 + rs1;
        mi0 = mn0;
        mi1 = mn1;

#pragma unroll
        for (int j = 0; j < 8; j++) {
            o[j][0] *= cr0;
            o[j][1] *= cr0;
            o[j][2] *= cr1;
            o[j][3] *= cr1;
        }

        // ---- O += P @ V ----
#pragma unroll
        for (int t = 0; t < 4; t++) {
            uint32_t ph[4], pl[4];
            {
                const float* p0 = s[2 * t];
                const float* p1 = s[2 * t + 1];
                __nv_bfloat16 hh, ll;
                float hf[8], lf[8];
#pragma unroll
                for (int e = 0; e < 4; e++) {
                    splitf(p0[e], hh, ll);
                    hf[e] = __bfloat162float(hh);
                    lf[e] = __bfloat162float(ll);
                    splitf(p1[e], hh, ll);
                    hf[4 + e] = __bfloat162float(hh);
                    lf[4 + e] = __bfloat162float(ll);
                }
                ph[0] = pkbf(hf[0], hf[1]);
                ph[1] = pkbf(hf[2], hf[3]);
                ph[2] = pkbf(hf[4], hf[5]);
                ph[3] = pkbf(hf[6], hf[7]);
                pl[0] = pkbf(lf[0], lf[1]);
                pl[1] = pkbf(lf[2], lf[3]);
                pl[2] = pkbf(lf[4], lf[5]);
                pl[3] = pkbf(lf[6], lf[7]);
            }
            const int kel = 16 * t;
            uint32_t vh[4][4], vl[4][4];
#pragma unroll
            for (int ng = 0; ng < 4; ng++) {
                const uint32_t off =
                    2u * ((kel + v_kr) * KSTR + 16 * ng + v_nc);
                LDSM4T(vh[ng][0], vh[ng][1], vh[ng][2], vh[ng][3], uVh + off);
                LDSM4T(vl[ng][0], vl[ng][1], vl[ng][2], vl[ng][3], uVl + off);
            }
#pragma unroll
            for (int j = 0; j < 8; j++) {
                const uint32_t* bvh = &vh[j >> 1][2 * (j & 1)];
                const uint32_t* bvl = &vl[j >> 1][2 * (j & 1)];
                mma_bf16(o[j], ph, bvh);
                mma_bf16(o[j], ph, bvl);
                mma_bf16(o[j], pl, bvh);
            }
        }

        __syncthreads();
        if (kt + 2 <= ktmax) load_tile(kt + 2, kt & 1);
        CP_COMMIT();
    }

    // ---- normalize + store SPLIT to g_aoh/g_aol [b, s, h*64+d] ----
    const float inv0 = 1.0f / li0;
    const float inv1 = 1.0f / li1;
    const size_t o0 = ((size_t)b * NS + qrow0) * NHID + h * HDIM;
    const size_t o1 = ((size_t)b * NS + qrow1) * NHID + h * HDIM;
#pragma unroll
    for (int j = 0; j < 8; j++) {
        const int d = 8 * j + kcbase;
        __nv_bfloat16 h0, h1, l0, l1;
        splitf(o[j][0] * inv0, h0, l0);
        splitf(o[j][1] * inv0, h1, l1);
        *(__nv_bfloat162*)&g_aoh[o0 + d] = __nv_bfloat162(h0, h1);
        *(__nv_bfloat162*)&g_aol[o0 + d] = __nv_bfloat162(l0, l1);
        splitf(o[j][2] * inv1, h0, l0);
        splitf(o[j][3] * inv1, h1, l1);
        *(__nv_bfloat162*)&g_aoh[o1 + d] = __nv_bfloat162(h0, h1);
        *(__nv_bfloat162*)&g_aol[o1 + d] = __nv_bfloat162(l0, l1);
    }
}

// ---------------------------------------------------------------------------
extern "C" void kernel_launch(void* const* d_in, const int* in_sizes, int n_in,
                              void* d_out, int out_size) {
    const float* x  = (const float*)d_in[0];
    const float* Wq = (const float*)d_in[1];
    const float* bq = (const float*)d_in[2];
    const float* Wk = (const float*)d_in[3];
    const float* bk = (const float*)d_in[4];
    const float* Wv = (const float*)d_in[5];
    const float* bv = (const float*)d_in[6];
    const float* Wo = (const float*)d_in[7];
    const float* bo = (const float*)d_in[8];
    float* out = (float*)d_out;

    const int GEMM_SMEM = 2 * GSTAGE * 2;                       // 81920 B
    const int ATTN_SMEM = (2 * 128 * KSTR + 2 * KVSTAGE) * 2;   // 110592 B
    cudaFuncSetAttribute(gemm_mma<0>, cudaFuncAttributeMaxDynamicSharedMemorySize,
                         GEMM_SMEM);
    cudaFuncSetAttribute(gemm_mma<1>, cudaFuncAttributeMaxDynamicSharedMemorySize,
                         GEMM_SMEM);
    cudaFuncSetAttribute(attn_mma, cudaFuncAttributeMaxDynamicSharedMemorySize,
                         ATTN_SMEM);

    rope_table<<<NS * 32 / 256, 256>>>();

    // 4M (x) + 4x1M (weights) elems, 4 per thread
    cvt_all<<<(MM * NHID + 4 * NHID * NHID) / 1024, 256>>>(x, Wq, Wk, Wv, Wo);

    gemm_mma<0><<<dim3(NHID / 128, MM / 128, 3), 256, GEMM_SMEM>>>(bq, bk, bv,
                                                                   nullptr);

    attn_mma<<<dim3(NS / BQ, NHEADS, NB), 256, ATTN_SMEM>>>();

    gemm_mma<1><<<dim3(NHID / 128, MM / 128), 256, GEMM_SMEM>>>(bo, nullptr,
                                                                nullptr, out);
}

// round 11
// speedup vs baseline: 1.1612x; 1.0665x over previous
#include <cuda_runtime.h>
#include <cuda_bf16.h>
#include <stdint.h>
#include <cstdint>
#include <math.h>

#define NB 2
#define NS 2048
#define NHID 1024
#define NHEADS 16
#define HDIM 64
#define MM (NB * NS)   // 4096

// ---------------- scratch (static device globals; no allocation) ----------
__device__ float g_cos[NS * 32];                 // rope tables [s][d]
__device__ float g_sin[NS * 32];
__device__ float g_q[NB * NHEADS * NS * HDIM];   // fp32 pre-rope [b,h,s,d]
__device__ float g_k[NB * NHEADS * NS * HDIM];

// split-bf16 operands
__device__ __nv_bfloat16 g_xh[MM * NHID];
__device__ __nv_bfloat16 g_xl[MM * NHID];
__device__ __nv_bfloat16 g_wh[4 * NHID * NHID];  // Wq,Wk,Wv,Wo
__device__ __nv_bfloat16 g_wl[4 * NHID * NHID];
__device__ __nv_bfloat16 g_aoh[MM * NHID];       // attention output, split
__device__ __nv_bfloat16 g_aol[MM * NHID];
// rope-rotated, split q/k (q pre-scaled by 0.125*log2e) + split v, [b,h,s,d]
__device__ __nv_bfloat16 g_qh[NB * NHEADS * NS * HDIM];
__device__ __nv_bfloat16 g_ql[NB * NHEADS * NS * HDIM];
__device__ __nv_bfloat16 g_kh[NB * NHEADS * NS * HDIM];
__device__ __nv_bfloat16 g_kl[NB * NHEADS * NS * HDIM];
__device__ __nv_bfloat16 g_vh[NB * NHEADS * NS * HDIM];
__device__ __nv_bfloat16 g_vl[NB * NHEADS * NS * HDIM];

// Q pre-scale: 0.125 * log2(e)  (softmax runs in exp2 domain)
#define QSCALE 0.18033688011112043f

// ---------------- mma.sync helpers (base sm_103 ISA) ------------------------
__device__ __forceinline__ uint32_t smem_u32(const void* p) {
    uint32_t a;
    asm("{ .reg .u64 t; cvta.to.shared.u64 t, %1; cvt.u32.u64 %0, t; }"
        : "=r"(a) : "l"(p));
    return a;
}
#define LDSM4(r0, r1, r2, r3, addr)                                          \
    asm volatile("ldmatrix.sync.aligned.m8n8.x4.shared.b16 {%0,%1,%2,%3}, [%4];" \
                 : "=r"(r0), "=r"(r1), "=r"(r2), "=r"(r3) : "r"(addr))
#define LDSM4T(r0, r1, r2, r3, addr)                                         \
    asm volatile(                                                            \
        "ldmatrix.sync.aligned.m8n8.x4.trans.shared.b16 {%0,%1,%2,%3}, [%4];" \
        : "=r"(r0), "=r"(r1), "=r"(r2), "=r"(r3) : "r"(addr))

__device__ __forceinline__ void mma_bf16(float* d, const uint32_t* a,
                                         const uint32_t* b) {
    asm volatile(
        "mma.sync.aligned.m16n8k16.row.col.f32.bf16.bf16.f32 "
        "{%0,%1,%2,%3}, {%4,%5,%6,%7}, {%8,%9}, {%0,%1,%2,%3};"
        : "+f"(d[0]), "+f"(d[1]), "+f"(d[2]), "+f"(d[3])
        : "r"(a[0]), "r"(a[1]), "r"(a[2]), "r"(a[3]), "r"(b[0]), "r"(b[1]));
}

__device__ __forceinline__ uint32_t pkbf(float a, float b) {
    __nv_bfloat162 t = __floats2bfloat162_rn(a, b);
    return *(uint32_t*)&t;
}
// fast pair split: hi = packed bf16(a,b); lo = packed bf16(a-hi.x, b-hi.y)
__device__ __forceinline__ uint32_t split2(float a, float b, uint32_t& lo) {
    uint32_t hi = pkbf(a, b);
    __nv_bfloat162 hb = *(__nv_bfloat162*)&hi;
    float2 hf = __bfloat1622float2(hb);
    lo = pkbf(a - hf.x, b - hf.y);
    return hi;
}
__device__ __forceinline__ void splitf(float v, __nv_bfloat16& h,
                                       __nv_bfloat16& l) {
    h = __float2bfloat16(v);
    l = __float2bfloat16(v - __bfloat162float(h));
}
__device__ __forceinline__ float ex2f(float x) {
    float y;
    asm("ex2.approx.ftz.f32 %0, %1;" : "=f"(y) : "f"(x));
    return y;
}

// ---------------- cp.async helpers -----------------------------------------
__device__ __forceinline__ void cpa16(uint32_t dst, const void* src) {
    asm volatile("cp.async.cg.shared.global [%0], [%1], 16;"
                 :: "r"(dst), "l"(src));
}
#define CP_COMMIT() asm volatile("cp.async.commit_group;" ::: "memory")
#define CP_WAIT1() asm volatile("cp.async.wait_group 1;" ::: "memory")

// ---------------------------------------------------------------------------
// Merged split conversion: x then Wq,Wk,Wv,Wo in one launch.
// ---------------------------------------------------------------------------
__global__ __launch_bounds__(256) void cvt_all(const float* __restrict__ x,
                                               const float* __restrict__ Wq,
                                               const float* __restrict__ Wk,
                                               const float* __restrict__ Wv,
                                               const float* __restrict__ Wo) {
    const size_t i = 4ull * ((size_t)blockIdx.x * blockDim.x + threadIdx.x);
    const size_t XN = (size_t)MM * NHID;     // 4M
    const size_t WN = (size_t)NHID * NHID;   // 1M (2^20)
    const float* s;
    __nv_bfloat16 *h, *l;
    size_t o;
    if (i < XN) {
        s = x;
        o = i;
        h = g_xh;
        l = g_xl;
    } else {
        const size_t j = i - XN;
        const int w = (int)(j >> 20);
        o = j & (WN - 1);
        s = (w == 0) ? Wq : (w == 1) ? Wk : (w == 2) ? Wv : Wo;
        h = g_wh + (size_t)w * WN;
        l = g_wl + (size_t)w * WN;
    }
    float4 v = *(const float4*)(s + o);
    uint32_t h01, h23, l01, l23;
    h01 = split2(v.x, v.y, l01);
    h23 = split2(v.z, v.w, l23);
    *(uint32_t*)(h + o)     = h01;
    *(uint32_t*)(h + o + 2) = h23;
    *(uint32_t*)(l + o)     = l01;
    *(uint32_t*)(l + o + 2) = l23;
}

// ---------------------------------------------------------------------------
// RoPE cos/sin table (fp64, 65536 entries)
// ---------------------------------------------------------------------------
__global__ void rope_table() {
    const int t = blockIdx.x * blockDim.x + threadIdx.x;
    const int d = t & 31;
    const int s = t >> 5;
    const double inv = exp2(-(double)d * 0.41524101186092029);
    double sd, cd;
    sincos((double)s * inv, &sd, &cd);
    g_cos[t] = (float)cd;
    g_sin[t] = (float)sd;
}

// ---------------------------------------------------------------------------
// RoPE apply: reads fp32 q/k, rotates, splits to bf16 hi/lo.
// Q additionally scaled by QSCALE (exp2-domain softmax).
// ---------------------------------------------------------------------------
__global__ __launch_bounds__(256) void rope_apply() {
    int t = blockIdx.x * blockDim.x + threadIdx.x;
    const int half = NB * NHEADS * NS * 8;
    const bool isq = (t < half);
    if (!isq) t -= half;
    const int dg = t & 7;
    const int s = (t >> 3) & (NS - 1);
    const int bh = t >> 14;

    const float4 c4 = *(const float4*)&g_cos[s * 32 + dg * 4];
    const float4 s4 = *(const float4*)&g_sin[s * 32 + dg * 4];

    const size_t off = ((size_t)bh * NS + s) * HDIM + dg * 4;
    const float* p = (isq ? g_q : g_k) + off;
    float4 x1 = *(const float4*)(p);
    float4 x2 = *(const float4*)(p + 32);
    float4 r1, r2;
    r1.x = x1.x * c4.x - x2.x * s4.x;  r2.x = x2.x * c4.x + x1.x * s4.x;
    r1.y = x1.y * c4.y - x2.y * s4.y;  r2.y = x2.y * c4.y + x1.y * s4.y;
    r1.z = x1.z * c4.z - x2.z * s4.z;  r2.z = x2.z * c4.z + x1.z * s4.z;
    r1.w = x1.w * c4.w - x2.w * s4.w;  r2.w = x2.w * c4.w + x1.w * s4.w;
    if (isq) {
        r1.x *= QSCALE; r1.y *= QSCALE; r1.z *= QSCALE; r1.w *= QSCALE;
        r2.x *= QSCALE; r2.y *= QSCALE; r2.z *= QSCALE; r2.w *= QSCALE;
    }
    __nv_bfloat16* dh = (isq ? g_qh : g_kh) + off;
    __nv_bfloat16* dl = (isq ? g_ql : g_kl) + off;
    uint32_t h01, h23, l01, l23;
    h01 = split2(r1.x, r1.y, l01);
    h23 = split2(r1.z, r1.w, l23);
    *(uint32_t*)(dh)     = h01;
    *(uint32_t*)(dh + 2) = h23;
    *(uint32_t*)(dl)     = l01;
    *(uint32_t*)(dl + 2) = l23;
    h01 = split2(r2.x, r2.y, l01);
    h23 = split2(r2.z, r2.w, l23);
    *(uint32_t*)(dh + 32) = h01;
    *(uint32_t*)(dh + 34) = h23;
    *(uint32_t*)(dl + 32) = l01;
    *(uint32_t*)(dl + 34) = l23;
}

// ---------------------------------------------------------------------------
// HMMA GEMM, 2-stage cp.async pipeline (2 CTAs/SM). C = A*W^T + bias,
// split-bf16 3-pass.
// PROJ=0: z=0/1 -> fp32 g_q/g_k (rope applied separately), z=2 -> split V.
// PROJ=1: out projection from g_aoh/g_aol to Cout fp32.
// ---------------------------------------------------------------------------
#define KC2 32
#define NKC2 (NHID / KC2)   // 32
#define GSTR 40
#define GSTAGE (4 * 128 * GSTR)     // bf16 elems per stage

template <int PROJ>
__global__ __launch_bounds__(256) void gemm_mma(const float* __restrict__ b0p,
                                                const float* __restrict__ b1p,
                                                const float* __restrict__ b2p,
                                                float* __restrict__ Cout) {
    extern __shared__ __nv_bfloat16 sb[];

    const int tid = threadIdx.x;
    const int wid = tid >> 5;
    const int lane = tid & 31;
    const int wr = wid >> 2;
    const int wc = wid & 3;

    const int n0 = blockIdx.x * 128;
    const int m0 = blockIdx.y * 128;
    const int z = PROJ ? 3 : blockIdx.z;

    const __nv_bfloat16* Ah = PROJ ? g_aoh : g_xh;
    const __nv_bfloat16* Al = PROJ ? g_aol : g_xl;
    const __nv_bfloat16* Wh = g_wh + (size_t)z * NHID * NHID;
    const __nv_bfloat16* Wl = g_wl + (size_t)z * NHID * NHID;
    const float* bias = PROJ ? b0p : (z == 0 ? b0p : (z == 1 ? b1p : b2p));

    const __nv_bfloat16* gsrc[4] = {Ah + (size_t)m0 * NHID, Al + (size_t)m0 * NHID,
                                    Wh + (size_t)n0 * NHID, Wl + (size_t)n0 * NHID};

    float acc[4][4][4];
#pragma unroll
    for (int mt = 0; mt < 4; mt++)
#pragma unroll
        for (int nt = 0; nt < 4; nt++)
#pragma unroll
            for (int e = 0; e < 4; e++) acc[mt][nt][e] = 0.0f;

    const uint32_t uS = smem_u32(sb);

    auto load_chunk = [&](int c, int stage) {
        const int kc = c * KC2;
        const uint32_t sdst = uS + 2u * (uint32_t)(stage * GSTAGE);
#pragma unroll
        for (int t = 0; t < 4; t++) {
            const uint32_t db = sdst + 2u * (uint32_t)(t * 128 * GSTR);
            const __nv_bfloat16* src = gsrc[t];
#pragma unroll
            for (int i = 0; i < 2; i++) {
                const int idx = tid + 256 * i;
                const int row = idx >> 2;
                const int seg = idx & 3;
                cpa16(db + 2u * (uint32_t)(row * GSTR + seg * 8),
                      src + (size_t)row * NHID + kc + seg * 8);
            }
        }
    };

    const int a_row = lane & 15;
    const int a_koff = (lane >> 4) * 8;
    const int b_row = (lane & 7) + ((lane >> 4) & 1) * 8;
    const int b_koff = ((lane >> 3) & 1) * 8;

    load_chunk(0, 0);
    CP_COMMIT();
    load_chunk(1, 1);
    CP_COMMIT();

    for (int c = 0; c < NKC2; c++) {
        CP_WAIT1();
        __syncthreads();

        const uint32_t sstage = uS + 2u * (uint32_t)((c & 1) * GSTAGE);
        const uint32_t uAh = sstage;
        const uint32_t uAl = sstage + 2u * (128 * GSTR);
        const uint32_t uWh = sstage + 2u * (2 * 128 * GSTR);
        const uint32_t uWl = sstage + 2u * (3 * 128 * GSTR);

#pragma unroll
        for (int k16 = 0; k16 < 2; k16++) {
            const int kel = k16 * 16;
            uint32_t ah[4][4], al[4][4], bh[8], bl[8];
#pragma unroll
            for (int mt = 0; mt < 4; mt++) {
                const uint32_t off =
                    2u * ((64 * wr + 16 * mt + a_row) * GSTR + kel + a_koff);
                LDSM4(ah[mt][0], ah[mt][1], ah[mt][2], ah[mt][3], uAh + off);
                LDSM4(al[mt][0], al[mt][1], al[mt][2], al[mt][3], uAl + off);
            }
#pragma unroll
            for (int np = 0; np < 2; np++) {
                const uint32_t off =
                    2u * ((32 * wc + 16 * np + b_row) * GSTR + kel + b_koff);
                LDSM4(bh[4 * np], bh[4 * np + 1], bh[4 * np + 2], bh[4 * np + 3],
                      uWh + off);
                LDSM4(bl[4 * np], bl[4 * np + 1], bl[4 * np + 2], bl[4 * np + 3],
                      uWl + off);
            }
#pragma unroll
            for (int mt = 0; mt < 4; mt++)
#pragma unroll
                for (int nt = 0; nt < 4; nt++) {
                    const uint32_t* bt_h = &bh[4 * (nt >> 1) + 2 * (nt & 1)];
                    const uint32_t* bt_l = &bl[4 * (nt >> 1) + 2 * (nt & 1)];
                    mma_bf16(acc[mt][nt], ah[mt], bt_h);
                    mma_bf16(acc[mt][nt], ah[mt], bt_l);
                    mma_bf16(acc[mt][nt], al[mt], bt_h);
                }
        }
        __syncthreads();
        if (c + 2 < NKC2) load_chunk(c + 2, c & 1);
        CP_COMMIT();
    }

    // ---- epilogue ----
    const int mrow = (lane >> 2);
    const int ncol = (lane & 3) * 2;
#pragma unroll
    for (int mt = 0; mt < 4; mt++) {
#pragma unroll
        for (int half = 0; half < 2; half++) {
            const int m = m0 + 64 * wr + 16 * mt + mrow + 8 * half;
#pragma unroll
            for (int nt = 0; nt < 4; nt++) {
                const int n = n0 + 32 * wc + 8 * nt + ncol;
                float v0 = acc[mt][nt][2 * half] + bias[n];
                float v1 = acc[mt][nt][2 * half + 1] + bias[n + 1];
                if (PROJ) {
                    *(float2*)&Cout[(size_t)m * NHID + n] = make_float2(v0, v1);
                } else {
                    const int bb = m >> 11;
                    const int s = m & (NS - 1);
                    const int h = n >> 6;
                    const int d = n & (HDIM - 1);
                    const size_t o =
                        (((size_t)(bb * NHEADS + h) * NS + s) * HDIM + d);
                    if (z == 2) {   // V: store split bf16 directly
                        uint32_t lo;
                        uint32_t hi = split2(v0, v1, lo);
                        *(uint32_t*)&g_vh[o] = hi;
                        *(uint32_t*)&g_vl[o] = lo;
                    } else {
                        float* dst = (z == 0) ? g_q : g_k;
                        *(float2*)&dst[o] = make_float2(v0, v1);
                    }
                }
            }
        }
    }
}

// ---------------------------------------------------------------------------
// Flash attention via HMMA, cp.async double-buffered K/V, exp2-domain softmax.
// CTA = (b, h, 128-row q tile); 8 warps x 16 q-rows; K/V tiles of 64.
// ---------------------------------------------------------------------------
#define BQ 128
#define BK 64
#define KSTR 72
#define KVSTAGE (4 * 64 * KSTR)   // bf16 elems per stage (kh,kl,vh,vl)

__global__ __launch_bounds__(256, 2) void attn_mma() {
    extern __shared__ __nv_bfloat16 sa_[];
    __nv_bfloat16* sQh = sa_;                    // 128*72
    __nv_bfloat16* sQl = sa_ + 128 * KSTR;
    __nv_bfloat16* sKV = sa_ + 2 * 128 * KSTR;   // 2 stages

    const int qt = (int)(gridDim.x - 1) - (int)blockIdx.x;   // big tiles first
    const int h = blockIdx.y;
    const int b = blockIdx.z;
    const int tid = threadIdx.x;
    const int wid = tid >> 5;
    const int lane = tid & 31;

    const size_t bhoff = (size_t)(b * NHEADS + h) * NS * HDIM;
    const __nv_bfloat16* kvsrc[4] = {g_kh + bhoff, g_kl + bhoff,
                                     g_vh + bhoff, g_vl + bhoff};

    const uint32_t uQh = smem_u32(sQh);
    const uint32_t uQl = smem_u32(sQl);
    const uint32_t uKV = smem_u32(sKV);

    auto load_tile = [&](int kt, int stage) {
        const uint32_t sdst = uKV + 2u * (uint32_t)(stage * KVSTAGE);
        const size_t gb = (size_t)kt * BK * HDIM;
#pragma unroll
        for (int t = 0; t < 4; t++) {
            const __nv_bfloat16* src = kvsrc[t] + gb;
            const uint32_t db = sdst + 2u * (uint32_t)(t * 64 * KSTR);
#pragma unroll
            for (int i = 0; i < 2; i++) {
                const int idx = tid + 256 * i;
                const int row = idx >> 3;
                const int seg = idx & 7;
                cpa16(db + 2u * (uint32_t)(row * KSTR + seg * 8),
                      src + row * HDIM + seg * 8);
            }
        }
    };

    // ---- load Q tile (pre-scaled incl log2e, pre-split) ----
    {
        const int row = tid >> 1;
        const int c0 = (tid & 1) * 32;
        const __nv_bfloat16* sh = g_qh + bhoff + ((size_t)qt * BQ + row) * HDIM + c0;
        const __nv_bfloat16* sl = g_ql + bhoff + ((size_t)qt * BQ + row) * HDIM + c0;
        __nv_bfloat16* dh = sQh + row * KSTR + c0;
        __nv_bfloat16* dl = sQl + row * KSTR + c0;
#pragma unroll
        for (int j = 0; j < 4; j++) {
            *(uint4*)(dh + 8 * j) = *(const uint4*)(sh + 8 * j);
            *(uint4*)(dl + 8 * j) = *(const uint4*)(sl + 8 * j);
        }
    }

    const int a_row = lane & 15;
    const int a_koff = (lane >> 4) * 8;
    const int b_row = (lane & 7) + ((lane >> 4) & 1) * 8;
    const int b_koff = ((lane >> 3) & 1) * 8;
    const int v_kr = (lane & 7) + 8 * ((lane >> 3) & 1);
    const int v_nc = 8 * (lane >> 4);

    float o[8][4];
#pragma unroll
    for (int j = 0; j < 8; j++)
#pragma unroll
        for (int e = 0; e < 4; e++) o[j][e] = 0.0f;
    float mi0 = -1e30f, mi1 = -1e30f, li0 = 0.0f, li1 = 0.0f;

    const int qrow0 = qt * BQ + wid * 16 + (lane >> 2);
    const int qrow1 = qrow0 + 8;
    const int kcbase = 2 * (lane & 3);

    const int ktmax = 2 * qt + 1;   // >= 1 always
    load_tile(0, 0);
    CP_COMMIT();
    load_tile(1, 1);
    CP_COMMIT();

    for (int kt = 0; kt <= ktmax; kt++) {
        CP_WAIT1();
        __syncthreads();

        const uint32_t sstage = uKV + 2u * (uint32_t)((kt & 1) * KVSTAGE);
        const uint32_t uKh = sstage;
        const uint32_t uKl = sstage + 2u * (64 * KSTR);
        const uint32_t uVh = sstage + 2u * (2 * 64 * KSTR);
        const uint32_t uVl = sstage + 2u * (3 * 64 * KSTR);

        // ---- S = Q @ K^T (exp2 domain) ----
        float s[8][4];
#pragma unroll
        for (int j = 0; j < 8; j++)
#pragma unroll
            for (int e = 0; e < 4; e++) s[j][e] = 0.0f;

#pragma unroll
        for (int k16 = 0; k16 < 4; k16++) {
            const int kel = 16 * k16;
            uint32_t qh[4], ql[4], kh[4][4], kl[4][4];
            {
                const uint32_t off =
                    2u * ((wid * 16 + a_row) * KSTR + kel + a_koff);
                LDSM4(qh[0], qh[1], qh[2], qh[3], uQh + off);
                LDSM4(ql[0], ql[1], ql[2], ql[3], uQl + off);
            }
#pragma unroll
            for (int ng = 0; ng < 4; ng++) {
                const uint32_t off =
                    2u * ((16 * ng + b_row) * KSTR + kel + b_koff);
                LDSM4(kh[ng][0], kh[ng][1], kh[ng][2], kh[ng][3], uKh + off);
                LDSM4(kl[ng][0], kl[ng][1], kl[ng][2], kl[ng][3], uKl + off);
            }
#pragma unroll
            for (int j = 0; j < 8; j++) {
                const uint32_t* bh = &kh[j >> 1][2 * (j & 1)];
                const uint32_t* bl = &kl[j >> 1][2 * (j & 1)];
                mma_bf16(s[j], qh, bh);
                mma_bf16(s[j], qh, bl);
                mma_bf16(s[j], ql, bh);
            }
        }

        // ---- causal mask ----
        if (kt * BK + BK - 1 > qrow0) {
#pragma unroll
            for (int j = 0; j < 8; j++) {
                const int kc = kt * BK + 8 * j + kcbase;
                if (kc > qrow0) s[j][0] = -1e30f;
                if (kc + 1 > qrow0) s[j][1] = -1e30f;
            }
        }
        if (kt * BK + BK - 1 > qrow1) {
#pragma unroll
            for (int j = 0; j < 8; j++) {
                const int kc = kt * BK + 8 * j + kcbase;
                if (kc > qrow1) s[j][2] = -1e30f;
                if (kc + 1 > qrow1) s[j][3] = -1e30f;
            }
        }

        // ---- online softmax (exp2) ----
        float mx0 = s[0][0], mx1 = s[0][2];
#pragma unroll
        for (int j = 0; j < 8; j++) {
            mx0 = fmaxf(mx0, fmaxf(s[j][0], s[j][1]));
            mx1 = fmaxf(mx1, fmaxf(s[j][2], s[j][3]));
        }
        mx0 = fmaxf(mx0, __shfl_xor_sync(0xffffffffu, mx0, 1));
        mx0 = fmaxf(mx0, __shfl_xor_sync(0xffffffffu, mx0, 2));
        mx1 = fmaxf(mx1, __shfl_xor_sync(0xffffffffu, mx1, 1));
        mx1 = fmaxf(mx1, __shfl_xor_sync(0xffffffffu, mx1, 2));

        const float mn0 = fmaxf(mi0, mx0);
        const float mn1 = fmaxf(mi1, mx1);
        const float cr0 = ex2f(mi0 - mn0);
        const float cr1 = ex2f(mi1 - mn1);

        float rs0 = 0.0f, rs1 = 0.0f;
#pragma unroll
        for (int j = 0; j < 8; j++) {
            s[j][0] = ex2f(s[j][0] - mn0);
            s[j][1] = ex2f(s[j][1] - mn0);
            s[j][2] = ex2f(s[j][2] - mn1);
            s[j][3] = ex2f(s[j][3] - mn1);
            rs0 += s[j][0] + s[j][1];
            rs1 += s[j][2] + s[j][3];
        }
        rs0 += __shfl_xor_sync(0xffffffffu, rs0, 1);
        rs0 += __shfl_xor_sync(0xffffffffu, rs0, 2);
        rs1 += __shfl_xor_sync(0xffffffffu, rs1, 1);
        rs1 += __shfl_xor_sync(0xffffffffu, rs1, 2);
        li0 = li0 * cr0 + rs0;
        li1 = li1 * cr1 + rs1;
        mi0 = mn0;
        mi1 = mn1;

#pragma unroll
        for (int j = 0; j < 8; j++) {
            o[j][0] *= cr0;
            o[j][1] *= cr0;
            o[j][2] *= cr1;
            o[j][3] *= cr1;
        }

        // ---- O += P @ V (fast register P pack) ----
#pragma unroll
        for (int t = 0; t < 4; t++) {
            uint32_t ph[4], pl[4];
            {
                const float* p0 = s[2 * t];
                const float* p1 = s[2 * t + 1];
                ph[0] = split2(p0[0], p0[1], pl[0]);
                ph[1] = split2(p0[2], p0[3], pl[1]);
                ph[2] = split2(p1[0], p1[1], pl[2]);
                ph[3] = split2(p1[2], p1[3], pl[3]);
            }
            const int kel = 16 * t;
            uint32_t vh[4][4], vl[4][4];
#pragma unroll
            for (int ng = 0; ng < 4; ng++) {
                const uint32_t off =
                    2u * ((kel + v_kr) * KSTR + 16 * ng + v_nc);
                LDSM4T(vh[ng][0], vh[ng][1], vh[ng][2], vh[ng][3], uVh + off);
                LDSM4T(vl[ng][0], vl[ng][1], vl[ng][2], vl[ng][3], uVl + off);
            }
#pragma unroll
            for (int j = 0; j < 8; j++) {
                const uint32_t* bvh = &vh[j >> 1][2 * (j & 1)];
                const uint32_t* bvl = &vl[j >> 1][2 * (j & 1)];
                mma_bf16(o[j], ph, bvh);
                mma_bf16(o[j], ph, bvl);
                mma_bf16(o[j], pl, bvh);
            }
        }

        __syncthreads();
        if (kt + 2 <= ktmax) load_tile(kt + 2, kt & 1);
        CP_COMMIT();
    }

    // ---- normalize + store SPLIT to g_aoh/g_aol [b, s, h*64+d] ----
    const float inv0 = 1.0f / li0;
    const float inv1 = 1.0f / li1;
    const size_t o0 = ((size_t)b * NS + qrow0) * NHID + h * HDIM;
    const size_t o1 = ((size_t)b * NS + qrow1) * NHID + h * HDIM;
#pragma unroll
    for (int j = 0; j < 8; j++) {
        const int d = 8 * j + kcbase;
        uint32_t lo;
        uint32_t hi = split2(o[j][0] * inv0, o[j][1] * inv0, lo);
        *(uint32_t*)&g_aoh[o0 + d] = hi;
        *(uint32_t*)&g_aol[o0 + d] = lo;
        hi = split2(o[j][2] * inv1, o[j][3] * inv1, lo);
        *(uint32_t*)&g_aoh[o1 + d] = hi;
        *(uint32_t*)&g_aol[o1 + d] = lo;
    }
}

// ---------------------------------------------------------------------------
extern "C" void kernel_launch(void* const* d_in, const int* in_sizes, int n_in,
                              void* d_out, int out_size) {
    const float* x  = (const float*)d_in[0];
    const float* Wq = (const float*)d_in[1];
    const float* bq = (const float*)d_in[2];
    const float* Wk = (const float*)d_in[3];
    const float* bk = (const float*)d_in[4];
    const float* Wv = (const float*)d_in[5];
    const float* bv = (const float*)d_in[6];
    const float* Wo = (const float*)d_in[7];
    const float* bo = (const float*)d_in[8];
    float* out = (float*)d_out;

    const int GEMM_SMEM = 2 * GSTAGE * 2;                       // 81920 B
    const int ATTN_SMEM = (2 * 128 * KSTR + 2 * KVSTAGE) * 2;   // 110592 B
    cudaFuncSetAttribute(gemm_mma<0>, cudaFuncAttributeMaxDynamicSharedMemorySize,
                         GEMM_SMEM);
    cudaFuncSetAttribute(gemm_mma<1>, cudaFuncAttributeMaxDynamicSharedMemorySize,
                         GEMM_SMEM);
    cudaFuncSetAttribute(attn_mma, cudaFuncAttributeMaxDynamicSharedMemorySize,
                         ATTN_SMEM);

    rope_table<<<NS * 32 / 256, 256>>>();

    // 4M (x) + 4x1M (weights) elems, 4 per thread
    cvt_all<<<(MM * NHID + 4 * NHID * NHID) / 1024, 256>>>(x, Wq, Wk, Wv, Wo);

    gemm_mma<0><<<dim3(NHID / 128, MM / 128, 3), 256, GEMM_SMEM>>>(bq, bk, bv,
                                                                   nullptr);

    rope_apply<<<2 * NB * NHEADS * NS * 8 / 256, 256>>>();

    attn_mma<<<dim3(NS / BQ, NHEADS, NB), 256, ATTN_SMEM>>>();

    gemm_mma<1><<<dim3(NHID / 128, MM / 128), 256, GEMM_SMEM>>>(bo, nullptr,
                                                                nullptr, out);
}

// round 12
// speedup vs baseline: 1.3254x; 1.1414x over previous
#include <cuda_runtime.h>
#include <cuda_bf16.h>
#include <cuda_fp16.h>
#include <stdint.h>
#include <cstdint>
#include <math.h>

#define NB 2
#define NS 2048
#define NHID 1024
#define NHEADS 16
#define HDIM 64
#define MM (NB * NS)   // 4096

// ---------------- scratch (static device globals; no allocation) ----------
__device__ float g_cos[NS * 32];                 // rope tables [s][d]
__device__ float g_sin[NS * 32];
__device__ float g_q[NB * NHEADS * NS * HDIM];   // fp32 pre-rope [b,h,s,d]
__device__ float g_k[NB * NHEADS * NS * HDIM];

// split-bf16 operands (projection GEMMs)
__device__ __nv_bfloat16 g_xh[MM * NHID];
__device__ __nv_bfloat16 g_xl[MM * NHID];
__device__ __nv_bfloat16 g_wh[4 * NHID * NHID];  // Wq,Wk,Wv,Wo
__device__ __nv_bfloat16 g_wl[4 * NHID * NHID];
__device__ __nv_bfloat16 g_aoh[MM * NHID];       // attention output, split
__device__ __nv_bfloat16 g_aol[MM * NHID];
// attention operands in fp16: q split hi/lo (pre-scaled), k/v hi only
__device__ __half g_qh[NB * NHEADS * NS * HDIM];
__device__ __half g_ql[NB * NHEADS * NS * HDIM];
__device__ __half g_kh[NB * NHEADS * NS * HDIM];
__device__ __half g_vh[NB * NHEADS * NS * HDIM];

// Q pre-scale: 0.125 * log2(e)  (softmax runs in exp2 domain)
#define QSCALE 0.18033688011112043f

// ---------------- mma.sync helpers (base sm_103 ISA) ------------------------
__device__ __forceinline__ uint32_t smem_u32(const void* p) {
    uint32_t a;
    asm("{ .reg .u64 t; cvta.to.shared.u64 t, %1; cvt.u32.u64 %0, t; }"
        : "=r"(a) : "l"(p));
    return a;
}
#define LDSM4(r0, r1, r2, r3, addr)                                          \
    asm volatile("ldmatrix.sync.aligned.m8n8.x4.shared.b16 {%0,%1,%2,%3}, [%4];" \
                 : "=r"(r0), "=r"(r1), "=r"(r2), "=r"(r3) : "r"(addr))
#define LDSM4T(r0, r1, r2, r3, addr)                                         \
    asm volatile(                                                            \
        "ldmatrix.sync.aligned.m8n8.x4.trans.shared.b16 {%0,%1,%2,%3}, [%4];" \
        : "=r"(r0), "=r"(r1), "=r"(r2), "=r"(r3) : "r"(addr))

__device__ __forceinline__ void mma_bf16(float* d, const uint32_t* a,
                                         const uint32_t* b) {
    asm volatile(
        "mma.sync.aligned.m16n8k16.row.col.f32.bf16.bf16.f32 "
        "{%0,%1,%2,%3}, {%4,%5,%6,%7}, {%8,%9}, {%0,%1,%2,%3};"
        : "+f"(d[0]), "+f"(d[1]), "+f"(d[2]), "+f"(d[3])
        : "r"(a[0]), "r"(a[1]), "r"(a[2]), "r"(a[3]), "r"(b[0]), "r"(b[1]));
}
__device__ __forceinline__ void mma_f16(float* d, const uint32_t* a,
                                        const uint32_t* b) {
    asm volatile(
        "mma.sync.aligned.m16n8k16.row.col.f32.f16.f16.f32 "
        "{%0,%1,%2,%3}, {%4,%5,%6,%7}, {%8,%9}, {%0,%1,%2,%3};"
        : "+f"(d[0]), "+f"(d[1]), "+f"(d[2]), "+f"(d[3])
        : "r"(a[0]), "r"(a[1]), "r"(a[2]), "r"(a[3]), "r"(b[0]), "r"(b[1]));
}

__device__ __forceinline__ uint32_t pkbf(float a, float b) {
    __nv_bfloat162 t = __floats2bfloat162_rn(a, b);
    return *(uint32_t*)&t;
}
__device__ __forceinline__ uint32_t pkh(float a, float b) {
    __half2 t = __floats2half2_rn(a, b);
    return *(uint32_t*)&t;
}
// bf16 pair split
__device__ __forceinline__ uint32_t split2(float a, float b, uint32_t& lo) {
    uint32_t hi = pkbf(a, b);
    __nv_bfloat162 hb = *(__nv_bfloat162*)&hi;
    float2 hf = __bfloat1622float2(hb);
    lo = pkbf(a - hf.x, b - hf.y);
    return hi;
}
// fp16 pair split
__device__ __forceinline__ uint32_t split2h(float a, float b, uint32_t& lo) {
    uint32_t hi = pkh(a, b);
    __half2 hb = *(__half2*)&hi;
    float2 hf = __half22float2(hb);
    lo = pkh(a - hf.x, b - hf.y);
    return hi;
}
__device__ __forceinline__ float ex2f(float x) {
    float y;
    asm("ex2.approx.ftz.f32 %0, %1;" : "=f"(y) : "f"(x));
    return y;
}

// ---------------- cp.async helpers -----------------------------------------
__device__ __forceinline__ void cpa16(uint32_t dst, const void* src) {
    asm volatile("cp.async.cg.shared.global [%0], [%1], 16;"
                 :: "r"(dst), "l"(src));
}
#define CP_COMMIT() asm volatile("cp.async.commit_group;" ::: "memory")
#define CP_WAIT1() asm volatile("cp.async.wait_group 1;" ::: "memory")

// ---------------------------------------------------------------------------
// Merged split conversion: x then Wq,Wk,Wv,Wo in one launch.
// ---------------------------------------------------------------------------
__global__ __launch_bounds__(256) void cvt_all(const float* __restrict__ x,
                                               const float* __restrict__ Wq,
                                               const float* __restrict__ Wk,
                                               const float* __restrict__ Wv,
                                               const float* __restrict__ Wo) {
    const size_t i = 4ull * ((size_t)blockIdx.x * blockDim.x + threadIdx.x);
    const size_t XN = (size_t)MM * NHID;     // 4M
    const size_t WN = (size_t)NHID * NHID;   // 1M (2^20)
    const float* s;
    __nv_bfloat16 *h, *l;
    size_t o;
    if (i < XN) {
        s = x;
        o = i;
        h = g_xh;
        l = g_xl;
    } else {
        const size_t j = i - XN;
        const int w = (int)(j >> 20);
        o = j & (WN - 1);
        s = (w == 0) ? Wq : (w == 1) ? Wk : (w == 2) ? Wv : Wo;
        h = g_wh + (size_t)w * WN;
        l = g_wl + (size_t)w * WN;
    }
    float4 v = *(const float4*)(s + o);
    uint32_t h01, h23, l01, l23;
    h01 = split2(v.x, v.y, l01);
    h23 = split2(v.z, v.w, l23);
    *(uint32_t*)(h + o)     = h01;
    *(uint32_t*)(h + o + 2) = h23;
    *(uint32_t*)(l + o)     = l01;
    *(uint32_t*)(l + o + 2) = l23;
}

// ---------------------------------------------------------------------------
// RoPE cos/sin table (fp64, 65536 entries)
// ---------------------------------------------------------------------------
__global__ void rope_table() {
    const int t = blockIdx.x * blockDim.x + threadIdx.x;
    const int d = t & 31;
    const int s = t >> 5;
    const double inv = exp2(-(double)d * 0.41524101186092029);
    double sd, cd;
    sincos((double)s * inv, &sd, &cd);
    g_cos[t] = (float)cd;
    g_sin[t] = (float)sd;
}

// ---------------------------------------------------------------------------
// RoPE apply: reads fp32 q/k, rotates.
// Q: scaled by QSCALE, split fp16 hi/lo. K: single fp16.
// ---------------------------------------------------------------------------
__global__ __launch_bounds__(256) void rope_apply() {
    int t = blockIdx.x * blockDim.x + threadIdx.x;
    const int half = NB * NHEADS * NS * 8;
    const bool isq = (t < half);
    if (!isq) t -= half;
    const int dg = t & 7;
    const int s = (t >> 3) & (NS - 1);
    const int bh = t >> 14;

    const float4 c4 = *(const float4*)&g_cos[s * 32 + dg * 4];
    const float4 s4 = *(const float4*)&g_sin[s * 32 + dg * 4];

    const size_t off = ((size_t)bh * NS + s) * HDIM + dg * 4;
    const float* p = (isq ? g_q : g_k) + off;
    float4 x1 = *(const float4*)(p);
    float4 x2 = *(const float4*)(p + 32);
    float4 r1, r2;
    r1.x = x1.x * c4.x - x2.x * s4.x;  r2.x = x2.x * c4.x + x1.x * s4.x;
    r1.y = x1.y * c4.y - x2.y * s4.y;  r2.y = x2.y * c4.y + x1.y * s4.y;
    r1.z = x1.z * c4.z - x2.z * s4.z;  r2.z = x2.z * c4.z + x1.z * s4.z;
    r1.w = x1.w * c4.w - x2.w * s4.w;  r2.w = x2.w * c4.w + x1.w * s4.w;
    if (isq) {
        r1.x *= QSCALE; r1.y *= QSCALE; r1.z *= QSCALE; r1.w *= QSCALE;
        r2.x *= QSCALE; r2.y *= QSCALE; r2.z *= QSCALE; r2.w *= QSCALE;
        __half* dh = g_qh + off;
        __half* dl = g_ql + off;
        uint32_t h01, h23, l01, l23;
        h01 = split2h(r1.x, r1.y, l01);
        h23 = split2h(r1.z, r1.w, l23);
        *(uint32_t*)(dh)     = h01;
        *(uint32_t*)(dh + 2) = h23;
        *(uint32_t*)(dl)     = l01;
        *(uint32_t*)(dl + 2) = l23;
        h01 = split2h(r2.x, r2.y, l01);
        h23 = split2h(r2.z, r2.w, l23);
        *(uint32_t*)(dh + 32) = h01;
        *(uint32_t*)(dh + 34) = h23;
        *(uint32_t*)(dl + 32) = l01;
        *(uint32_t*)(dl + 34) = l23;
    } else {
        __half* dh = g_kh + off;
        *(uint32_t*)(dh)      = pkh(r1.x, r1.y);
        *(uint32_t*)(dh + 2)  = pkh(r1.z, r1.w);
        *(uint32_t*)(dh + 32) = pkh(r2.x, r2.y);
        *(uint32_t*)(dh + 34) = pkh(r2.z, r2.w);
    }
}

// ---------------------------------------------------------------------------
// HMMA GEMM, 2-stage cp.async pipeline (2 CTAs/SM). C = A*W^T + bias,
// split-bf16 3-pass.
// PROJ=0: z=0/1 -> fp32 g_q/g_k (rope applied separately), z=2 -> fp16 V.
// PROJ=1: out projection from g_aoh/g_aol to Cout fp32.
// ---------------------------------------------------------------------------
#define KC2 32
#define NKC2 (NHID / KC2)   // 32
#define GSTR 40
#define GSTAGE (4 * 128 * GSTR)     // bf16 elems per stage

template <int PROJ>
__global__ __launch_bounds__(256) void gemm_mma(const float* __restrict__ b0p,
                                                const float* __restrict__ b1p,
                                                const float* __restrict__ b2p,
                                                float* __restrict__ Cout) {
    extern __shared__ __nv_bfloat16 sb[];

    const int tid = threadIdx.x;
    const int wid = tid >> 5;
    const int lane = tid & 31;
    const int wr = wid >> 2;
    const int wc = wid & 3;

    const int n0 = blockIdx.x * 128;
    const int m0 = blockIdx.y * 128;
    const int z = PROJ ? 3 : blockIdx.z;

    const __nv_bfloat16* Ah = PROJ ? g_aoh : g_xh;
    const __nv_bfloat16* Al = PROJ ? g_aol : g_xl;
    const __nv_bfloat16* Wh = g_wh + (size_t)z * NHID * NHID;
    const __nv_bfloat16* Wl = g_wl + (size_t)z * NHID * NHID;
    const float* bias = PROJ ? b0p : (z == 0 ? b0p : (z == 1 ? b1p : b2p));

    const __nv_bfloat16* gsrc[4] = {Ah + (size_t)m0 * NHID, Al + (size_t)m0 * NHID,
                                    Wh + (size_t)n0 * NHID, Wl + (size_t)n0 * NHID};

    float acc[4][4][4];
#pragma unroll
    for (int mt = 0; mt < 4; mt++)
#pragma unroll
        for (int nt = 0; nt < 4; nt++)
#pragma unroll
            for (int e = 0; e < 4; e++) acc[mt][nt][e] = 0.0f;

    const uint32_t uS = smem_u32(sb);

    auto load_chunk = [&](int c, int stage) {
        const int kc = c * KC2;
        const uint32_t sdst = uS + 2u * (uint32_t)(stage * GSTAGE);
#pragma unroll
        for (int t = 0; t < 4; t++) {
            const uint32_t db = sdst + 2u * (uint32_t)(t * 128 * GSTR);
            const __nv_bfloat16* src = gsrc[t];
#pragma unroll
            for (int i = 0; i < 2; i++) {
                const int idx = tid + 256 * i;
                const int row = idx >> 2;
                const int seg = idx & 3;
                cpa16(db + 2u * (uint32_t)(row * GSTR + seg * 8),
                      src + (size_t)row * NHID + kc + seg * 8);
            }
        }
    };

    const int a_row = lane & 15;
    const int a_koff = (lane >> 4) * 8;
    const int b_row = (lane & 7) + ((lane >> 4) & 1) * 8;
    const int b_koff = ((lane >> 3) & 1) * 8;

    load_chunk(0, 0);
    CP_COMMIT();
    load_chunk(1, 1);
    CP_COMMIT();

    for (int c = 0; c < NKC2; c++) {
        CP_WAIT1();
        __syncthreads();

        const uint32_t sstage = uS + 2u * (uint32_t)((c & 1) * GSTAGE);
        const uint32_t uAh = sstage;
        const uint32_t uAl = sstage + 2u * (128 * GSTR);
        const uint32_t uWh = sstage + 2u * (2 * 128 * GSTR);
        const uint32_t uWl = sstage + 2u * (3 * 128 * GSTR);

#pragma unroll
        for (int k16 = 0; k16 < 2; k16++) {
            const int kel = k16 * 16;
            uint32_t ah[4][4], al[4][4], bh[8], bl[8];
#pragma unroll
            for (int mt = 0; mt < 4; mt++) {
                const uint32_t off =
                    2u * ((64 * wr + 16 * mt + a_row) * GSTR + kel + a_koff);
                LDSM4(ah[mt][0], ah[mt][1], ah[mt][2], ah[mt][3], uAh + off);
                LDSM4(al[mt][0], al[mt][1], al[mt][2], al[mt][3], uAl + off);
            }
#pragma unroll
            for (int np = 0; np < 2; np++) {
                const uint32_t off =
                    2u * ((32 * wc + 16 * np + b_row) * GSTR + kel + b_koff);
                LDSM4(bh[4 * np], bh[4 * np + 1], bh[4 * np + 2], bh[4 * np + 3],
                      uWh + off);
                LDSM4(bl[4 * np], bl[4 * np + 1], bl[4 * np + 2], bl[4 * np + 3],
                      uWl + off);
            }
#pragma unroll
            for (int mt = 0; mt < 4; mt++)
#pragma unroll
                for (int nt = 0; nt < 4; nt++) {
                    const uint32_t* bt_h = &bh[4 * (nt >> 1) + 2 * (nt & 1)];
                    const uint32_t* bt_l = &bl[4 * (nt >> 1) + 2 * (nt & 1)];
                    mma_bf16(acc[mt][nt], ah[mt], bt_h);
                    mma_bf16(acc[mt][nt], ah[mt], bt_l);
                    mma_bf16(acc[mt][nt], al[mt], bt_h);
                }
        }
        __syncthreads();
        if (c + 2 < NKC2) load_chunk(c + 2, c & 1);
        CP_COMMIT();
    }

    // ---- epilogue ----
    const int mrow = (lane >> 2);
    const int ncol = (lane & 3) * 2;
#pragma unroll
    for (int mt = 0; mt < 4; mt++) {
#pragma unroll
        for (int half = 0; half < 2; half++) {
            const int m = m0 + 64 * wr + 16 * mt + mrow + 8 * half;
#pragma unroll
            for (int nt = 0; nt < 4; nt++) {
                const int n = n0 + 32 * wc + 8 * nt + ncol;
                float v0 = acc[mt][nt][2 * half] + bias[n];
                float v1 = acc[mt][nt][2 * half + 1] + bias[n + 1];
                if (PROJ) {
                    *(float2*)&Cout[(size_t)m * NHID + n] = make_float2(v0, v1);
                } else {
                    const int bb = m >> 11;
                    const int s = m & (NS - 1);
                    const int h = n >> 6;
                    const int d = n & (HDIM - 1);
                    const size_t o =
                        (((size_t)(bb * NHEADS + h) * NS + s) * HDIM + d);
                    if (z == 2) {   // V: store fp16 hi only
                        *(uint32_t*)&g_vh[o] = pkh(v0, v1);
                    } else {
                        float* dst = (z == 0) ? g_q : g_k;
                        *(float2*)&dst[o] = make_float2(v0, v1);
                    }
                }
            }
        }
    }
}

// ---------------------------------------------------------------------------
// Flash attention, fp16 HMMA. S = (Qh+Ql)*Kh (2-pass), O = (Ph+Pl)*Vh (2-pass).
// CTA = (b, h, 128-row q tile); 8 warps x 16 q-rows; K/V tiles of 64;
// cp.async double-buffered; exp2-domain softmax; masked-warp skip.
// ---------------------------------------------------------------------------
#define BQ 128
#define BK 64
#define KSTR 72
#define KVSTAGE (2 * 64 * KSTR)   // fp16 elems per stage (kh,vh)

__global__ __launch_bounds__(256, 2) void attn_mma() {
    extern __shared__ __half sa_[];
    __half* sQh = sa_;                    // 128*72
    __half* sQl = sa_ + 128 * KSTR;
    __half* sKV = sa_ + 2 * 128 * KSTR;   // 2 stages of (kh, vh)

    const int qt = (int)(gridDim.x - 1) - (int)blockIdx.x;   // big tiles first
    const int h = blockIdx.y;
    const int b = blockIdx.z;
    const int tid = threadIdx.x;
    const int wid = tid >> 5;
    const int lane = tid & 31;

    const size_t bhoff = (size_t)(b * NHEADS + h) * NS * HDIM;
    const __half* kvsrc[2] = {g_kh + bhoff, g_vh + bhoff};

    const uint32_t uQh = smem_u32(sQh);
    const uint32_t uQl = smem_u32(sQl);
    const uint32_t uKV = smem_u32(sKV);

    auto load_tile = [&](int kt, int stage) {
        const uint32_t sdst = uKV + 2u * (uint32_t)(stage * KVSTAGE);
        const size_t gb = (size_t)kt * BK * HDIM;
#pragma unroll
        for (int t = 0; t < 2; t++) {
            const __half* src = kvsrc[t] + gb;
            const uint32_t db = sdst + 2u * (uint32_t)(t * 64 * KSTR);
#pragma unroll
            for (int i = 0; i < 2; i++) {
                const int idx = tid + 256 * i;
                const int row = idx >> 3;
                const int seg = idx & 7;
                cpa16(db + 2u * (uint32_t)(row * KSTR + seg * 8),
                      src + row * HDIM + seg * 8);
            }
        }
    };

    // ---- load Q tile (pre-scaled incl log2e, pre-split fp16) ----
    {
        const int row = tid >> 1;
        const int c0 = (tid & 1) * 32;
        const __half* sh = g_qh + bhoff + ((size_t)qt * BQ + row) * HDIM + c0;
        const __half* sl = g_ql + bhoff + ((size_t)qt * BQ + row) * HDIM + c0;
        __half* dh = sQh + row * KSTR + c0;
        __half* dl = sQl + row * KSTR + c0;
#pragma unroll
        for (int j = 0; j < 4; j++) {
            *(uint4*)(dh + 8 * j) = *(const uint4*)(sh + 8 * j);
            *(uint4*)(dl + 8 * j) = *(const uint4*)(sl + 8 * j);
        }
    }

    const int a_row = lane & 15;
    const int a_koff = (lane >> 4) * 8;
    const int b_row = (lane & 7) + ((lane >> 4) & 1) * 8;
    const int b_koff = ((lane >> 3) & 1) * 8;
    const int v_kr = (lane & 7) + 8 * ((lane >> 3) & 1);
    const int v_nc = 8 * (lane >> 4);

    float o[8][4];
#pragma unroll
    for (int j = 0; j < 8; j++)
#pragma unroll
        for (int e = 0; e < 4; e++) o[j][e] = 0.0f;
    float mi0 = -1e30f, mi1 = -1e30f, li0 = 0.0f, li1 = 0.0f;

    const int qrow0 = qt * BQ + wid * 16 + (lane >> 2);
    const int qrow1 = qrow0 + 8;
    const int kcbase = 2 * (lane & 3);
    const int wrow_max = qt * BQ + wid * 16 + 15;   // warp's last q row

    const int ktmax = 2 * qt + 1;   // >= 1 always
    load_tile(0, 0);
    CP_COMMIT();
    load_tile(1, 1);
    CP_COMMIT();

    for (int kt = 0; kt <= ktmax; kt++) {
        CP_WAIT1();
        __syncthreads();

        if (kt * BK <= wrow_max) {   // warp has at least one unmasked key
            const uint32_t sstage = uKV + 2u * (uint32_t)((kt & 1) * KVSTAGE);
            const uint32_t uKh = sstage;
            const uint32_t uVh = sstage + 2u * (64 * KSTR);

            // ---- S = Q @ K^T (exp2 domain), 2-pass fp16 ----
            float s[8][4];
#pragma unroll
            for (int j = 0; j < 8; j++)
#pragma unroll
                for (int e = 0; e < 4; e++) s[j][e] = 0.0f;

#pragma unroll
            for (int k16 = 0; k16 < 4; k16++) {
                const int kel = 16 * k16;
                uint32_t qh[4], ql[4], kh[4][4];
                {
                    const uint32_t off =
                        2u * ((wid * 16 + a_row) * KSTR + kel + a_koff);
                    LDSM4(qh[0], qh[1], qh[2], qh[3], uQh + off);
                    LDSM4(ql[0], ql[1], ql[2], ql[3], uQl + off);
                }
#pragma unroll
                for (int ng = 0; ng < 4; ng++) {
                    const uint32_t off =
                        2u * ((16 * ng + b_row) * KSTR + kel + b_koff);
                    LDSM4(kh[ng][0], kh[ng][1], kh[ng][2], kh[ng][3],
                          uKh + off);
                }
#pragma unroll
                for (int j = 0; j < 8; j++) {
                    const uint32_t* bh = &kh[j >> 1][2 * (j & 1)];
                    mma_f16(s[j], qh, bh);
                    mma_f16(s[j], ql, bh);
                }
            }

            // ---- causal mask ----
            if (kt * BK + BK - 1 > qrow0) {
#pragma unroll
                for (int j = 0; j < 8; j++) {
                    const int kc = kt * BK + 8 * j + kcbase;
                    if (kc > qrow0) s[j][0] = -1e30f;
                    if (kc + 1 > qrow0) s[j][1] = -1e30f;
                }
            }
            if (kt * BK + BK - 1 > qrow1) {
#pragma unroll
                for (int j = 0; j < 8; j++) {
                    const int kc = kt * BK + 8 * j + kcbase;
                    if (kc > qrow1) s[j][2] = -1e30f;
                    if (kc + 1 > qrow1) s[j][3] = -1e30f;
                }
            }

            // ---- online softmax (exp2) ----
            float mx0 = s[0][0], mx1 = s[0][2];
#pragma unroll
            for (int j = 0; j < 8; j++) {
                mx0 = fmaxf(mx0, fmaxf(s[j][0], s[j][1]));
                mx1 = fmaxf(mx1, fmaxf(s[j][2], s[j][3]));
            }
            mx0 = fmaxf(mx0, __shfl_xor_sync(0xffffffffu, mx0, 1));
            mx0 = fmaxf(mx0, __shfl_xor_sync(0xffffffffu, mx0, 2));
            mx1 = fmaxf(mx1, __shfl_xor_sync(0xffffffffu, mx1, 1));
            mx1 = fmaxf(mx1, __shfl_xor_sync(0xffffffffu, mx1, 2));

            const float mn0 = fmaxf(mi0, mx0);
            const float mn1 = fmaxf(mi1, mx1);
            const float cr0 = ex2f(mi0 - mn0);
            const float cr1 = ex2f(mi1 - mn1);

            float rs0 = 0.0f, rs1 = 0.0f;
#pragma unroll
            for (int j = 0; j < 8; j++) {
                s[j][0] = ex2f(s[j][0] - mn0);
                s[j][1] = ex2f(s[j][1] - mn0);
                s[j][2] = ex2f(s[j][2] - mn1);
                s[j][3] = ex2f(s[j][3] - mn1);
                rs0 += s[j][0] + s[j][1];
                rs1 += s[j][2] + s[j][3];
            }
            rs0 += __shfl_xor_sync(0xffffffffu, rs0, 1);
            rs0 += __shfl_xor_sync(0xffffffffu, rs0, 2);
            rs1 += __shfl_xor_sync(0xffffffffu, rs1, 1);
            rs1 += __shfl_xor_sync(0xffffffffu, rs1, 2);
            li0 = li0 * cr0 + rs0;
            li1 = li1 * cr1 + rs1;
            mi0 = mn0;
            mi1 = mn1;

#pragma unroll
            for (int j = 0; j < 8; j++) {
                o[j][0] *= cr0;
                o[j][1] *= cr0;
                o[j][2] *= cr1;
                o[j][3] *= cr1;
            }

            // ---- O += P @ V (2-pass: (Ph+Pl) * Vh) ----
#pragma unroll
            for (int t = 0; t < 4; t++) {
                uint32_t ph[4], pl[4];
                {
                    const float* p0 = s[2 * t];
                    const float* p1 = s[2 * t + 1];
                    ph[0] = split2h(p0[0], p0[1], pl[0]);
                    ph[1] = split2h(p0[2], p0[3], pl[1]);
                    ph[2] = split2h(p1[0], p1[1], pl[2]);
                    ph[3] = split2h(p1[2], p1[3], pl[3]);
                }
                const int kel = 16 * t;
                uint32_t vh[4][4];
#pragma unroll
                for (int ng = 0; ng < 4; ng++) {
                    const uint32_t off =
                        2u * ((kel + v_kr) * KSTR + 16 * ng + v_nc);
                    LDSM4T(vh[ng][0], vh[ng][1], vh[ng][2], vh[ng][3],
                           uVh + off);
                }
#pragma unroll
                for (int j = 0; j < 8; j++) {
                    const uint32_t* bvh = &vh[j >> 1][2 * (j & 1)];
                    mma_f16(o[j], ph, bvh);
                    mma_f16(o[j], pl, bvh);
                }
            }
        }

        __syncthreads();
        if (kt + 2 <= ktmax) load_tile(kt + 2, kt & 1);
        CP_COMMIT();
    }

    // ---- normalize + store SPLIT bf16 to g_aoh/g_aol [b, s, h*64+d] ----
    const float inv0 = 1.0f / li0;
    const float inv1 = 1.0f / li1;
    const size_t o0 = ((size_t)b * NS + qrow0) * NHID + h * HDIM;
    const size_t o1 = ((size_t)b * NS + qrow1) * NHID + h * HDIM;
#pragma unroll
    for (int j = 0; j < 8; j++) {
        const int d = 8 * j + kcbase;
        uint32_t lo;
        uint32_t hi = split2(o[j][0] * inv0, o[j][1] * inv0, lo);
        *(uint32_t*)&g_aoh[o0 + d] = hi;
        *(uint32_t*)&g_aol[o0 + d] = lo;
        hi = split2(o[j][2] * inv1, o[j][3] * inv1, lo);
        *(uint32_t*)&g_aoh[o1 + d] = hi;
        *(uint32_t*)&g_aol[o1 + d] = lo;
    }
}

// ---------------------------------------------------------------------------
extern "C" void kernel_launch(void* const* d_in, const int* in_sizes, int n_in,
                              void* d_out, int out_size) {
    const float* x  = (const float*)d_in[0];
    const float* Wq = (const float*)d_in[1];
    const float* bq = (const float*)d_in[2];
    const float* Wk = (const float*)d_in[3];
    const float* bk = (const float*)d_in[4];
    const float* Wv = (const float*)d_in[5];
    const float* bv = (const float*)d_in[6];
    const float* Wo = (const float*)d_in[7];
    const float* bo = (const float*)d_in[8];
    float* out = (float*)d_out;

    const int GEMM_SMEM = 2 * GSTAGE * 2;                       // 81920 B
    const int ATTN_SMEM = (2 * 128 * KSTR + 2 * KVSTAGE) * 2;   // 73728 B
    cudaFuncSetAttribute(gemm_mma<0>, cudaFuncAttributeMaxDynamicSharedMemorySize,
                         GEMM_SMEM);
    cudaFuncSetAttribute(gemm_mma<1>, cudaFuncAttributeMaxDynamicSharedMemorySize,
                         GEMM_SMEM);
    cudaFuncSetAttribute(attn_mma, cudaFuncAttributeMaxDynamicSharedMemorySize,
                         ATTN_SMEM);

    rope_table<<<NS * 32 / 256, 256>>>();

    // 4M (x) + 4x1M (weights) elems, 4 per thread
    cvt_all<<<(MM * NHID + 4 * NHID * NHID) / 1024, 256>>>(x, Wq, Wk, Wv, Wo);

    gemm_mma<0><<<dim3(NHID / 128, MM / 128, 3), 256, GEMM_SMEM>>>(bq, bk, bv,
                                                                   nullptr);

    rope_apply<<<2 * NB * NHEADS * NS * 8 / 256, 256>>>();

    attn_mma<<<dim3(NS / BQ, NHEADS, NB), 256, ATTN_SMEM>>>();

    gemm_mma<1><<<dim3(NHID / 128, MM / 128), 256, GEMM_SMEM>>>(bo, nullptr,
                                                                nullptr, out);
}

// round 13
// speedup vs baseline: 1.6319x; 1.2313x over previous
#include <cuda_runtime.h>
#include <cuda_bf16.h>
#include <cuda_fp16.h>
#include <stdint.h>
#include <cstdint>
#include <math.h>

#define NB 2
#define NS 2048
#define NHID 1024
#define NHEADS 16
#define HDIM 64
#define MM (NB * NS)   // 4096

// ---------------- scratch (static device globals; no allocation) ----------
__device__ float g_cos[NS * 32];                 // rope tables [s][d]
__device__ float g_sin[NS * 32];
__device__ float g_q[NB * NHEADS * NS * HDIM];   // fp32 pre-rope [b,h,s,d]
__device__ float g_k[NB * NHEADS * NS * HDIM];

// fp16 operands
__device__ __half g_xh[MM * NHID];               // x split hi/lo
__device__ __half g_xl[MM * NHID];
__device__ __half g_w[4 * NHID * NHID];          // Wq,Wk,Wv,Wo single fp16
__device__ __half g_aoh[MM * NHID];              // attention output split
__device__ __half g_aol[MM * NHID];
// attention operands: q split hi/lo (pre-scaled), k/v single fp16, [b,h,s,d]
__device__ __half g_qh[NB * NHEADS * NS * HDIM];
__device__ __half g_ql[NB * NHEADS * NS * HDIM];
__device__ __half g_kh[NB * NHEADS * NS * HDIM];
__device__ __half g_vh[NB * NHEADS * NS * HDIM];

// Q pre-scale: 0.125 * log2(e)  (softmax runs in exp2 domain)
#define QSCALE 0.18033688011112043f

// ---------------- mma.sync helpers (base sm_103 ISA) ------------------------
__device__ __forceinline__ uint32_t smem_u32(const void* p) {
    uint32_t a;
    asm("{ .reg .u64 t; cvta.to.shared.u64 t, %1; cvt.u32.u64 %0, t; }"
        : "=r"(a) : "l"(p));
    return a;
}
#define LDSM4(r0, r1, r2, r3, addr)                                          \
    asm volatile("ldmatrix.sync.aligned.m8n8.x4.shared.b16 {%0,%1,%2,%3}, [%4];" \
                 : "=r"(r0), "=r"(r1), "=r"(r2), "=r"(r3) : "r"(addr))
#define LDSM4T(r0, r1, r2, r3, addr)                                         \
    asm volatile(                                                            \
        "ldmatrix.sync.aligned.m8n8.x4.trans.shared.b16 {%0,%1,%2,%3}, [%4];" \
        : "=r"(r0), "=r"(r1), "=r"(r2), "=r"(r3) : "r"(addr))

__device__ __forceinline__ void mma_f16(float* d, const uint32_t* a,
                                        const uint32_t* b) {
    asm volatile(
        "mma.sync.aligned.m16n8k16.row.col.f32.f16.f16.f32 "
        "{%0,%1,%2,%3}, {%4,%5,%6,%7}, {%8,%9}, {%0,%1,%2,%3};"
        : "+f"(d[0]), "+f"(d[1]), "+f"(d[2]), "+f"(d[3])
        : "r"(a[0]), "r"(a[1]), "r"(a[2]), "r"(a[3]), "r"(b[0]), "r"(b[1]));
}

__device__ __forceinline__ uint32_t pkh(float a, float b) {
    __half2 t = __floats2half2_rn(a, b);
    return *(uint32_t*)&t;
}
// fp16 pair split
__device__ __forceinline__ uint32_t split2h(float a, float b, uint32_t& lo) {
    uint32_t hi = pkh(a, b);
    __half2 hb = *(__half2*)&hi;
    float2 hf = __half22float2(hb);
    lo = pkh(a - hf.x, b - hf.y);
    return hi;
}
__device__ __forceinline__ float ex2f(float x) {
    float y;
    asm("ex2.approx.ftz.f32 %0, %1;" : "=f"(y) : "f"(x));
    return y;
}

// ---------------- cp.async helpers -----------------------------------------
__device__ __forceinline__ void cpa16(uint32_t dst, const void* src) {
    asm volatile("cp.async.cg.shared.global [%0], [%1], 16;"
                 :: "r"(dst), "l"(src));
}
#define CP_COMMIT() asm volatile("cp.async.commit_group;" ::: "memory")
#define CP_WAIT1() asm volatile("cp.async.wait_group 1;" ::: "memory")

// ---------------------------------------------------------------------------
// Merged conversion: x -> fp16 hi/lo split; Wq..Wo -> single fp16.
// ---------------------------------------------------------------------------
__global__ __launch_bounds__(256) void cvt_all(const float* __restrict__ x,
                                               const float* __restrict__ Wq,
                                               const float* __restrict__ Wk,
                                               const float* __restrict__ Wv,
                                               const float* __restrict__ Wo) {
    const size_t i = 4ull * ((size_t)blockIdx.x * blockDim.x + threadIdx.x);
    const size_t XN = (size_t)MM * NHID;     // 4M
    const size_t WN = (size_t)NHID * NHID;   // 1M (2^20)
    if (i < XN) {
        float4 v = *(const float4*)(x + i);
        uint32_t h01, h23, l01, l23;
        h01 = split2h(v.x, v.y, l01);
        h23 = split2h(v.z, v.w, l23);
        *(uint32_t*)(g_xh + i)     = h01;
        *(uint32_t*)(g_xh + i + 2) = h23;
        *(uint32_t*)(g_xl + i)     = l01;
        *(uint32_t*)(g_xl + i + 2) = l23;
    } else {
        const size_t j = i - XN;
        const int w = (int)(j >> 20);
        const size_t o = j & (WN - 1);
        const float* s = (w == 0) ? Wq : (w == 1) ? Wk : (w == 2) ? Wv : Wo;
        float4 v = *(const float4*)(s + o);
        __half* d = g_w + (size_t)w * WN + o;
        *(uint32_t*)(d)     = pkh(v.x, v.y);
        *(uint32_t*)(d + 2) = pkh(v.z, v.w);
    }
}

// ---------------------------------------------------------------------------
// RoPE cos/sin table (fp64, 65536 entries)
// ---------------------------------------------------------------------------
__global__ void rope_table() {
    const int t = blockIdx.x * blockDim.x + threadIdx.x;
    const int d = t & 31;
    const int s = t >> 5;
    const double inv = exp2(-(double)d * 0.41524101186092029);
    double sd, cd;
    sincos((double)s * inv, &sd, &cd);
    g_cos[t] = (float)cd;
    g_sin[t] = (float)sd;
}

// ---------------------------------------------------------------------------
// RoPE apply: reads fp32 q/k, rotates.
// Q: scaled by QSCALE, split fp16 hi/lo. K: single fp16.
// ---------------------------------------------------------------------------
__global__ __launch_bounds__(256) void rope_apply() {
    int t = blockIdx.x * blockDim.x + threadIdx.x;
    const int half = NB * NHEADS * NS * 8;
    const bool isq = (t < half);
    if (!isq) t -= half;
    const int dg = t & 7;
    const int s = (t >> 3) & (NS - 1);
    const int bh = t >> 14;

    const float4 c4 = *(const float4*)&g_cos[s * 32 + dg * 4];
    const float4 s4 = *(const float4*)&g_sin[s * 32 + dg * 4];

    const size_t off = ((size_t)bh * NS + s) * HDIM + dg * 4;
    const float* p = (isq ? g_q : g_k) + off;
    float4 x1 = *(const float4*)(p);
    float4 x2 = *(const float4*)(p + 32);
    float4 r1, r2;
    r1.x = x1.x * c4.x - x2.x * s4.x;  r2.x = x2.x * c4.x + x1.x * s4.x;
    r1.y = x1.y * c4.y - x2.y * s4.y;  r2.y = x2.y * c4.y + x1.y * s4.y;
    r1.z = x1.z * c4.z - x2.z * s4.z;  r2.z = x2.z * c4.z + x1.z * s4.z;
    r1.w = x1.w * c4.w - x2.w * s4.w;  r2.w = x2.w * c4.w + x1.w * s4.w;
    if (isq) {
        r1.x *= QSCALE; r1.y *= QSCALE; r1.z *= QSCALE; r1.w *= QSCALE;
        r2.x *= QSCALE; r2.y *= QSCALE; r2.z *= QSCALE; r2.w *= QSCALE;
        __half* dh = g_qh + off;
        __half* dl = g_ql + off;
        uint32_t h01, h23, l01, l23;
        h01 = split2h(r1.x, r1.y, l01);
        h23 = split2h(r1.z, r1.w, l23);
        *(uint32_t*)(dh)     = h01;
        *(uint32_t*)(dh + 2) = h23;
        *(uint32_t*)(dl)     = l01;
        *(uint32_t*)(dl + 2) = l23;
        h01 = split2h(r2.x, r2.y, l01);
        h23 = split2h(r2.z, r2.w, l23);
        *(uint32_t*)(dh + 32) = h01;
        *(uint32_t*)(dh + 34) = h23;
        *(uint32_t*)(dl + 32) = l01;
        *(uint32_t*)(dl + 34) = l23;
    } else {
        __half* dh = g_kh + off;
        *(uint32_t*)(dh)      = pkh(r1.x, r1.y);
        *(uint32_t*)(dh + 2)  = pkh(r1.z, r1.w);
        *(uint32_t*)(dh + 32) = pkh(r2.x, r2.y);
        *(uint32_t*)(dh + 34) = pkh(r2.z, r2.w);
    }
}

// ---------------------------------------------------------------------------
// fp16 HMMA GEMM, 2-stage cp.async pipeline (2 CTAs/SM).
// C = (Ah + Al) * W^T + bias  (2-pass fp16 split-A, single-fp16 W).
// PROJ=0: z=0/1 -> fp32 g_q/g_k (rope applied separately), z=2 -> fp16 V.
// PROJ=1: out projection from g_aoh/g_aol to Cout fp32.
// ---------------------------------------------------------------------------
#define KC2 32
#define NKC2 (NHID / KC2)   // 32
#define GSTR 40
#define GSTAGE (3 * 128 * GSTR)     // fp16 elems per stage

template <int PROJ>
__global__ __launch_bounds__(256) void gemm_mma(const float* __restrict__ b0p,
                                                const float* __restrict__ b1p,
                                                const float* __restrict__ b2p,
                                                float* __restrict__ Cout) {
    extern __shared__ __half sb[];

    const int tid = threadIdx.x;
    const int wid = tid >> 5;
    const int lane = tid & 31;
    const int wr = wid >> 2;
    const int wc = wid & 3;

    const int n0 = blockIdx.x * 128;
    const int m0 = blockIdx.y * 128;
    const int z = PROJ ? 3 : blockIdx.z;

    const __half* Ah = PROJ ? g_aoh : g_xh;
    const __half* Al = PROJ ? g_aol : g_xl;
    const __half* W = g_w + (size_t)z * NHID * NHID;
    const float* bias = PROJ ? b0p : (z == 0 ? b0p : (z == 1 ? b1p : b2p));

    const __half* gsrc[3] = {Ah + (size_t)m0 * NHID, Al + (size_t)m0 * NHID,
                             W + (size_t)n0 * NHID};

    float acc[4][4][4];
#pragma unroll
    for (int mt = 0; mt < 4; mt++)
#pragma unroll
        for (int nt = 0; nt < 4; nt++)
#pragma unroll
            for (int e = 0; e < 4; e++) acc[mt][nt][e] = 0.0f;

    const uint32_t uS = smem_u32(sb);

    auto load_chunk = [&](int c, int stage) {
        const int kc = c * KC2;
        const uint32_t sdst = uS + 2u * (uint32_t)(stage * GSTAGE);
#pragma unroll
        for (int t = 0; t < 3; t++) {
            const uint32_t db = sdst + 2u * (uint32_t)(t * 128 * GSTR);
            const __half* src = gsrc[t];
#pragma unroll
            for (int i = 0; i < 2; i++) {
                const int idx = tid + 256 * i;
                const int row = idx >> 2;
                const int seg = idx & 3;
                cpa16(db + 2u * (uint32_t)(row * GSTR + seg * 8),
                      src + (size_t)row * NHID + kc + seg * 8);
            }
        }
    };

    const int a_row = lane & 15;
    const int a_koff = (lane >> 4) * 8;
    const int b_row = (lane & 7) + ((lane >> 4) & 1) * 8;
    const int b_koff = ((lane >> 3) & 1) * 8;

    load_chunk(0, 0);
    CP_COMMIT();
    load_chunk(1, 1);
    CP_COMMIT();

    for (int c = 0; c < NKC2; c++) {
        CP_WAIT1();
        __syncthreads();

        const uint32_t sstage = uS + 2u * (uint32_t)((c & 1) * GSTAGE);
        const uint32_t uAh = sstage;
        const uint32_t uAl = sstage + 2u * (128 * GSTR);
        const uint32_t uW  = sstage + 2u * (2 * 128 * GSTR);

#pragma unroll
        for (int k16 = 0; k16 < 2; k16++) {
            const int kel = k16 * 16;
            uint32_t ah[4][4], al[4][4], bh[8];
#pragma unroll
            for (int mt = 0; mt < 4; mt++) {
                const uint32_t off =
                    2u * ((64 * wr + 16 * mt + a_row) * GSTR + kel + a_koff);
                LDSM4(ah[mt][0], ah[mt][1], ah[mt][2], ah[mt][3], uAh + off);
                LDSM4(al[mt][0], al[mt][1], al[mt][2], al[mt][3], uAl + off);
            }
#pragma unroll
            for (int np = 0; np < 2; np++) {
                const uint32_t off =
                    2u * ((32 * wc + 16 * np + b_row) * GSTR + kel + b_koff);
                LDSM4(bh[4 * np], bh[4 * np + 1], bh[4 * np + 2], bh[4 * np + 3],
                      uW + off);
            }
#pragma unroll
            for (int mt = 0; mt < 4; mt++)
#pragma unroll
                for (int nt = 0; nt < 4; nt++) {
                    const uint32_t* bt = &bh[4 * (nt >> 1) + 2 * (nt & 1)];
                    mma_f16(acc[mt][nt], ah[mt], bt);
                    mma_f16(acc[mt][nt], al[mt], bt);
                }
        }
        __syncthreads();
        if (c + 2 < NKC2) load_chunk(c + 2, c & 1);
        CP_COMMIT();
    }

    // ---- epilogue ----
    const int mrow = (lane >> 2);
    const int ncol = (lane & 3) * 2;
#pragma unroll
    for (int mt = 0; mt < 4; mt++) {
#pragma unroll
        for (int half = 0; half < 2; half++) {
            const int m = m0 + 64 * wr + 16 * mt + mrow + 8 * half;
#pragma unroll
            for (int nt = 0; nt < 4; nt++) {
                const int n = n0 + 32 * wc + 8 * nt + ncol;
                float v0 = acc[mt][nt][2 * half] + bias[n];
                float v1 = acc[mt][nt][2 * half + 1] + bias[n + 1];
                if (PROJ) {
                    *(float2*)&Cout[(size_t)m * NHID + n] = make_float2(v0, v1);
                } else {
                    const int bb = m >> 11;
                    const int s = m & (NS - 1);
                    const int h = n >> 6;
                    const int d = n & (HDIM - 1);
                    const size_t o =
                        (((size_t)(bb * NHEADS + h) * NS + s) * HDIM + d);
                    if (z == 2) {   // V: store fp16 hi only
                        *(uint32_t*)&g_vh[o] = pkh(v0, v1);
                    } else {
                        float* dst = (z == 0) ? g_q : g_k;
                        *(float2*)&dst[o] = make_float2(v0, v1);
                    }
                }
            }
        }
    }
}

// ---------------------------------------------------------------------------
// Flash attention, fp16 HMMA. S = (Qh+Ql)*Kh (2-pass), O = (Ph+Pl)*Vh (2-pass).
// CTA = (b, h, 128-row q tile); 8 warps x 16 q-rows; K/V tiles of 64;
// cp.async double-buffered; exp2-domain softmax; masked-warp skip.
// ---------------------------------------------------------------------------
#define BQ 128
#define BK 64
#define KSTR 72
#define KVSTAGE (2 * 64 * KSTR)   // fp16 elems per stage (kh,vh)

__global__ __launch_bounds__(256, 2) void attn_mma() {
    extern __shared__ __half sa_[];
    __half* sQh = sa_;                    // 128*72
    __half* sQl = sa_ + 128 * KSTR;
    __half* sKV = sa_ + 2 * 128 * KSTR;   // 2 stages of (kh, vh)

    const int qt = (int)(gridDim.x - 1) - (int)blockIdx.x;   // big tiles first
    const int h = blockIdx.y;
    const int b = blockIdx.z;
    const int tid = threadIdx.x;
    const int wid = tid >> 5;
    const int lane = tid & 31;

    const size_t bhoff = (size_t)(b * NHEADS + h) * NS * HDIM;
    const __half* kvsrc[2] = {g_kh + bhoff, g_vh + bhoff};

    const uint32_t uQh = smem_u32(sQh);
    const uint32_t uQl = smem_u32(sQl);
    const uint32_t uKV = smem_u32(sKV);

    auto load_tile = [&](int kt, int stage) {
        const uint32_t sdst = uKV + 2u * (uint32_t)(stage * KVSTAGE);
        const size_t gb = (size_t)kt * BK * HDIM;
#pragma unroll
        for (int t = 0; t < 2; t++) {
            const __half* src = kvsrc[t] + gb;
            const uint32_t db = sdst + 2u * (uint32_t)(t * 64 * KSTR);
#pragma unroll
            for (int i = 0; i < 2; i++) {
                const int idx = tid + 256 * i;
                const int row = idx >> 3;
                const int seg = idx & 7;
                cpa16(db + 2u * (uint32_t)(row * KSTR + seg * 8),
                      src + row * HDIM + seg * 8);
            }
        }
    };

    // ---- load Q tile (pre-scaled incl log2e, pre-split fp16) ----
    {
        const int row = tid >> 1;
        const int c0 = (tid & 1) * 32;
        const __half* sh = g_qh + bhoff + ((size_t)qt * BQ + row) * HDIM + c0;
        const __half* sl = g_ql + bhoff + ((size_t)qt * BQ + row) * HDIM + c0;
        __half* dh = sQh + row * KSTR + c0;
        __half* dl = sQl + row * KSTR + c0;
#pragma unroll
        for (int j = 0; j < 4; j++) {
            *(uint4*)(dh + 8 * j) = *(const uint4*)(sh + 8 * j);
            *(uint4*)(dl + 8 * j) = *(const uint4*)(sl + 8 * j);
        }
    }

    const int a_row = lane & 15;
    const int a_koff = (lane >> 4) * 8;
    const int b_row = (lane & 7) + ((lane >> 4) & 1) * 8;
    const int b_koff = ((lane >> 3) & 1) * 8;
    const int v_kr = (lane & 7) + 8 * ((lane >> 3) & 1);
    const int v_nc = 8 * (lane >> 4);

    float o[8][4];
#pragma unroll
    for (int j = 0; j < 8; j++)
#pragma unroll
        for (int e = 0; e < 4; e++) o[j][e] = 0.0f;
    float mi0 = -1e30f, mi1 = -1e30f, li0 = 0.0f, li1 = 0.0f;

    const int qrow0 = qt * BQ + wid * 16 + (lane >> 2);
    const int qrow1 = qrow0 + 8;
    const int kcbase = 2 * (lane & 3);
    const int wrow_max = qt * BQ + wid * 16 + 15;   // warp's last q row

    const int ktmax = 2 * qt + 1;   // >= 1 always
    load_tile(0, 0);
    CP_COMMIT();
    load_tile(1, 1);
    CP_COMMIT();

    for (int kt = 0; kt <= ktmax; kt++) {
        CP_WAIT1();
        __syncthreads();

        if (kt * BK <= wrow_max) {   // warp has at least one unmasked key
            const uint32_t sstage = uKV + 2u * (uint32_t)((kt & 1) * KVSTAGE);
            const uint32_t uKh = sstage;
            const uint32_t uVh = sstage + 2u * (64 * KSTR);

            // ---- S = Q @ K^T (exp2 domain), 2-pass fp16 ----
            float s[8][4];
#pragma unroll
            for (int j = 0; j < 8; j++)
#pragma unroll
                for (int e = 0; e < 4; e++) s[j][e] = 0.0f;

#pragma unroll
            for (int k16 = 0; k16 < 4; k16++) {
                const int kel = 16 * k16;
                uint32_t qh[4], ql[4], kh[4][4];
                {
                    const uint32_t off =
                        2u * ((wid * 16 + a_row) * KSTR + kel + a_koff);
                    LDSM4(qh[0], qh[1], qh[2], qh[3], uQh + off);
                    LDSM4(ql[0], ql[1], ql[2], ql[3], uQl + off);
                }
#pragma unroll
                for (int ng = 0; ng < 4; ng++) {
                    const uint32_t off =
                        2u * ((16 * ng + b_row) * KSTR + kel + b_koff);
                    LDSM4(kh[ng][0], kh[ng][1], kh[ng][2], kh[ng][3],
                          uKh + off);
                }
#pragma unroll
                for (int j = 0; j < 8; j++) {
                    const uint32_t* bh = &kh[j >> 1][2 * (j & 1)];
                    mma_f16(s[j], qh, bh);
                    mma_f16(s[j], ql, bh);
                }
            }

            // ---- causal mask ----
            if (kt * BK + BK - 1 > qrow0) {
#pragma unroll
                for (int j = 0; j < 8; j++) {
                    const int kc = kt * BK + 8 * j + kcbase;
                    if (kc > qrow0) s[j][0] = -1e30f;
                    if (kc + 1 > qrow0) s[j][1] = -1e30f;
                }
            }
            if (kt * BK + BK - 1 > qrow1) {
#pragma unroll
                for (int j = 0; j < 8; j++) {
                    const int kc = kt * BK + 8 * j + kcbase;
                    if (kc > qrow1) s[j][2] = -1e30f;
                    if (kc + 1 > qrow1) s[j][3] = -1e30f;
                }
            }

            // ---- online softmax (exp2) ----
            float mx0 = s[0][0], mx1 = s[0][2];
#pragma unroll
            for (int j = 0; j < 8; j++) {
                mx0 = fmaxf(mx0, fmaxf(s[j][0], s[j][1]));
                mx1 = fmaxf(mx1, fmaxf(s[j][2], s[j][3]));
            }
            mx0 = fmaxf(mx0, __shfl_xor_sync(0xffffffffu, mx0, 1));
            mx0 = fmaxf(mx0, __shfl_xor_sync(0xffffffffu, mx0, 2));
            mx1 = fmaxf(mx1, __shfl_xor_sync(0xffffffffu, mx1, 1));
            mx1 = fmaxf(mx1, __shfl_xor_sync(0xffffffffu, mx1, 2));

            const float mn0 = fmaxf(mi0, mx0);
            const float mn1 = fmaxf(mi1, mx1);
            const float cr0 = ex2f(mi0 - mn0);
            const float cr1 = ex2f(mi1 - mn1);

            float rs0 = 0.0f, rs1 = 0.0f;
#pragma unroll
            for (int j = 0; j < 8; j++) {
                s[j][0] = ex2f(s[j][0] - mn0);
                s[j][1] = ex2f(s[j][1] - mn0);
                s[j][2] = ex2f(s[j][2] - mn1);
                s[j][3] = ex2f(s[j][3] - mn1);
                rs0 += s[j][0] + s[j][1];
                rs1 += s[j][2] + s[j][3];
            }
            rs0 += __shfl_xor_sync(0xffffffffu, rs0, 1);
            rs0 += __shfl_xor_sync(0xffffffffu, rs0, 2);
            rs1 += __shfl_xor_sync(0xffffffffu, rs1, 1);
            rs1 += __shfl_xor_sync(0xffffffffu, rs1, 2);
            li0 = li0 * cr0 + rs0;
            li1 = li1 * cr1 + rs1;
            mi0 = mn0;
            mi1 = mn1;

#pragma unroll
            for (int j = 0; j < 8; j++) {
                o[j][0] *= cr0;
                o[j][1] *= cr0;
                o[j][2] *= cr1;
                o[j][3] *= cr1;
            }

            // ---- O += P @ V (2-pass: (Ph+Pl) * Vh) ----
#pragma unroll
            for (int t = 0; t < 4; t++) {
                uint32_t ph[4], pl[4];
                {
                    const float* p0 = s[2 * t];
                    const float* p1 = s[2 * t + 1];
                    ph[0] = split2h(p0[0], p0[1], pl[0]);
                    ph[1] = split2h(p0[2], p0[3], pl[1]);
                    ph[2] = split2h(p1[0], p1[1], pl[2]);
                    ph[3] = split2h(p1[2], p1[3], pl[3]);
                }
                const int kel = 16 * t;
                uint32_t vh[4][4];
#pragma unroll
                for (int ng = 0; ng < 4; ng++) {
                    const uint32_t off =
                        2u * ((kel + v_kr) * KSTR + 16 * ng + v_nc);
                    LDSM4T(vh[ng][0], vh[ng][1], vh[ng][2], vh[ng][3],
                           uVh + off);
                }
#pragma unroll
                for (int j = 0; j < 8; j++) {
                    const uint32_t* bvh = &vh[j >> 1][2 * (j & 1)];
                    mma_f16(o[j], ph, bvh);
                    mma_f16(o[j], pl, bvh);
                }
            }
        }

        __syncthreads();
        if (kt + 2 <= ktmax) load_tile(kt + 2, kt & 1);
        CP_COMMIT();
    }

    // ---- normalize + store SPLIT fp16 to g_aoh/g_aol [b, s, h*64+d] ----
    const float inv0 = 1.0f / li0;
    const float inv1 = 1.0f / li1;
    const size_t o0 = ((size_t)b * NS + qrow0) * NHID + h * HDIM;
    const size_t o1 = ((size_t)b * NS + qrow1) * NHID + h * HDIM;
#pragma unroll
    for (int j = 0; j < 8; j++) {
        const int d = 8 * j + kcbase;
        uint32_t lo;
        uint32_t hi = split2h(o[j][0] * inv0, o[j][1] * inv0, lo);
        *(uint32_t*)&g_aoh[o0 + d] = hi;
        *(uint32_t*)&g_aol[o0 + d] = lo;
        hi = split2h(o[j][2] * inv1, o[j][3] * inv1, lo);
        *(uint32_t*)&g_aoh[o1 + d] = hi;
        *(uint32_t*)&g_aol[o1 + d] = lo;
    }
}

// ---------------------------------------------------------------------------
extern "C" void kernel_launch(void* const* d_in, const int* in_sizes, int n_in,
                              void* d_out, int out_size) {
    const float* x  = (const float*)d_in[0];
    const float* Wq = (const float*)d_in[1];
    const float* bq = (const float*)d_in[2];
    const float* Wk = (const float*)d_in[3];
    const float* bk = (const float*)d_in[4];
    const float* Wv = (const float*)d_in[5];
    const float* bv = (const float*)d_in[6];
    const float* Wo = (const float*)d_in[7];
    const float* bo = (const float*)d_in[8];
    float* out = (float*)d_out;

    const int GEMM_SMEM = 2 * GSTAGE * 2;                       // 61440 B
    const int ATTN_SMEM = (2 * 128 * KSTR + 2 * KVSTAGE) * 2;   // 73728 B
    cudaFuncSetAttribute(gemm_mma<0>, cudaFuncAttributeMaxDynamicSharedMemorySize,
                         GEMM_SMEM);
    cudaFuncSetAttribute(gemm_mma<1>, cudaFuncAttributeMaxDynamicSharedMemorySize,
                         GEMM_SMEM);
    cudaFuncSetAttribute(attn_mma, cudaFuncAttributeMaxDynamicSharedMemorySize,
                         ATTN_SMEM);

    rope_table<<<NS * 32 / 256, 256>>>();

    // 4M (x) + 4x1M (weights) elems, 4 per thread
    cvt_all<<<(MM * NHID + 4 * NHID * NHID) / 1024, 256>>>(x, Wq, Wk, Wv, Wo);

    gemm_mma<0><<<dim3(NHID / 128, MM / 128, 3), 256, GEMM_SMEM>>>(bq, bk, bv,
                                                                   nullptr);

    rope_apply<<<2 * NB * NHEADS * NS * 8 / 256, 256>>>();

    attn_mma<<<dim3(NS / BQ, NHEADS, NB), 256, ATTN_SMEM>>>();

    gemm_mma<1><<<dim3(NHID / 128, MM / 128), 256, GEMM_SMEM>>>(bo, nullptr,
                                                                nullptr, out);
}

// round 14
// speedup vs baseline: 1.8760x; 1.1496x over previous
#include <cuda_runtime.h>
#include <cuda_bf16.h>
#include <cuda_fp16.h>
#include <stdint.h>
#include <cstdint>
#include <math.h>

#define NB 2
#define NS 2048
#define NHID 1024
#define NHEADS 16
#define HDIM 64
#define MM (NB * NS)   // 4096

// ---------------- scratch (static device globals; no allocation) ----------
__device__ float g_cos[NS * 32];                 // rope tables [s][d]
__device__ float g_sin[NS * 32];
__device__ float g_q[NB * NHEADS * NS * HDIM];   // fp32 pre-rope [b,h,s,d]
__device__ float g_k[NB * NHEADS * NS * HDIM];

// fp16 operands
__device__ __half g_xh[MM * NHID];               // x split hi/lo
__device__ __half g_xl[MM * NHID];
__device__ __half g_w[4 * NHID * NHID];          // Wq,Wk,Wv,Wo single fp16
__device__ __half g_aoh[MM * NHID];              // attention output split
__device__ __half g_aol[MM * NHID];
// attention operands: q/k/v single fp16 (q pre-scaled), [b,h,s,d]
__device__ __half g_qh[NB * NHEADS * NS * HDIM];
__device__ __half g_kh[NB * NHEADS * NS * HDIM];
__device__ __half g_vh[NB * NHEADS * NS * HDIM];

// Q pre-scale: 0.125 * log2(e)  (softmax runs in exp2 domain)
#define QSCALE 0.18033688011112043f

// ---------------- mma.sync helpers (base sm_103 ISA) ------------------------
__device__ __forceinline__ uint32_t smem_u32(const void* p) {
    uint32_t a;
    asm("{ .reg .u64 t; cvta.to.shared.u64 t, %1; cvt.u32.u64 %0, t; }"
        : "=r"(a) : "l"(p));
    return a;
}
#define LDSM4(r0, r1, r2, r3, addr)                                          \
    asm volatile("ldmatrix.sync.aligned.m8n8.x4.shared.b16 {%0,%1,%2,%3}, [%4];" \
                 : "=r"(r0), "=r"(r1), "=r"(r2), "=r"(r3) : "r"(addr))
#define LDSM4T(r0, r1, r2, r3, addr)                                         \
    asm volatile(                                                            \
        "ldmatrix.sync.aligned.m8n8.x4.trans.shared.b16 {%0,%1,%2,%3}, [%4];" \
        : "=r"(r0), "=r"(r1), "=r"(r2), "=r"(r3) : "r"(addr))

__device__ __forceinline__ void mma_f16(float* d, const uint32_t* a,
                                        const uint32_t* b) {
    asm volatile(
        "mma.sync.aligned.m16n8k16.row.col.f32.f16.f16.f32 "
        "{%0,%1,%2,%3}, {%4,%5,%6,%7}, {%8,%9}, {%0,%1,%2,%3};"
        : "+f"(d[0]), "+f"(d[1]), "+f"(d[2]), "+f"(d[3])
        : "r"(a[0]), "r"(a[1]), "r"(a[2]), "r"(a[3]), "r"(b[0]), "r"(b[1]));
}

__device__ __forceinline__ uint32_t pkh(float a, float b) {
    __half2 t = __floats2half2_rn(a, b);
    return *(uint32_t*)&t;
}
// fp16 pair split
__device__ __forceinline__ uint32_t split2h(float a, float b, uint32_t& lo) {
    uint32_t hi = pkh(a, b);
    __half2 hb = *(__half2*)&hi;
    float2 hf = __half22float2(hb);
    lo = pkh(a - hf.x, b - hf.y);
    return hi;
}
__device__ __forceinline__ float ex2f(float x) {
    float y;
    asm("ex2.approx.ftz.f32 %0, %1;" : "=f"(y) : "f"(x));
    return y;
}

// ---------------- cp.async helpers -----------------------------------------
__device__ __forceinline__ void cpa16(uint32_t dst, const void* src) {
    asm volatile("cp.async.cg.shared.global [%0], [%1], 16;"
                 :: "r"(dst), "l"(src));
}
#define CP_COMMIT() asm volatile("cp.async.commit_group;" ::: "memory")
#define CP_WAIT1() asm volatile("cp.async.wait_group 1;" ::: "memory")

// ---------------------------------------------------------------------------
// Merged conversion: x -> fp16 hi/lo split; Wq..Wo -> single fp16.
// ---------------------------------------------------------------------------
__global__ __launch_bounds__(256) void cvt_all(const float* __restrict__ x,
                                               const float* __restrict__ Wq,
                                               const float* __restrict__ Wk,
                                               const float* __restrict__ Wv,
                                               const float* __restrict__ Wo) {
    const size_t i = 4ull * ((size_t)blockIdx.x * blockDim.x + threadIdx.x);
    const size_t XN = (size_t)MM * NHID;     // 4M
    const size_t WN = (size_t)NHID * NHID;   // 1M (2^20)
    if (i < XN) {
        float4 v = *(const float4*)(x + i);
        uint32_t h01, h23, l01, l23;
        h01 = split2h(v.x, v.y, l01);
        h23 = split2h(v.z, v.w, l23);
        *(uint32_t*)(g_xh + i)     = h01;
        *(uint32_t*)(g_xh + i + 2) = h23;
        *(uint32_t*)(g_xl + i)     = l01;
        *(uint32_t*)(g_xl + i + 2) = l23;
    } else {
        const size_t j = i - XN;
        const int w = (int)(j >> 20);
        const size_t o = j & (WN - 1);
        const float* s = (w == 0) ? Wq : (w == 1) ? Wk : (w == 2) ? Wv : Wo;
        float4 v = *(const float4*)(s + o);
        __half* d = g_w + (size_t)w * WN + o;
        *(uint32_t*)(d)     = pkh(v.x, v.y);
        *(uint32_t*)(d + 2) = pkh(v.z, v.w);
    }
}

// ---------------------------------------------------------------------------
// RoPE cos/sin table (fp64, 65536 entries)
// ---------------------------------------------------------------------------
__global__ void rope_table() {
    const int t = blockIdx.x * blockDim.x + threadIdx.x;
    const int d = t & 31;
    const int s = t >> 5;
    const double inv = exp2(-(double)d * 0.41524101186092029);
    double sd, cd;
    sincos((double)s * inv, &sd, &cd);
    g_cos[t] = (float)cd;
    g_sin[t] = (float)sd;
}

// ---------------------------------------------------------------------------
// RoPE apply: reads fp32 q/k, rotates, stores single fp16.
// Q additionally scaled by QSCALE.
// ---------------------------------------------------------------------------
__global__ __launch_bounds__(256) void rope_apply() {
    int t = blockIdx.x * blockDim.x + threadIdx.x;
    const int half = NB * NHEADS * NS * 8;
    const bool isq = (t < half);
    if (!isq) t -= half;
    const int dg = t & 7;
    const int s = (t >> 3) & (NS - 1);
    const int bh = t >> 14;

    const float4 c4 = *(const float4*)&g_cos[s * 32 + dg * 4];
    const float4 s4 = *(const float4*)&g_sin[s * 32 + dg * 4];

    const size_t off = ((size_t)bh * NS + s) * HDIM + dg * 4;
    const float* p = (isq ? g_q : g_k) + off;
    float4 x1 = *(const float4*)(p);
    float4 x2 = *(const float4*)(p + 32);
    float4 r1, r2;
    r1.x = x1.x * c4.x - x2.x * s4.x;  r2.x = x2.x * c4.x + x1.x * s4.x;
    r1.y = x1.y * c4.y - x2.y * s4.y;  r2.y = x2.y * c4.y + x1.y * s4.y;
    r1.z = x1.z * c4.z - x2.z * s4.z;  r2.z = x2.z * c4.z + x1.z * s4.z;
    r1.w = x1.w * c4.w - x2.w * s4.w;  r2.w = x2.w * c4.w + x1.w * s4.w;
    if (isq) {
        r1.x *= QSCALE; r1.y *= QSCALE; r1.z *= QSCALE; r1.w *= QSCALE;
        r2.x *= QSCALE; r2.y *= QSCALE; r2.z *= QSCALE; r2.w *= QSCALE;
    }
    __half* dh = (isq ? g_qh : g_kh) + off;
    *(uint32_t*)(dh)      = pkh(r1.x, r1.y);
    *(uint32_t*)(dh + 2)  = pkh(r1.z, r1.w);
    *(uint32_t*)(dh + 32) = pkh(r2.x, r2.y);
    *(uint32_t*)(dh + 34) = pkh(r2.z, r2.w);
}

// ---------------------------------------------------------------------------
// fp16 HMMA GEMM, 2-stage cp.async pipeline (2 CTAs/SM).
// C = (Ah + Al) * W^T + bias  (2-pass fp16 split-A, single-fp16 W).
// PROJ=0: z=0/1 -> fp32 g_q/g_k (rope applied separately), z=2 -> fp16 V.
// PROJ=1: out projection from g_aoh/g_aol to Cout fp32.
// ---------------------------------------------------------------------------
#define KC2 32
#define NKC2 (NHID / KC2)   // 32
#define GSTR 40
#define GSTAGE (3 * 128 * GSTR)     // fp16 elems per stage

template <int PROJ>
__global__ __launch_bounds__(256) void gemm_mma(const float* __restrict__ b0p,
                                                const float* __restrict__ b1p,
                                                const float* __restrict__ b2p,
                                                float* __restrict__ Cout) {
    extern __shared__ __half sb[];

    const int tid = threadIdx.x;
    const int wid = tid >> 5;
    const int lane = tid & 31;
    const int wr = wid >> 2;
    const int wc = wid & 3;

    const int n0 = blockIdx.x * 128;
    const int m0 = blockIdx.y * 128;
    const int z = PROJ ? 3 : blockIdx.z;

    const __half* Ah = PROJ ? g_aoh : g_xh;
    const __half* Al = PROJ ? g_aol : g_xl;
    const __half* W = g_w + (size_t)z * NHID * NHID;
    const float* bias = PROJ ? b0p : (z == 0 ? b0p : (z == 1 ? b1p : b2p));

    const __half* gsrc[3] = {Ah + (size_t)m0 * NHID, Al + (size_t)m0 * NHID,
                             W + (size_t)n0 * NHID};

    float acc[4][4][4];
#pragma unroll
    for (int mt = 0; mt < 4; mt++)
#pragma unroll
        for (int nt = 0; nt < 4; nt++)
#pragma unroll
            for (int e = 0; e < 4; e++) acc[mt][nt][e] = 0.0f;

    const uint32_t uS = smem_u32(sb);

    auto load_chunk = [&](int c, int stage) {
        const int kc = c * KC2;
        const uint32_t sdst = uS + 2u * (uint32_t)(stage * GSTAGE);
#pragma unroll
        for (int t = 0; t < 3; t++) {
            const uint32_t db = sdst + 2u * (uint32_t)(t * 128 * GSTR);
            const __half* src = gsrc[t];
#pragma unroll
            for (int i = 0; i < 2; i++) {
                const int idx = tid + 256 * i;
                const int row = idx >> 2;
                const int seg = idx & 3;
                cpa16(db + 2u * (uint32_t)(row * GSTR + seg * 8),
                      src + (size_t)row * NHID + kc + seg * 8);
            }
        }
    };

    const int a_row = lane & 15;
    const int a_koff = (lane >> 4) * 8;
    const int b_row = (lane & 7) + ((lane >> 4) & 1) * 8;
    const int b_koff = ((lane >> 3) & 1) * 8;

    load_chunk(0, 0);
    CP_COMMIT();
    load_chunk(1, 1);
    CP_COMMIT();

    for (int c = 0; c < NKC2; c++) {
        CP_WAIT1();
        __syncthreads();

        const uint32_t sstage = uS + 2u * (uint32_t)((c & 1) * GSTAGE);
        const uint32_t uAh = sstage;
        const uint32_t uAl = sstage + 2u * (128 * GSTR);
        const uint32_t uW  = sstage + 2u * (2 * 128 * GSTR);

#pragma unroll
        for (int k16 = 0; k16 < 2; k16++) {
            const int kel = k16 * 16;
            uint32_t ah[4][4], al[4][4], bh[8];
#pragma unroll
            for (int mt = 0; mt < 4; mt++) {
                const uint32_t off =
                    2u * ((64 * wr + 16 * mt + a_row) * GSTR + kel + a_koff);
                LDSM4(ah[mt][0], ah[mt][1], ah[mt][2], ah[mt][3], uAh + off);
                LDSM4(al[mt][0], al[mt][1], al[mt][2], al[mt][3], uAl + off);
            }
#pragma unroll
            for (int np = 0; np < 2; np++) {
                const uint32_t off =
                    2u * ((32 * wc + 16 * np + b_row) * GSTR + kel + b_koff);
                LDSM4(bh[4 * np], bh[4 * np + 1], bh[4 * np + 2], bh[4 * np + 3],
                      uW + off);
            }
#pragma unroll
            for (int mt = 0; mt < 4; mt++)
#pragma unroll
                for (int nt = 0; nt < 4; nt++) {
                    const uint32_t* bt = &bh[4 * (nt >> 1) + 2 * (nt & 1)];
                    mma_f16(acc[mt][nt], ah[mt], bt);
                    mma_f16(acc[mt][nt], al[mt], bt);
                }
        }
        __syncthreads();
        if (c + 2 < NKC2) load_chunk(c + 2, c & 1);
        CP_COMMIT();
    }

    // ---- epilogue ----
    const int mrow = (lane >> 2);
    const int ncol = (lane & 3) * 2;
#pragma unroll
    for (int mt = 0; mt < 4; mt++) {
#pragma unroll
        for (int half = 0; half < 2; half++) {
            const int m = m0 + 64 * wr + 16 * mt + mrow + 8 * half;
#pragma unroll
            for (int nt = 0; nt < 4; nt++) {
                const int n = n0 + 32 * wc + 8 * nt + ncol;
                float v0 = acc[mt][nt][2 * half] + bias[n];
                float v1 = acc[mt][nt][2 * half + 1] + bias[n + 1];
                if (PROJ) {
                    *(float2*)&Cout[(size_t)m * NHID + n] = make_float2(v0, v1);
                } else {
                    const int bb = m >> 11;
                    const int s = m & (NS - 1);
                    const int h = n >> 6;
                    const int d = n & (HDIM - 1);
                    const size_t o =
                        (((size_t)(bb * NHEADS + h) * NS + s) * HDIM + d);
                    if (z == 2) {   // V: store fp16 hi only
                        *(uint32_t*)&g_vh[o] = pkh(v0, v1);
                    } else {
                        float* dst = (z == 0) ? g_q : g_k;
                        *(float2*)&dst[o] = make_float2(v0, v1);
                    }
                }
            }
        }
    }
}

// ---------------------------------------------------------------------------
// Flash attention, pure fp16 HMMA (single-pass S and PV).
// CTA = (b, h, 128-row q tile); 8 warps x 16 q-rows; K/V tiles of 64;
// cp.async double-buffered; exp2-domain softmax; masked-warp skip.
// ---------------------------------------------------------------------------
#define BQ 128
#define BK 64
#define KSTR 72
#define KVSTAGE (2 * 64 * KSTR)   // fp16 elems per stage (kh,vh)

__global__ __launch_bounds__(256, 2) void attn_mma() {
    extern __shared__ __half sa_[];
    __half* sQh = sa_;                    // 128*72
    __half* sKV = sa_ + 128 * KSTR;       // 2 stages of (kh, vh)

    const int qt = (int)(gridDim.x - 1) - (int)blockIdx.x;   // big tiles first
    const int h = blockIdx.y;
    const int b = blockIdx.z;
    const int tid = threadIdx.x;
    const int wid = tid >> 5;
    const int lane = tid & 31;

    const size_t bhoff = (size_t)(b * NHEADS + h) * NS * HDIM;
    const __half* kvsrc[2] = {g_kh + bhoff, g_vh + bhoff};

    const uint32_t uQh = smem_u32(sQh);
    const uint32_t uKV = smem_u32(sKV);

    auto load_tile = [&](int kt, int stage) {
        const uint32_t sdst = uKV + 2u * (uint32_t)(stage * KVSTAGE);
        const size_t gb = (size_t)kt * BK * HDIM;
#pragma unroll
        for (int t = 0; t < 2; t++) {
            const __half* src = kvsrc[t] + gb;
            const uint32_t db = sdst + 2u * (uint32_t)(t * 64 * KSTR);
#pragma unroll
            for (int i = 0; i < 2; i++) {
                const int idx = tid + 256 * i;
                const int row = idx >> 3;
                const int seg = idx & 7;
                cpa16(db + 2u * (uint32_t)(row * KSTR + seg * 8),
                      src + row * HDIM + seg * 8);
            }
        }
    };

    // ---- load Q tile (pre-scaled incl log2e, fp16) ----
    {
        const int row = tid >> 1;
        const int c0 = (tid & 1) * 32;
        const __half* sh = g_qh + bhoff + ((size_t)qt * BQ + row) * HDIM + c0;
        __half* dh = sQh + row * KSTR + c0;
#pragma unroll
        for (int j = 0; j < 4; j++)
            *(uint4*)(dh + 8 * j) = *(const uint4*)(sh + 8 * j);
    }

    const int a_row = lane & 15;
    const int a_koff = (lane >> 4) * 8;
    const int b_row = (lane & 7) + ((lane >> 4) & 1) * 8;
    const int b_koff = ((lane >> 3) & 1) * 8;
    const int v_kr = (lane & 7) + 8 * ((lane >> 3) & 1);
    const int v_nc = 8 * (lane >> 4);

    float o[8][4];
#pragma unroll
    for (int j = 0; j < 8; j++)
#pragma unroll
        for (int e = 0; e < 4; e++) o[j][e] = 0.0f;
    float mi0 = -1e30f, mi1 = -1e30f, li0 = 0.0f, li1 = 0.0f;

    const int qrow0 = qt * BQ + wid * 16 + (lane >> 2);
    const int qrow1 = qrow0 + 8;
    const int kcbase = 2 * (lane & 3);
    const int wrow_max = qt * BQ + wid * 16 + 15;   // warp's last q row

    const int ktmax = 2 * qt + 1;   // >= 1 always
    load_tile(0, 0);
    CP_COMMIT();
    load_tile(1, 1);
    CP_COMMIT();

    for (int kt = 0; kt <= ktmax; kt++) {
        CP_WAIT1();
        __syncthreads();

        if (kt * BK <= wrow_max) {   // warp has at least one unmasked key
            const uint32_t sstage = uKV + 2u * (uint32_t)((kt & 1) * KVSTAGE);
            const uint32_t uKh = sstage;
            const uint32_t uVh = sstage + 2u * (64 * KSTR);

            // ---- S = Q @ K^T (exp2 domain), fp16 single pass ----
            float s[8][4];
#pragma unroll
            for (int j = 0; j < 8; j++)
#pragma unroll
                for (int e = 0; e < 4; e++) s[j][e] = 0.0f;

#pragma unroll
            for (int k16 = 0; k16 < 4; k16++) {
                const int kel = 16 * k16;
                uint32_t qh[4], kh[4][4];
                {
                    const uint32_t off =
                        2u * ((wid * 16 + a_row) * KSTR + kel + a_koff);
                    LDSM4(qh[0], qh[1], qh[2], qh[3], uQh + off);
                }
#pragma unroll
                for (int ng = 0; ng < 4; ng++) {
                    const uint32_t off =
                        2u * ((16 * ng + b_row) * KSTR + kel + b_koff);
                    LDSM4(kh[ng][0], kh[ng][1], kh[ng][2], kh[ng][3],
                          uKh + off);
                }
#pragma unroll
                for (int j = 0; j < 8; j++)
                    mma_f16(s[j], qh, &kh[j >> 1][2 * (j & 1)]);
            }

            // ---- causal mask ----
            if (kt * BK + BK - 1 > qrow0) {
#pragma unroll
                for (int j = 0; j < 8; j++) {
                    const int kc = kt * BK + 8 * j + kcbase;
                    if (kc > qrow0) s[j][0] = -1e30f;
                    if (kc + 1 > qrow0) s[j][1] = -1e30f;
                }
            }
            if (kt * BK + BK - 1 > qrow1) {
#pragma unroll
                for (int j = 0; j < 8; j++) {
                    const int kc = kt * BK + 8 * j + kcbase;
                    if (kc > qrow1) s[j][2] = -1e30f;
                    if (kc + 1 > qrow1) s[j][3] = -1e30f;
                }
            }

            // ---- online softmax (exp2) ----
            float mx0 = s[0][0], mx1 = s[0][2];
#pragma unroll
            for (int j = 0; j < 8; j++) {
                mx0 = fmaxf(mx0, fmaxf(s[j][0], s[j][1]));
                mx1 = fmaxf(mx1, fmaxf(s[j][2], s[j][3]));
            }
            mx0 = fmaxf(mx0, __shfl_xor_sync(0xffffffffu, mx0, 1));
            mx0 = fmaxf(mx0, __shfl_xor_sync(0xffffffffu, mx0, 2));
            mx1 = fmaxf(mx1, __shfl_xor_sync(0xffffffffu, mx1, 1));
            mx1 = fmaxf(mx1, __shfl_xor_sync(0xffffffffu, mx1, 2));

            const float mn0 = fmaxf(mi0, mx0);
            const float mn1 = fmaxf(mi1, mx1);
            const float cr0 = ex2f(mi0 - mn0);
            const float cr1 = ex2f(mi1 - mn1);

            float rs0 = 0.0f, rs1 = 0.0f;
#pragma unroll
            for (int j = 0; j < 8; j++) {
                s[j][0] = ex2f(s[j][0] - mn0);
                s[j][1] = ex2f(s[j][1] - mn0);
                s[j][2] = ex2f(s[j][2] - mn1);
                s[j][3] = ex2f(s[j][3] - mn1);
                rs0 += s[j][0] + s[j][1];
                rs1 += s[j][2] + s[j][3];
            }
            rs0 += __shfl_xor_sync(0xffffffffu, rs0, 1);
            rs0 += __shfl_xor_sync(0xffffffffu, rs0, 2);
            rs1 += __shfl_xor_sync(0xffffffffu, rs1, 1);
            rs1 += __shfl_xor_sync(0xffffffffu, rs1, 2);
            li0 = li0 * cr0 + rs0;
            li1 = li1 * cr1 + rs1;
            mi0 = mn0;
            mi1 = mn1;

#pragma unroll
            for (int j = 0; j < 8; j++) {
                o[j][0] *= cr0;
                o[j][1] *= cr0;
                o[j][2] *= cr1;
                o[j][3] *= cr1;
            }

            // ---- O += P @ V (fp16 single pass) ----
#pragma unroll
            for (int t = 0; t < 4; t++) {
                uint32_t ph[4];
                {
                    const float* p0 = s[2 * t];
                    const float* p1 = s[2 * t + 1];
                    ph[0] = pkh(p0[0], p0[1]);
                    ph[1] = pkh(p0[2], p0[3]);
                    ph[2] = pkh(p1[0], p1[1]);
                    ph[3] = pkh(p1[2], p1[3]);
                }
                const int kel = 16 * t;
                uint32_t vh[4][4];
#pragma unroll
                for (int ng = 0; ng < 4; ng++) {
                    const uint32_t off =
                        2u * ((kel + v_kr) * KSTR + 16 * ng + v_nc);
                    LDSM4T(vh[ng][0], vh[ng][1], vh[ng][2], vh[ng][3],
                           uVh + off);
                }
#pragma unroll
                for (int j = 0; j < 8; j++)
                    mma_f16(o[j], ph, &vh[j >> 1][2 * (j & 1)]);
            }
        }

        __syncthreads();
        if (kt + 2 <= ktmax) load_tile(kt + 2, kt & 1);
        CP_COMMIT();
    }

    // ---- normalize + store SPLIT fp16 to g_aoh/g_aol [b, s, h*64+d] ----
    const float inv0 = 1.0f / li0;
    const float inv1 = 1.0f / li1;
    const size_t o0 = ((size_t)b * NS + qrow0) * NHID + h * HDIM;
    const size_t o1 = ((size_t)b * NS + qrow1) * NHID + h * HDIM;
#pragma unroll
    for (int j = 0; j < 8; j++) {
        const int d = 8 * j + kcbase;
        uint32_t lo;
        uint32_t hi = split2h(o[j][0] * inv0, o[j][1] * inv0, lo);
        *(uint32_t*)&g_aoh[o0 + d] = hi;
        *(uint32_t*)&g_aol[o0 + d] = lo;
        hi = split2h(o[j][2] * inv1, o[j][3] * inv1, lo);
        *(uint32_t*)&g_aoh[o1 + d] = hi;
        *(uint32_t*)&g_aol[o1 + d] = lo;
    }
}

// ---------------------------------------------------------------------------
extern "C" void kernel_launch(void* const* d_in, const int* in_sizes, int n_in,
                              void* d_out, int out_size) {
    const float* x  = (const float*)d_in[0];
    const float* Wq = (const float*)d_in[1];
    const float* bq = (const float*)d_in[2];
    const float* Wk = (const float*)d_in[3];
    const float* bk = (const float*)d_in[4];
    const float* Wv = (const float*)d_in[5];
    const float* bv = (const float*)d_in[6];
    const float* Wo = (const float*)d_in[7];
    const float* bo = (const float*)d_in[8];
    float* out = (float*)d_out;

    const int GEMM_SMEM = 2 * GSTAGE * 2;                   // 61440 B
    const int ATTN_SMEM = (128 * KSTR + 2 * KVSTAGE) * 2;   // 55296 B
    cudaFuncSetAttribute(gemm_mma<0>, cudaFuncAttributeMaxDynamicSharedMemorySize,
                         GEMM_SMEM);
    cudaFuncSetAttribute(gemm_mma<1>, cudaFuncAttributeMaxDynamicSharedMemorySize,
                         GEMM_SMEM);
    cudaFuncSetAttribute(attn_mma, cudaFuncAttributeMaxDynamicSharedMemorySize,
                         ATTN_SMEM);

    rope_table<<<NS * 32 / 256, 256>>>();

    // 4M (x) + 4x1M (weights) elems, 4 per thread
    cvt_all<<<(MM * NHID + 4 * NHID * NHID) / 1024, 256>>>(x, Wq, Wk, Wv, Wo);

    gemm_mma<0><<<dim3(NHID / 128, MM / 128, 3), 256, GEMM_SMEM>>>(bq, bk, bv,
                                                                   nullptr);

    rope_apply<<<2 * NB * NHEADS * NS * 8 / 256, 256>>>();

    attn_mma<<<dim3(NS / BQ, NHEADS, NB), 256, ATTN_SMEM>>>();

    gemm_mma<1><<<dim3(NHID / 128, MM / 128), 256, GEMM_SMEM>>>(bo, nullptr,
                                                                nullptr, out);
}

// round 15
// speedup vs baseline: 2.4948x; 1.3298x over previous
#include <cuda_runtime.h>
#include <cuda_bf16.h>
#include <cuda_fp16.h>
#include <stdint.h>
#include <cstdint>
#include <math.h>

#define NB 2
#define NS 2048
#define NHID 1024
#define NHEADS 16
#define HDIM 64
#define MM (NB * NS)   // 4096

// ---------------- scratch (static device globals; no allocation) ----------
__device__ float g_cos[NS * 32];                 // rope tables [s][d]
__device__ float g_sin[NS * 32];
__device__ float g_q[NB * NHEADS * NS * HDIM];   // fp32 pre-rope [b,h,s,d]
__device__ float g_k[NB * NHEADS * NS * HDIM];

// fp16 operands (all single precision-level now; ladder closed)
__device__ __half g_x[MM * NHID];                // x fp16
__device__ __half g_w[4 * NHID * NHID];          // Wq,Wk,Wv,Wo fp16
__device__ __half g_ao[MM * NHID];               // attention output fp16
// attention operands: q/k/v fp16 (q pre-scaled), [b,h,s,d]
__device__ __half g_qh[NB * NHEADS * NS * HDIM];
__device__ __half g_kh[NB * NHEADS * NS * HDIM];
__device__ __half g_vh[NB * NHEADS * NS * HDIM];

// Q pre-scale: 0.125 * log2(e)  (softmax runs in exp2 domain)
#define QSCALE 0.18033688011112043f

// ---------------- mma.sync helpers (base sm_103 ISA) ------------------------
__device__ __forceinline__ uint32_t smem_u32(const void* p) {
    uint32_t a;
    asm("{ .reg .u64 t; cvta.to.shared.u64 t, %1; cvt.u32.u64 %0, t; }"
        : "=r"(a) : "l"(p));
    return a;
}
#define LDSM4(r0, r1, r2, r3, addr)                                          \
    asm volatile("ldmatrix.sync.aligned.m8n8.x4.shared.b16 {%0,%1,%2,%3}, [%4];" \
                 : "=r"(r0), "=r"(r1), "=r"(r2), "=r"(r3) : "r"(addr))
#define LDSM4T(r0, r1, r2, r3, addr)                                         \
    asm volatile(                                                            \
        "ldmatrix.sync.aligned.m8n8.x4.trans.shared.b16 {%0,%1,%2,%3}, [%4];" \
        : "=r"(r0), "=r"(r1), "=r"(r2), "=r"(r3) : "r"(addr))

__device__ __forceinline__ void mma_f16(float* d, const uint32_t* a,
                                        const uint32_t* b) {
    asm volatile(
        "mma.sync.aligned.m16n8k16.row.col.f32.f16.f16.f32 "
        "{%0,%1,%2,%3}, {%4,%5,%6,%7}, {%8,%9}, {%0,%1,%2,%3};"
        : "+f"(d[0]), "+f"(d[1]), "+f"(d[2]), "+f"(d[3])
        : "r"(a[0]), "r"(a[1]), "r"(a[2]), "r"(a[3]), "r"(b[0]), "r"(b[1]));
}

__device__ __forceinline__ uint32_t pkh(float a, float b) {
    __half2 t = __floats2half2_rn(a, b);
    return *(uint32_t*)&t;
}
__device__ __forceinline__ float ex2f(float x) {
    float y;
    asm("ex2.approx.ftz.f32 %0, %1;" : "=f"(y) : "f"(x));
    return y;
}

// ---------------- cp.async helpers -----------------------------------------
__device__ __forceinline__ void cpa16(uint32_t dst, const void* src) {
    asm volatile("cp.async.cg.shared.global [%0], [%1], 16;"
                 :: "r"(dst), "l"(src));
}
#define CP_COMMIT() asm volatile("cp.async.commit_group;" ::: "memory")
#define CP_WAIT1() asm volatile("cp.async.wait_group 1;" ::: "memory")

// ---------------------------------------------------------------------------
// Merged conversion: x and Wq..Wo -> single fp16, one launch.
// ---------------------------------------------------------------------------
__global__ __launch_bounds__(256) void cvt_all(const float* __restrict__ x,
                                               const float* __restrict__ Wq,
                                               const float* __restrict__ Wk,
                                               const float* __restrict__ Wv,
                                               const float* __restrict__ Wo) {
    const size_t i = 4ull * ((size_t)blockIdx.x * blockDim.x + threadIdx.x);
    const size_t XN = (size_t)MM * NHID;     // 4M
    const size_t WN = (size_t)NHID * NHID;   // 1M (2^20)
    const float* s;
    __half* d;
    if (i < XN) {
        s = x + i;
        d = g_x + i;
    } else {
        const size_t j = i - XN;
        const int w = (int)(j >> 20);
        const size_t o = j & (WN - 1);
        s = ((w == 0) ? Wq : (w == 1) ? Wk : (w == 2) ? Wv : Wo) + o;
        d = g_w + (size_t)w * WN + o;
    }
    float4 v = *(const float4*)s;
    *(uint32_t*)(d)     = pkh(v.x, v.y);
    *(uint32_t*)(d + 2) = pkh(v.z, v.w);
}

// ---------------------------------------------------------------------------
// RoPE cos/sin table (fp64, 65536 entries)
// ---------------------------------------------------------------------------
__global__ void rope_table() {
    const int t = blockIdx.x * blockDim.x + threadIdx.x;
    const int d = t & 31;
    const int s = t >> 5;
    const double inv = exp2(-(double)d * 0.41524101186092029);
    double sd, cd;
    sincos((double)s * inv, &sd, &cd);
    g_cos[t] = (float)cd;
    g_sin[t] = (float)sd;
}

// ---------------------------------------------------------------------------
// RoPE apply: reads fp32 q/k, rotates, stores fp16 (Q scaled by QSCALE).
// ---------------------------------------------------------------------------
__global__ __launch_bounds__(256) void rope_apply() {
    int t = blockIdx.x * blockDim.x + threadIdx.x;
    const int half = NB * NHEADS * NS * 8;
    const bool isq = (t < half);
    if (!isq) t -= half;
    const int dg = t & 7;
    const int s = (t >> 3) & (NS - 1);
    const int bh = t >> 14;

    const float4 c4 = *(const float4*)&g_cos[s * 32 + dg * 4];
    const float4 s4 = *(const float4*)&g_sin[s * 32 + dg * 4];

    const size_t off = ((size_t)bh * NS + s) * HDIM + dg * 4;
    const float* p = (isq ? g_q : g_k) + off;
    float4 x1 = *(const float4*)(p);
    float4 x2 = *(const float4*)(p + 32);
    float4 r1, r2;
    r1.x = x1.x * c4.x - x2.x * s4.x;  r2.x = x2.x * c4.x + x1.x * s4.x;
    r1.y = x1.y * c4.y - x2.y * s4.y;  r2.y = x2.y * c4.y + x1.y * s4.y;
    r1.z = x1.z * c4.z - x2.z * s4.z;  r2.z = x2.z * c4.z + x1.z * s4.z;
    r1.w = x1.w * c4.w - x2.w * s4.w;  r2.w = x2.w * c4.w + x1.w * s4.w;
    if (isq) {
        r1.x *= QSCALE; r1.y *= QSCALE; r1.z *= QSCALE; r1.w *= QSCALE;
        r2.x *= QSCALE; r2.y *= QSCALE; r2.z *= QSCALE; r2.w *= QSCALE;
    }
    __half* dh = (isq ? g_qh : g_kh) + off;
    *(uint32_t*)(dh)      = pkh(r1.x, r1.y);
    *(uint32_t*)(dh + 2)  = pkh(r1.z, r1.w);
    *(uint32_t*)(dh + 32) = pkh(r2.x, r2.y);
    *(uint32_t*)(dh + 34) = pkh(r2.z, r2.w);
}

// ---------------------------------------------------------------------------
// fp16 HMMA GEMM, single-pass, 2-stage cp.async pipeline.
// C = A * W^T + bias.
// PROJ=0: z=0/1 -> fp32 g_q/g_k (rope applied separately), z=2 -> fp16 V.
// PROJ=1: out projection from g_ao to Cout fp32.
// ---------------------------------------------------------------------------
#define KC2 32
#define NKC2 (NHID / KC2)   // 32
#define GSTR 40
#define GSTAGE (2 * 128 * GSTR)     // fp16 elems per stage (A, W)

template <int PROJ>
__global__ __launch_bounds__(256) void gemm_mma(const float* __restrict__ b0p,
                                                const float* __restrict__ b1p,
                                                const float* __restrict__ b2p,
                                                float* __restrict__ Cout) {
    extern __shared__ __half sb[];

    const int tid = threadIdx.x;
    const int wid = tid >> 5;
    const int lane = tid & 31;
    const int wr = wid >> 2;
    const int wc = wid & 3;

    const int n0 = blockIdx.x * 128;
    const int m0 = blockIdx.y * 128;
    const int z = PROJ ? 3 : blockIdx.z;

    const __half* A = PROJ ? g_ao : g_x;
    const __half* W = g_w + (size_t)z * NHID * NHID;
    const float* bias = PROJ ? b0p : (z == 0 ? b0p : (z == 1 ? b1p : b2p));

    const __half* gsrc[2] = {A + (size_t)m0 * NHID, W + (size_t)n0 * NHID};

    float acc[4][4][4];
#pragma unroll
    for (int mt = 0; mt < 4; mt++)
#pragma unroll
        for (int nt = 0; nt < 4; nt++)
#pragma unroll
            for (int e = 0; e < 4; e++) acc[mt][nt][e] = 0.0f;

    const uint32_t uS = smem_u32(sb);

    auto load_chunk = [&](int c, int stage) {
        const int kc = c * KC2;
        const uint32_t sdst = uS + 2u * (uint32_t)(stage * GSTAGE);
#pragma unroll
        for (int t = 0; t < 2; t++) {
            const uint32_t db = sdst + 2u * (uint32_t)(t * 128 * GSTR);
            const __half* src = gsrc[t];
#pragma unroll
            for (int i = 0; i < 2; i++) {
                const int idx = tid + 256 * i;
                const int row = idx >> 2;
                const int seg = idx & 3;
                cpa16(db + 2u * (uint32_t)(row * GSTR + seg * 8),
                      src + (size_t)row * NHID + kc + seg * 8);
            }
        }
    };

    const int a_row = lane & 15;
    const int a_koff = (lane >> 4) * 8;
    const int b_row = (lane & 7) + ((lane >> 4) & 1) * 8;
    const int b_koff = ((lane >> 3) & 1) * 8;

    load_chunk(0, 0);
    CP_COMMIT();
    load_chunk(1, 1);
    CP_COMMIT();

    for (int c = 0; c < NKC2; c++) {
        CP_WAIT1();
        __syncthreads();

        const uint32_t sstage = uS + 2u * (uint32_t)((c & 1) * GSTAGE);
        const uint32_t uA = sstage;
        const uint32_t uW = sstage + 2u * (128 * GSTR);

#pragma unroll
        for (int k16 = 0; k16 < 2; k16++) {
            const int kel = k16 * 16;
            uint32_t ah[4][4], bh[8];
#pragma unroll
            for (int mt = 0; mt < 4; mt++) {
                const uint32_t off =
                    2u * ((64 * wr + 16 * mt + a_row) * GSTR + kel + a_koff);
                LDSM4(ah[mt][0], ah[mt][1], ah[mt][2], ah[mt][3], uA + off);
            }
#pragma unroll
            for (int np = 0; np < 2; np++) {
                const uint32_t off =
                    2u * ((32 * wc + 16 * np + b_row) * GSTR + kel + b_koff);
                LDSM4(bh[4 * np], bh[4 * np + 1], bh[4 * np + 2], bh[4 * np + 3],
                      uW + off);
            }
#pragma unroll
            for (int mt = 0; mt < 4; mt++)
#pragma unroll
                for (int nt = 0; nt < 4; nt++)
                    mma_f16(acc[mt][nt], ah[mt],
                            &bh[4 * (nt >> 1) + 2 * (nt & 1)]);
        }
        __syncthreads();
        if (c + 2 < NKC2) load_chunk(c + 2, c & 1);
        CP_COMMIT();
    }

    // ---- epilogue ----
    const int mrow = (lane >> 2);
    const int ncol = (lane & 3) * 2;
#pragma unroll
    for (int mt = 0; mt < 4; mt++) {
#pragma unroll
        for (int half = 0; half < 2; half++) {
            const int m = m0 + 64 * wr + 16 * mt + mrow + 8 * half;
#pragma unroll
            for (int nt = 0; nt < 4; nt++) {
                const int n = n0 + 32 * wc + 8 * nt + ncol;
                float v0 = acc[mt][nt][2 * half] + bias[n];
                float v1 = acc[mt][nt][2 * half + 1] + bias[n + 1];
                if (PROJ) {
                    *(float2*)&Cout[(size_t)m * NHID + n] = make_float2(v0, v1);
                } else {
                    const int bb = m >> 11;
                    const int s = m & (NS - 1);
                    const int h = n >> 6;
                    const int d = n & (HDIM - 1);
                    const size_t o =
                        (((size_t)(bb * NHEADS + h) * NS + s) * HDIM + d);
                    if (z == 2) {   // V: store fp16
                        *(uint32_t*)&g_vh[o] = pkh(v0, v1);
                    } else {
                        float* dst = (z == 0) ? g_q : g_k;
                        *(float2*)&dst[o] = make_float2(v0, v1);
                    }
                }
            }
        }
    }
}

// ---------------------------------------------------------------------------
// Flash attention, pure fp16 HMMA (single-pass S and PV).
// CTA = (b, h, 128-row q tile); 8 warps x 16 q-rows; K/V tiles of 64;
// cp.async double-buffered; exp2-domain softmax; masked-warp skip.
// ---------------------------------------------------------------------------
#define BQ 128
#define BK 64
#define KSTR 72
#define KVSTAGE (2 * 64 * KSTR)   // fp16 elems per stage (kh,vh)

__global__ __launch_bounds__(256, 2) void attn_mma() {
    extern __shared__ __half sa_[];
    __half* sQh = sa_;                    // 128*72
    __half* sKV = sa_ + 128 * KSTR;       // 2 stages of (kh, vh)

    const int qt = (int)(gridDim.x - 1) - (int)blockIdx.x;   // big tiles first
    const int h = blockIdx.y;
    const int b = blockIdx.z;
    const int tid = threadIdx.x;
    const int wid = tid >> 5;
    const int lane = tid & 31;

    const size_t bhoff = (size_t)(b * NHEADS + h) * NS * HDIM;
    const __half* kvsrc[2] = {g_kh + bhoff, g_vh + bhoff};

    const uint32_t uQh = smem_u32(sQh);
    const uint32_t uKV = smem_u32(sKV);

    auto load_tile = [&](int kt, int stage) {
        const uint32_t sdst = uKV + 2u * (uint32_t)(stage * KVSTAGE);
        const size_t gb = (size_t)kt * BK * HDIM;
#pragma unroll
        for (int t = 0; t < 2; t++) {
            const __half* src = kvsrc[t] + gb;
            const uint32_t db = sdst + 2u * (uint32_t)(t * 64 * KSTR);
#pragma unroll
            for (int i = 0; i < 2; i++) {
                const int idx = tid + 256 * i;
                const int row = idx >> 3;
                const int seg = idx & 7;
                cpa16(db + 2u * (uint32_t)(row * KSTR + seg * 8),
                      src + row * HDIM + seg * 8);
            }
        }
    };

    // ---- load Q tile (pre-scaled incl log2e, fp16) ----
    {
        const int row = tid >> 1;
        const int c0 = (tid & 1) * 32;
        const __half* sh = g_qh + bhoff + ((size_t)qt * BQ + row) * HDIM + c0;
        __half* dh = sQh + row * KSTR + c0;
#pragma unroll
        for (int j = 0; j < 4; j++)
            *(uint4*)(dh + 8 * j) = *(const uint4*)(sh + 8 * j);
    }

    const int a_row = lane & 15;
    const int a_koff = (lane >> 4) * 8;
    const int b_row = (lane & 7) + ((lane >> 4) & 1) * 8;
    const int b_koff = ((lane >> 3) & 1) * 8;
    const int v_kr = (lane & 7) + 8 * ((lane >> 3) & 1);
    const int v_nc = 8 * (lane >> 4);

    float o[8][4];
#pragma unroll
    for (int j = 0; j < 8; j++)
#pragma unroll
        for (int e = 0; e < 4; e++) o[j][e] = 0.0f;
    float mi0 = -1e30f, mi1 = -1e30f, li0 = 0.0f, li1 = 0.0f;

    const int qrow0 = qt * BQ + wid * 16 + (lane >> 2);
    const int qrow1 = qrow0 + 8;
    const int kcbase = 2 * (lane & 3);
    const int wrow_max = qt * BQ + wid * 16 + 15;   // warp's last q row

    const int ktmax = 2 * qt + 1;   // >= 1 always
    load_tile(0, 0);
    CP_COMMIT();
    load_tile(1, 1);
    CP_COMMIT();

    for (int kt = 0; kt <= ktmax; kt++) {
        CP_WAIT1();
        __syncthreads();

        if (kt * BK <= wrow_max) {   // warp has at least one unmasked key
            const uint32_t sstage = uKV + 2u * (uint32_t)((kt & 1) * KVSTAGE);
            const uint32_t uKh = sstage;
            const uint32_t uVh = sstage + 2u * (64 * KSTR);

            // ---- S = Q @ K^T (exp2 domain), fp16 single pass ----
            float s[8][4];
#pragma unroll
            for (int j = 0; j < 8; j++)
#pragma unroll
                for (int e = 0; e < 4; e++) s[j][e] = 0.0f;

#pragma unroll
            for (int k16 = 0; k16 < 4; k16++) {
                const int kel = 16 * k16;
                uint32_t qh[4], kh[4][4];
                {
                    const uint32_t off =
                        2u * ((wid * 16 + a_row) * KSTR + kel + a_koff);
                    LDSM4(qh[0], qh[1], qh[2], qh[3], uQh + off);
                }
#pragma unroll
                for (int ng = 0; ng < 4; ng++) {
                    const uint32_t off =
                        2u * ((16 * ng + b_row) * KSTR + kel + b_koff);
                    LDSM4(kh[ng][0], kh[ng][1], kh[ng][2], kh[ng][3],
                          uKh + off);
                }
#pragma unroll
                for (int j = 0; j < 8; j++)
                    mma_f16(s[j], qh, &kh[j >> 1][2 * (j & 1)]);
            }

            // ---- causal mask ----
            if (kt * BK + BK - 1 > qrow0) {
#pragma unroll
                for (int j = 0; j < 8; j++) {
                    const int kc = kt * BK + 8 * j + kcbase;
                    if (kc > qrow0) s[j][0] = -1e30f;
                    if (kc + 1 > qrow0) s[j][1] = -1e30f;
                }
            }
            if (kt * BK + BK - 1 > qrow1) {
#pragma unroll
                for (int j = 0; j < 8; j++) {
                    const int kc = kt * BK + 8 * j + kcbase;
                    if (kc > qrow1) s[j][2] = -1e30f;
                    if (kc + 1 > qrow1) s[j][3] = -1e30f;
                }
            }

            // ---- online softmax (exp2) ----
            float mx0 = s[0][0], mx1 = s[0][2];
#pragma unroll
            for (int j = 0; j < 8; j++) {
                mx0 = fmaxf(mx0, fmaxf(s[j][0], s[j][1]));
                mx1 = fmaxf(mx1, fmaxf(s[j][2], s[j][3]));
            }
            mx0 = fmaxf(mx0, __shfl_xor_sync(0xffffffffu, mx0, 1));
            mx0 = fmaxf(mx0, __shfl_xor_sync(0xffffffffu, mx0, 2));
            mx1 = fmaxf(mx1, __shfl_xor_sync(0xffffffffu, mx1, 1));
            mx1 = fmaxf(mx1, __shfl_xor_sync(0xffffffffu, mx1, 2));

            const float mn0 = fmaxf(mi0, mx0);
            const float mn1 = fmaxf(mi1, mx1);
            const float cr0 = ex2f(mi0 - mn0);
            const float cr1 = ex2f(mi1 - mn1);

            float rs0 = 0.0f, rs1 = 0.0f;
#pragma unroll
            for (int j = 0; j < 8; j++) {
                s[j][0] = ex2f(s[j][0] - mn0);
                s[j][1] = ex2f(s[j][1] - mn0);
                s[j][2] = ex2f(s[j][2] - mn1);
                s[j][3] = ex2f(s[j][3] - mn1);
                rs0 += s[j][0] + s[j][1];
                rs1 += s[j][2] + s[j][3];
            }
            rs0 += __shfl_xor_sync(0xffffffffu, rs0, 1);
            rs0 += __shfl_xor_sync(0xffffffffu, rs0, 2);
            rs1 += __shfl_xor_sync(0xffffffffu, rs1, 1);
            rs1 += __shfl_xor_sync(0xffffffffu, rs1, 2);
            li0 = li0 * cr0 + rs0;
            li1 = li1 * cr1 + rs1;
            mi0 = mn0;
            mi1 = mn1;

#pragma unroll
            for (int j = 0; j < 8; j++) {
                o[j][0] *= cr0;
                o[j][1] *= cr0;
                o[j][2] *= cr1;
                o[j][3] *= cr1;
            }

            // ---- O += P @ V (fp16 single pass) ----
#pragma unroll
            for (int t = 0; t < 4; t++) {
                uint32_t ph[4];
                {
                    const float* p0 = s[2 * t];
                    const float* p1 = s[2 * t + 1];
                    ph[0] = pkh(p0[0], p0[1]);
                    ph[1] = pkh(p0[2], p0[3]);
                    ph[2] = pkh(p1[0], p1[1]);
                    ph[3] = pkh(p1[2], p1[3]);
                }
                const int kel = 16 * t;
                uint32_t vh[4][4];
#pragma unroll
                for (int ng = 0; ng < 4; ng++) {
                    const uint32_t off =
                        2u * ((kel + v_kr) * KSTR + 16 * ng + v_nc);
                    LDSM4T(vh[ng][0], vh[ng][1], vh[ng][2], vh[ng][3],
                           uVh + off);
                }
#pragma unroll
                for (int j = 0; j < 8; j++)
                    mma_f16(o[j], ph, &vh[j >> 1][2 * (j & 1)]);
            }
        }

        __syncthreads();
        if (kt + 2 <= ktmax) load_tile(kt + 2, kt & 1);
        CP_COMMIT();
    }

    // ---- normalize + store fp16 to g_ao [b, s, h*64+d] ----
    const float inv0 = 1.0f / li0;
    const float inv1 = 1.0f / li1;
    const size_t o0 = ((size_t)b * NS + qrow0) * NHID + h * HDIM;
    const size_t o1 = ((size_t)b * NS + qrow1) * NHID + h * HDIM;
#pragma unroll
    for (int j = 0; j < 8; j++) {
        const int d = 8 * j + kcbase;
        *(uint32_t*)&g_ao[o0 + d] = pkh(o[j][0] * inv0, o[j][1] * inv0);
        *(uint32_t*)&g_ao[o1 + d] = pkh(o[j][2] * inv1, o[j][3] * inv1);
    }
}

// ---------------------------------------------------------------------------
extern "C" void kernel_launch(void* const* d_in, const int* in_sizes, int n_in,
                              void* d_out, int out_size) {
    const float* x  = (const float*)d_in[0];
    const float* Wq = (const float*)d_in[1];
    const float* bq = (const float*)d_in[2];
    const float* Wk = (const float*)d_in[3];
    const float* bk = (const float*)d_in[4];
    const float* Wv = (const float*)d_in[5];
    const float* bv = (const float*)d_in[6];
    const float* Wo = (const float*)d_in[7];
    const float* bo = (const float*)d_in[8];
    float* out = (float*)d_out;

    const int GEMM_SMEM = 2 * GSTAGE * 2;                   // 40960 B
    const int ATTN_SMEM = (128 * KSTR + 2 * KVSTAGE) * 2;   // 55296 B
    cudaFuncSetAttribute(gemm_mma<0>, cudaFuncAttributeMaxDynamicSharedMemorySize,
                         GEMM_SMEM);
    cudaFuncSetAttribute(gemm_mma<1>, cudaFuncAttributeMaxDynamicSharedMemorySize,
                         GEMM_SMEM);
    cudaFuncSetAttribute(attn_mma, cudaFuncAttributeMaxDynamicSharedMemorySize,
                         ATTN_SMEM);

    rope_table<<<NS * 32 / 256, 256>>>();

    // 4M (x) + 4x1M (weights) elems, 4 per thread
    cvt_all<<<(MM * NHID + 4 * NHID * NHID) / 1024, 256>>>(x, Wq, Wk, Wv, Wo);

    gemm_mma<0><<<dim3(NHID / 128, MM / 128, 3), 256, GEMM_SMEM>>>(bq, bk, bv,
                                                                   nullptr);

    rope_apply<<<2 * NB * NHEADS * NS * 8 / 256, 256>>>();

    attn_mma<<<dim3(NS / BQ, NHEADS, NB), 256, ATTN_SMEM>>>();

    gemm_mma<1><<<dim3(NHID / 128, MM / 128), 256, GEMM_SMEM>>>(bo, nullptr,
                                                                nullptr, out);
}

// round 16
// speedup vs baseline: 2.5990x; 1.0418x over previous
#include <cuda_runtime.h>
#include <cuda_bf16.h>
#include <cuda_fp16.h>
#include <stdint.h>
#include <cstdint>
#include <math.h>

#define NB 2
#define NS 2048
#define NHID 1024
#define NHEADS 16
#define HDIM 64
#define MM (NB * NS)   // 4096

// ---------------- scratch (static device globals; no allocation) ----------
__device__ float g_cos[NS * 32];                 // rope tables [s][d]
__device__ float g_sin[NS * 32];
__device__ float g_q[NB * NHEADS * NS * HDIM];   // fp32 pre-rope [b,h,s,d]
__device__ float g_k[NB * NHEADS * NS * HDIM];

// fp16 operands
__device__ __half g_x[MM * NHID];                // x fp16
__device__ __half g_w[4 * NHID * NHID];          // Wq,Wk,Wv,Wo fp16
__device__ __half g_ao[MM * NHID];               // attention output fp16
// attention operands: q/k/v fp16 (q pre-scaled), [b,h,s,d]
__device__ __half g_qh[NB * NHEADS * NS * HDIM];
__device__ __half g_kh[NB * NHEADS * NS * HDIM];
__device__ __half g_vh[NB * NHEADS * NS * HDIM];

// Q pre-scale: 0.125 * log2(e)  (softmax runs in exp2 domain)
#define QSCALE 0.18033688011112043f

// ---------------- mma.sync helpers (base sm_103 ISA) ------------------------
__device__ __forceinline__ uint32_t smem_u32(const void* p) {
    uint32_t a;
    asm("{ .reg .u64 t; cvta.to.shared.u64 t, %1; cvt.u32.u64 %0, t; }"
        : "=r"(a) : "l"(p));
    return a;
}
#define LDSM4(r0, r1, r2, r3, addr)                                          \
    asm volatile("ldmatrix.sync.aligned.m8n8.x4.shared.b16 {%0,%1,%2,%3}, [%4];" \
                 : "=r"(r0), "=r"(r1), "=r"(r2), "=r"(r3) : "r"(addr))
#define LDSM4T(r0, r1, r2, r3, addr)                                         \
    asm volatile(                                                            \
        "ldmatrix.sync.aligned.m8n8.x4.trans.shared.b16 {%0,%1,%2,%3}, [%4];" \
        : "=r"(r0), "=r"(r1), "=r"(r2), "=r"(r3) : "r"(addr))

__device__ __forceinline__ void mma_f16(float* d, const uint32_t* a,
                                        const uint32_t* b) {
    asm volatile(
        "mma.sync.aligned.m16n8k16.row.col.f32.f16.f16.f32 "
        "{%0,%1,%2,%3}, {%4,%5,%6,%7}, {%8,%9}, {%0,%1,%2,%3};"
        : "+f"(d[0]), "+f"(d[1]), "+f"(d[2]), "+f"(d[3])
        : "r"(a[0]), "r"(a[1]), "r"(a[2]), "r"(a[3]), "r"(b[0]), "r"(b[1]));
}

__device__ __forceinline__ uint32_t pkh(float a, float b) {
    __half2 t = __floats2half2_rn(a, b);
    return *(uint32_t*)&t;
}
__device__ __forceinline__ float ex2f(float x) {
    float y;
    asm("ex2.approx.ftz.f32 %0, %1;" : "=f"(y) : "f"(x));
    return y;
}

// ---------------- cp.async helpers -----------------------------------------
__device__ __forceinline__ void cpa16(uint32_t dst, const void* src) {
    asm volatile("cp.async.cg.shared.global [%0], [%1], 16;"
                 :: "r"(dst), "l"(src));
}
#define CP_COMMIT() asm volatile("cp.async.commit_group;" ::: "memory")
#define CP_WAIT1() asm volatile("cp.async.wait_group 1;" ::: "memory")

// ---------------------------------------------------------------------------
// Merged conversion: x and Wq..Wo -> single fp16, one launch.
// ---------------------------------------------------------------------------
__global__ __launch_bounds__(256) void cvt_all(const float* __restrict__ x,
                                               const float* __restrict__ Wq,
                                               const float* __restrict__ Wk,
                                               const float* __restrict__ Wv,
                                               const float* __restrict__ Wo) {
    const size_t i = 4ull * ((size_t)blockIdx.x * blockDim.x + threadIdx.x);
    const size_t XN = (size_t)MM * NHID;     // 4M
    const size_t WN = (size_t)NHID * NHID;   // 1M (2^20)
    const float* s;
    __half* d;
    if (i < XN) {
        s = x + i;
        d = g_x + i;
    } else {
        const size_t j = i - XN;
        const int w = (int)(j >> 20);
        const size_t o = j & (WN - 1);
        s = ((w == 0) ? Wq : (w == 1) ? Wk : (w == 2) ? Wv : Wo) + o;
        d = g_w + (size_t)w * WN + o;
    }
    float4 v = *(const float4*)s;
    *(uint32_t*)(d)     = pkh(v.x, v.y);
    *(uint32_t*)(d + 2) = pkh(v.z, v.w);
}

// ---------------------------------------------------------------------------
// RoPE cos/sin table (fp64, 65536 entries)
// ---------------------------------------------------------------------------
__global__ void rope_table() {
    const int t = blockIdx.x * blockDim.x + threadIdx.x;
    const int d = t & 31;
    const int s = t >> 5;
    const double inv = exp2(-(double)d * 0.41524101186092029);
    double sd, cd;
    sincos((double)s * inv, &sd, &cd);
    g_cos[t] = (float)cd;
    g_sin[t] = (float)sd;
}

// ---------------------------------------------------------------------------
// RoPE apply: reads fp32 q/k, rotates, stores fp16 (Q scaled by QSCALE).
// ---------------------------------------------------------------------------
__global__ __launch_bounds__(256) void rope_apply() {
    int t = blockIdx.x * blockDim.x + threadIdx.x;
    const int half = NB * NHEADS * NS * 8;
    const bool isq = (t < half);
    if (!isq) t -= half;
    const int dg = t & 7;
    const int s = (t >> 3) & (NS - 1);
    const int bh = t >> 14;

    const float4 c4 = *(const float4*)&g_cos[s * 32 + dg * 4];
    const float4 s4 = *(const float4*)&g_sin[s * 32 + dg * 4];

    const size_t off = ((size_t)bh * NS + s) * HDIM + dg * 4;
    const float* p = (isq ? g_q : g_k) + off;
    float4 x1 = *(const float4*)(p);
    float4 x2 = *(const float4*)(p + 32);
    float4 r1, r2;
    r1.x = x1.x * c4.x - x2.x * s4.x;  r2.x = x2.x * c4.x + x1.x * s4.x;
    r1.y = x1.y * c4.y - x2.y * s4.y;  r2.y = x2.y * c4.y + x1.y * s4.y;
    r1.z = x1.z * c4.z - x2.z * s4.z;  r2.z = x2.z * c4.z + x1.z * s4.z;
    r1.w = x1.w * c4.w - x2.w * s4.w;  r2.w = x2.w * c4.w + x1.w * s4.w;
    if (isq) {
        r1.x *= QSCALE; r1.y *= QSCALE; r1.z *= QSCALE; r1.w *= QSCALE;
        r2.x *= QSCALE; r2.y *= QSCALE; r2.z *= QSCALE; r2.w *= QSCALE;
    }
    __half* dh = (isq ? g_qh : g_kh) + off;
    *(uint32_t*)(dh)      = pkh(r1.x, r1.y);
    *(uint32_t*)(dh + 2)  = pkh(r1.z, r1.w);
    *(uint32_t*)(dh + 32) = pkh(r2.x, r2.y);
    *(uint32_t*)(dh + 34) = pkh(r2.z, r2.w);
}

// ---------------------------------------------------------------------------
// fp16 HMMA GEMM, single-pass, 3-stage cp.async pipeline, ONE barrier per
// K-chunk (load for c+2 issued into the disjoint third stage before compute).
// PROJ=0: z=0/1 -> fp32 g_q/g_k (rope applied separately), z=2 -> fp16 V.
// PROJ=1: out projection from g_ao to Cout fp32.
// ---------------------------------------------------------------------------
#define KC2 32
#define NKC2 (NHID / KC2)   // 32
#define GSTR 40
#define GSTAGE (2 * 128 * GSTR)     // fp16 elems per stage (A, W)
#define GNSTG 3

template <int PROJ>
__global__ __launch_bounds__(256) void gemm_mma(const float* __restrict__ b0p,
                                                const float* __restrict__ b1p,
                                                const float* __restrict__ b2p,
                                                float* __restrict__ Cout) {
    extern __shared__ __half sb[];

    const int tid = threadIdx.x;
    const int wid = tid >> 5;
    const int lane = tid & 31;
    const int wr = wid >> 2;
    const int wc = wid & 3;

    const int n0 = blockIdx.x * 128;
    const int m0 = blockIdx.y * 128;
    const int z = PROJ ? 3 : blockIdx.z;

    const __half* A = PROJ ? g_ao : g_x;
    const __half* W = g_w + (size_t)z * NHID * NHID;
    const float* bias = PROJ ? b0p : (z == 0 ? b0p : (z == 1 ? b1p : b2p));

    const __half* gsrc[2] = {A + (size_t)m0 * NHID, W + (size_t)n0 * NHID};

    float acc[4][4][4];
#pragma unroll
    for (int mt = 0; mt < 4; mt++)
#pragma unroll
        for (int nt = 0; nt < 4; nt++)
#pragma unroll
            for (int e = 0; e < 4; e++) acc[mt][nt][e] = 0.0f;

    const uint32_t uS = smem_u32(sb);

    auto load_chunk = [&](int c, int stage) {
        const int kc = c * KC2;
        const uint32_t sdst = uS + 2u * (uint32_t)(stage * GSTAGE);
#pragma unroll
        for (int t = 0; t < 2; t++) {
            const uint32_t db = sdst + 2u * (uint32_t)(t * 128 * GSTR);
            const __half* src = gsrc[t];
#pragma unroll
            for (int i = 0; i < 2; i++) {
                const int idx = tid + 256 * i;
                const int row = idx >> 2;
                const int seg = idx & 3;
                cpa16(db + 2u * (uint32_t)(row * GSTR + seg * 8),
                      src + (size_t)row * NHID + kc + seg * 8);
            }
        }
    };

    const int a_row = lane & 15;
    const int a_koff = (lane >> 4) * 8;
    const int b_row = (lane & 7) + ((lane >> 4) & 1) * 8;
    const int b_koff = ((lane >> 3) & 1) * 8;

    load_chunk(0, 0);
    CP_COMMIT();
    load_chunk(1, 1);
    CP_COMMIT();

    int stg = 0;   // stage holding chunk c
    for (int c = 0; c < NKC2; c++) {
        CP_WAIT1();
        __syncthreads();

        // issue the next+2 load into the free third stage BEFORE compute
        const int lstg = (stg + 2 >= GNSTG) ? stg + 2 - GNSTG : stg + 2;
        if (c + 2 < NKC2) load_chunk(c + 2, lstg);
        CP_COMMIT();

        const uint32_t sstage = uS + 2u * (uint32_t)(stg * GSTAGE);
        const uint32_t uA = sstage;
        const uint32_t uW = sstage + 2u * (128 * GSTR);

#pragma unroll
        for (int k16 = 0; k16 < 2; k16++) {
            const int kel = k16 * 16;
            uint32_t ah[4][4], bh[8];
#pragma unroll
            for (int mt = 0; mt < 4; mt++) {
                const uint32_t off =
                    2u * ((64 * wr + 16 * mt + a_row) * GSTR + kel + a_koff);
                LDSM4(ah[mt][0], ah[mt][1], ah[mt][2], ah[mt][3], uA + off);
            }
#pragma unroll
            for (int np = 0; np < 2; np++) {
                const uint32_t off =
                    2u * ((32 * wc + 16 * np + b_row) * GSTR + kel + b_koff);
                LDSM4(bh[4 * np], bh[4 * np + 1], bh[4 * np + 2], bh[4 * np + 3],
                      uW + off);
            }
#pragma unroll
            for (int mt = 0; mt < 4; mt++)
#pragma unroll
                for (int nt = 0; nt < 4; nt++)
                    mma_f16(acc[mt][nt], ah[mt],
                            &bh[4 * (nt >> 1) + 2 * (nt & 1)]);
        }
        stg = (stg + 1 >= GNSTG) ? 0 : stg + 1;
    }

    // ---- epilogue ----
    const int mrow = (lane >> 2);
    const int ncol = (lane & 3) * 2;
#pragma unroll
    for (int mt = 0; mt < 4; mt++) {
#pragma unroll
        for (int half = 0; half < 2; half++) {
            const int m = m0 + 64 * wr + 16 * mt + mrow + 8 * half;
#pragma unroll
            for (int nt = 0; nt < 4; nt++) {
                const int n = n0 + 32 * wc + 8 * nt + ncol;
                float v0 = acc[mt][nt][2 * half] + bias[n];
                float v1 = acc[mt][nt][2 * half + 1] + bias[n + 1];
                if (PROJ) {
                    *(float2*)&Cout[(size_t)m * NHID + n] = make_float2(v0, v1);
                } else {
                    const int bb = m >> 11;
                    const int s = m & (NS - 1);
                    const int h = n >> 6;
                    const int d = n & (HDIM - 1);
                    const size_t o =
                        (((size_t)(bb * NHEADS + h) * NS + s) * HDIM + d);
                    if (z == 2) {   // V: store fp16
                        *(uint32_t*)&g_vh[o] = pkh(v0, v1);
                    } else {
                        float* dst = (z == 0) ? g_q : g_k;
                        *(float2*)&dst[o] = make_float2(v0, v1);
                    }
                }
            }
        }
    }
}

// ---------------------------------------------------------------------------
// Flash attention, pure fp16 HMMA (single-pass S and PV).
// CTA = (b, h, 128-row q tile); 8 warps x 16 q-rows; K/V tiles of 64;
// Q fragments hoisted to registers; 3-stage cp.async KV ring with ONE
// barrier per tile; exp2-domain softmax; masked-warp skip.
// ---------------------------------------------------------------------------
#define BQ 128
#define BK 64
#define KSTR 72
#define KVSTAGE (2 * 64 * KSTR)   // fp16 elems per stage (kh,vh)
#define ANSTG 3

__global__ __launch_bounds__(256, 2) void attn_mma() {
    extern __shared__ __half sa_[];
    __half* sQh = sa_;                    // 128*72 (used once for Q hoist)
    __half* sKV = sa_ + 128 * KSTR;       // 3 stages of (kh, vh)

    const int qt = (int)(gridDim.x - 1) - (int)blockIdx.x;   // big tiles first
    const int h = blockIdx.y;
    const int b = blockIdx.z;
    const int tid = threadIdx.x;
    const int wid = tid >> 5;
    const int lane = tid & 31;

    const size_t bhoff = (size_t)(b * NHEADS + h) * NS * HDIM;
    const __half* kvsrc[2] = {g_kh + bhoff, g_vh + bhoff};

    const uint32_t uQh = smem_u32(sQh);
    const uint32_t uKV = smem_u32(sKV);

    auto load_tile = [&](int kt, int stage) {
        const uint32_t sdst = uKV + 2u * (uint32_t)(stage * KVSTAGE);
        const size_t gb = (size_t)kt * BK * HDIM;
#pragma unroll
        for (int t = 0; t < 2; t++) {
            const __half* src = kvsrc[t] + gb;
            const uint32_t db = sdst + 2u * (uint32_t)(t * 64 * KSTR);
#pragma unroll
            for (int i = 0; i < 2; i++) {
                const int idx = tid + 256 * i;
                const int row = idx >> 3;
                const int seg = idx & 7;
                cpa16(db + 2u * (uint32_t)(row * KSTR + seg * 8),
                      src + row * HDIM + seg * 8);
            }
        }
    };

    // ---- stage Q tile to smem (pre-scaled incl log2e, fp16) ----
    {
        const int row = tid >> 1;
        const int c0 = (tid & 1) * 32;
        const __half* sh = g_qh + bhoff + ((size_t)qt * BQ + row) * HDIM + c0;
        __half* dh = sQh + row * KSTR + c0;
#pragma unroll
        for (int j = 0; j < 4; j++)
            *(uint4*)(dh + 8 * j) = *(const uint4*)(sh + 8 * j);
    }

    const int a_row = lane & 15;
    const int a_koff = (lane >> 4) * 8;
    const int b_row = (lane & 7) + ((lane >> 4) & 1) * 8;
    const int b_koff = ((lane >> 3) & 1) * 8;
    const int v_kr = (lane & 7) + 8 * ((lane >> 3) & 1);
    const int v_nc = 8 * (lane >> 4);

    const int ktmax = 2 * qt + 1;   // >= 1 always
    load_tile(0, 0);
    CP_COMMIT();
    load_tile(1, 1);
    CP_COMMIT();

    // ---- hoist Q fragments to registers (loop-invariant) ----
    __syncthreads();
    uint32_t qf[4][4];
#pragma unroll
    for (int k16 = 0; k16 < 4; k16++) {
        const uint32_t off =
            2u * ((wid * 16 + a_row) * KSTR + 16 * k16 + a_koff);
        LDSM4(qf[k16][0], qf[k16][1], qf[k16][2], qf[k16][3], uQh + off);
    }

    float o[8][4];
#pragma unroll
    for (int j = 0; j < 8; j++)
#pragma unroll
        for (int e = 0; e < 4; e++) o[j][e] = 0.0f;
    float mi0 = -1e30f, mi1 = -1e30f, li0 = 0.0f, li1 = 0.0f;

    const int qrow0 = qt * BQ + wid * 16 + (lane >> 2);
    const int qrow1 = qrow0 + 8;
    const int kcbase = 2 * (lane & 3);
    const int wrow_max = qt * BQ + wid * 16 + 15;   // warp's last q row

    int stg = 0;   // stage holding tile kt
    for (int kt = 0; kt <= ktmax; kt++) {
        CP_WAIT1();
        __syncthreads();

        // issue next+2 tile load into the free third stage BEFORE compute
        const int lstg = (stg + 2 >= ANSTG) ? stg + 2 - ANSTG : stg + 2;
        if (kt + 2 <= ktmax) load_tile(kt + 2, lstg);
        CP_COMMIT();

        if (kt * BK <= wrow_max) {   // warp has at least one unmasked key
            const uint32_t sstage = uKV + 2u * (uint32_t)(stg * KVSTAGE);
            const uint32_t uKh = sstage;
            const uint32_t uVh = sstage + 2u * (64 * KSTR);

            // ---- S = Q @ K^T (exp2 domain), fp16 single pass ----
            float s[8][4];
#pragma unroll
            for (int j = 0; j < 8; j++)
#pragma unroll
                for (int e = 0; e < 4; e++) s[j][e] = 0.0f;

#pragma unroll
            for (int k16 = 0; k16 < 4; k16++) {
                const int kel = 16 * k16;
                uint32_t kh[4][4];
#pragma unroll
                for (int ng = 0; ng < 4; ng++) {
                    const uint32_t off =
                        2u * ((16 * ng + b_row) * KSTR + kel + b_koff);
                    LDSM4(kh[ng][0], kh[ng][1], kh[ng][2], kh[ng][3],
                          uKh + off);
                }
#pragma unroll
                for (int j = 0; j < 8; j++)
                    mma_f16(s[j], qf[k16], &kh[j >> 1][2 * (j & 1)]);
            }

            // ---- causal mask ----
            if (kt * BK + BK - 1 > qrow0) {
#pragma unroll
                for (int j = 0; j < 8; j++) {
                    const int kc = kt * BK + 8 * j + kcbase;
                    if (kc > qrow0) s[j][0] = -1e30f;
                    if (kc + 1 > qrow0) s[j][1] = -1e30f;
                }
            }
            if (kt * BK + BK - 1 > qrow1) {
#pragma unroll
                for (int j = 0; j < 8; j++) {
                    const int kc = kt * BK + 8 * j + kcbase;
                    if (kc > qrow1) s[j][2] = -1e30f;
                    if (kc + 1 > qrow1) s[j][3] = -1e30f;
                }
            }

            // ---- online softmax (exp2) ----
            float mx0 = s[0][0], mx1 = s[0][2];
#pragma unroll
            for (int j = 0; j < 8; j++) {
                mx0 = fmaxf(mx0, fmaxf(s[j][0], s[j][1]));
                mx1 = fmaxf(mx1, fmaxf(s[j][2], s[j][3]));
            }
            mx0 = fmaxf(mx0, __shfl_xor_sync(0xffffffffu, mx0, 1));
            mx0 = fmaxf(mx0, __shfl_xor_sync(0xffffffffu, mx0, 2));
            mx1 = fmaxf(mx1, __shfl_xor_sync(0xffffffffu, mx1, 1));
            mx1 = fmaxf(mx1, __shfl_xor_sync(0xffffffffu, mx1, 2));

            const float mn0 = fmaxf(mi0, mx0);
            const float mn1 = fmaxf(mi1, mx1);
            const float cr0 = ex2f(mi0 - mn0);
            const float cr1 = ex2f(mi1 - mn1);

            float rs0 = 0.0f, rs1 = 0.0f;
#pragma unroll
            for (int j = 0; j < 8; j++) {
                s[j][0] = ex2f(s[j][0] - mn0);
                s[j][1] = ex2f(s[j][1] - mn0);
                s[j][2] = ex2f(s[j][2] - mn1);
                s[j][3] = ex2f(s[j][3] - mn1);
                rs0 += s[j][0] + s[j][1];
                rs1 += s[j][2] + s[j][3];
            }
            rs0 += __shfl_xor_sync(0xffffffffu, rs0, 1);
            rs0 += __shfl_xor_sync(0xffffffffu, rs0, 2);
            rs1 += __shfl_xor_sync(0xffffffffu, rs1, 1);
            rs1 += __shfl_xor_sync(0xffffffffu, rs1, 2);
            li0 = li0 * cr0 + rs0;
            li1 = li1 * cr1 + rs1;
            mi0 = mn0;
            mi1 = mn1;

#pragma unroll
            for (int j = 0; j < 8; j++) {
                o[j][0] *= cr0;
                o[j][1] *= cr0;
                o[j][2] *= cr1;
                o[j][3] *= cr1;
            }

            // ---- O += P @ V (fp16 single pass) ----
#pragma unroll
            for (int t = 0; t < 4; t++) {
                uint32_t ph[4];
                {
                    const float* p0 = s[2 * t];
                    const float* p1 = s[2 * t + 1];
                    ph[0] = pkh(p0[0], p0[1]);
                    ph[1] = pkh(p0[2], p0[3]);
                    ph[2] = pkh(p1[0], p1[1]);
                    ph[3] = pkh(p1[2], p1[3]);
                }
                const int kel = 16 * t;
                uint32_t vh[4][4];
#pragma unroll
                for (int ng = 0; ng < 4; ng++) {
                    const uint32_t off =
                        2u * ((kel + v_kr) * KSTR + 16 * ng + v_nc);
                    LDSM4T(vh[ng][0], vh[ng][1], vh[ng][2], vh[ng][3],
                           uVh + off);
                }
#pragma unroll
                for (int j = 0; j < 8; j++)
                    mma_f16(o[j], ph, &vh[j >> 1][2 * (j & 1)]);
            }
        }
        stg = (stg + 1 >= ANSTG) ? 0 : stg + 1;
    }

    // ---- normalize + store fp16 to g_ao [b, s, h*64+d] ----
    const float inv0 = 1.0f / li0;
    const float inv1 = 1.0f / li1;
    const size_t o0 = ((size_t)b * NS + qrow0) * NHID + h * HDIM;
    const size_t o1 = ((size_t)b * NS + qrow1) * NHID + h * HDIM;
#pragma unroll
    for (int j = 0; j < 8; j++) {
        const int d = 8 * j + kcbase;
        *(uint32_t*)&g_ao[o0 + d] = pkh(o[j][0] * inv0, o[j][1] * inv0);
        *(uint32_t*)&g_ao[o1 + d] = pkh(o[j][2] * inv1, o[j][3] * inv1);
    }
}

// ---------------------------------------------------------------------------
extern "C" void kernel_launch(void* const* d_in, const int* in_sizes, int n_in,
                              void* d_out, int out_size) {
    const float* x  = (const float*)d_in[0];
    const float* Wq = (const float*)d_in[1];
    const float* bq = (const float*)d_in[2];
    const float* Wk = (const float*)d_in[3];
    const float* bk = (const float*)d_in[4];
    const float* Wv = (const float*)d_in[5];
    const float* bv = (const float*)d_in[6];
    const float* Wo = (const float*)d_in[7];
    const float* bo = (const float*)d_in[8];
    float* out = (float*)d_out;

    const int GEMM_SMEM = GNSTG * GSTAGE * 2;                   // 61440 B
    const int ATTN_SMEM = (128 * KSTR + ANSTG * KVSTAGE) * 2;   // 73728 B
    cudaFuncSetAttribute(gemm_mma<0>, cudaFuncAttributeMaxDynamicSharedMemorySize,
                         GEMM_SMEM);
    cudaFuncSetAttribute(gemm_mma<1>, cudaFuncAttributeMaxDynamicSharedMemorySize,
                         GEMM_SMEM);
    cudaFuncSetAttribute(attn_mma, cudaFuncAttributeMaxDynamicSharedMemorySize,
                         ATTN_SMEM);

    rope_table<<<NS * 32 / 256, 256>>>();

    // 4M (x) + 4x1M (weights) elems, 4 per thread
    cvt_all<<<(MM * NHID + 4 * NHID * NHID) / 1024, 256>>>(x, Wq, Wk, Wv, Wo);

    gemm_mma<0><<<dim3(NHID / 128, MM / 128, 3), 256, GEMM_SMEM>>>(bq, bk, bv,
                                                                   nullptr);

    rope_apply<<<2 * NB * NHEADS * NS * 8 / 256, 256>>>();

    attn_mma<<<dim3(NS / BQ, NHEADS, NB), 256, ATTN_SMEM>>>();

    gemm_mma<1><<<dim3(NHID / 128, MM / 128), 256, GEMM_SMEM>>>(bo, nullptr,
                                                                nullptr, out);
}

// round 17
// speedup vs baseline: 2.7757x; 1.0680x over previous
#include <cuda_runtime.h>
#include <cuda_bf16.h>
#include <cuda_fp16.h>
#include <stdint.h>
#include <cstdint>
#include <math.h>

#define NB 2
#define NS 2048
#define NHID 1024
#define NHEADS 16
#define HDIM 64
#define MM (NB * NS)   // 4096

// ---------------- scratch (static device globals; no allocation) ----------
__device__ float g_cos[NS * 32];                 // rope tables [s][d]
__device__ float g_sin[NS * 32];
__device__ float g_q[NB * NHEADS * NS * HDIM];   // fp32 pre-rope [b,h,s,d]
__device__ float g_k[NB * NHEADS * NS * HDIM];

// fp16 operands
__device__ __half g_x[MM * NHID];                // x fp16
__device__ __half g_w[4 * NHID * NHID];          // Wq,Wk,Wv,Wo fp16
__device__ __half g_ao[MM * NHID];               // attention output fp16
// attention operands: q/k/v fp16 (q pre-scaled), [b,h,s,d]
__device__ __half g_qh[NB * NHEADS * NS * HDIM];
__device__ __half g_kh[NB * NHEADS * NS * HDIM];
__device__ __half g_vh[NB * NHEADS * NS * HDIM];

// Q pre-scale: 0.125 * log2(e)  (softmax runs in exp2 domain)
#define QSCALE 0.18033688011112043f

// ---------------- mma.sync helpers (base sm_103 ISA) ------------------------
__device__ __forceinline__ uint32_t smem_u32(const void* p) {
    uint32_t a;
    asm("{ .reg .u64 t; cvta.to.shared.u64 t, %1; cvt.u32.u64 %0, t; }"
        : "=r"(a) : "l"(p));
    return a;
}
#define LDSM4(r0, r1, r2, r3, addr)                                          \
    asm volatile("ldmatrix.sync.aligned.m8n8.x4.shared.b16 {%0,%1,%2,%3}, [%4];" \
                 : "=r"(r0), "=r"(r1), "=r"(r2), "=r"(r3) : "r"(addr))
#define LDSM4T(r0, r1, r2, r3, addr)                                         \
    asm volatile(                                                            \
        "ldmatrix.sync.aligned.m8n8.x4.trans.shared.b16 {%0,%1,%2,%3}, [%4];" \
        : "=r"(r0), "=r"(r1), "=r"(r2), "=r"(r3) : "r"(addr))

__device__ __forceinline__ void mma_f16(float* d, const uint32_t* a,
                                        const uint32_t* b) {
    asm volatile(
        "mma.sync.aligned.m16n8k16.row.col.f32.f16.f16.f32 "
        "{%0,%1,%2,%3}, {%4,%5,%6,%7}, {%8,%9}, {%0,%1,%2,%3};"
        : "+f"(d[0]), "+f"(d[1]), "+f"(d[2]), "+f"(d[3])
        : "r"(a[0]), "r"(a[1]), "r"(a[2]), "r"(a[3]), "r"(b[0]), "r"(b[1]));
}

__device__ __forceinline__ uint32_t pkh(float a, float b) {
    __half2 t = __floats2half2_rn(a, b);
    return *(uint32_t*)&t;
}
__device__ __forceinline__ float ex2f(float x) {
    float y;
    asm("ex2.approx.ftz.f32 %0, %1;" : "=f"(y) : "f"(x));
    return y;
}

// ---------------- cp.async helpers -----------------------------------------
__device__ __forceinline__ void cpa16(uint32_t dst, const void* src) {
    asm volatile("cp.async.cg.shared.global [%0], [%1], 16;"
                 :: "r"(dst), "l"(src));
}
#define CP_COMMIT() asm volatile("cp.async.commit_group;" ::: "memory")
#define CP_WAIT1() asm volatile("cp.async.wait_group 1;" ::: "memory")
#define CP_WAIT0() asm volatile("cp.async.wait_group 0;" ::: "memory")

// ---------------------------------------------------------------------------
// Merged conversion: x and Wq..Wo -> single fp16, one launch.
// ---------------------------------------------------------------------------
__global__ __launch_bounds__(256) void cvt_all(const float* __restrict__ x,
                                               const float* __restrict__ Wq,
                                               const float* __restrict__ Wk,
                                               const float* __restrict__ Wv,
                                               const float* __restrict__ Wo) {
    const size_t i = 4ull * ((size_t)blockIdx.x * blockDim.x + threadIdx.x);
    const size_t XN = (size_t)MM * NHID;     // 4M
    const size_t WN = (size_t)NHID * NHID;   // 1M (2^20)
    const float* s;
    __half* d;
    if (i < XN) {
        s = x + i;
        d = g_x + i;
    } else {
        const size_t j = i - XN;
        const int w = (int)(j >> 20);
        const size_t o = j & (WN - 1);
        s = ((w == 0) ? Wq : (w == 1) ? Wk : (w == 2) ? Wv : Wo) + o;
        d = g_w + (size_t)w * WN + o;
    }
    float4 v = *(const float4*)s;
    *(uint32_t*)(d)     = pkh(v.x, v.y);
    *(uint32_t*)(d + 2) = pkh(v.z, v.w);
}

// ---------------------------------------------------------------------------
// RoPE cos/sin table (fp64, 65536 entries)
// ---------------------------------------------------------------------------
__global__ void rope_table() {
    const int t = blockIdx.x * blockDim.x + threadIdx.x;
    const int d = t & 31;
    const int s = t >> 5;
    const double inv = exp2(-(double)d * 0.41524101186092029);
    double sd, cd;
    sincos((double)s * inv, &sd, &cd);
    g_cos[t] = (float)cd;
    g_sin[t] = (float)sd;
}

// ---------------------------------------------------------------------------
// RoPE apply: reads fp32 q/k, rotates, stores fp16 (Q scaled by QSCALE).
// ---------------------------------------------------------------------------
__global__ __launch_bounds__(256) void rope_apply() {
    int t = blockIdx.x * blockDim.x + threadIdx.x;
    const int half = NB * NHEADS * NS * 8;
    const bool isq = (t < half);
    if (!isq) t -= half;
    const int dg = t & 7;
    const int s = (t >> 3) & (NS - 1);
    const int bh = t >> 14;

    const float4 c4 = *(const float4*)&g_cos[s * 32 + dg * 4];
    const float4 s4 = *(const float4*)&g_sin[s * 32 + dg * 4];

    const size_t off = ((size_t)bh * NS + s) * HDIM + dg * 4;
    const float* p = (isq ? g_q : g_k) + off;
    float4 x1 = *(const float4*)(p);
    float4 x2 = *(const float4*)(p + 32);
    float4 r1, r2;
    r1.x = x1.x * c4.x - x2.x * s4.x;  r2.x = x2.x * c4.x + x1.x * s4.x;
    r1.y = x1.y * c4.y - x2.y * s4.y;  r2.y = x2.y * c4.y + x1.y * s4.y;
    r1.z = x1.z * c4.z - x2.z * s4.z;  r2.z = x2.z * c4.z + x1.z * s4.z;
    r1.w = x1.w * c4.w - x2.w * s4.w;  r2.w = x2.w * c4.w + x1.w * s4.w;
    if (isq) {
        r1.x *= QSCALE; r1.y *= QSCALE; r1.z *= QSCALE; r1.w *= QSCALE;
        r2.x *= QSCALE; r2.y *= QSCALE; r2.z *= QSCALE; r2.w *= QSCALE;
    }
    __half* dh = (isq ? g_qh : g_kh) + off;
    *(uint32_t*)(dh)      = pkh(r1.x, r1.y);
    *(uint32_t*)(dh + 2)  = pkh(r1.z, r1.w);
    *(uint32_t*)(dh + 32) = pkh(r2.x, r2.y);
    *(uint32_t*)(dh + 34) = pkh(r2.z, r2.w);
}

// ---------------------------------------------------------------------------
// fp16 HMMA GEMM, single-pass, 3-stage cp.async pipeline, ONE barrier per
// K-chunk (load for c+2 issued into the disjoint third stage before compute).
// PROJ=0: z=0/1 -> fp32 g_q/g_k (rope applied separately), z=2 -> fp16 V.
// PROJ=1: out projection from g_ao to Cout fp32.
// ---------------------------------------------------------------------------
#define KC2 32
#define NKC2 (NHID / KC2)   // 32
#define GSTR 40
#define GSTAGE (2 * 128 * GSTR)     // fp16 elems per stage (A, W)
#define GNSTG 3

template <int PROJ>
__global__ __launch_bounds__(256) void gemm_mma(const float* __restrict__ b0p,
                                                const float* __restrict__ b1p,
                                                const float* __restrict__ b2p,
                                                float* __restrict__ Cout) {
    extern __shared__ __half sb[];

    const int tid = threadIdx.x;
    const int wid = tid >> 5;
    const int lane = tid & 31;
    const int wr = wid >> 2;
    const int wc = wid & 3;

    const int n0 = blockIdx.x * 128;
    const int m0 = blockIdx.y * 128;
    const int z = PROJ ? 3 : blockIdx.z;

    const __half* A = PROJ ? g_ao : g_x;
    const __half* W = g_w + (size_t)z * NHID * NHID;
    const float* bias = PROJ ? b0p : (z == 0 ? b0p : (z == 1 ? b1p : b2p));

    const __half* gsrc[2] = {A + (size_t)m0 * NHID, W + (size_t)n0 * NHID};

    float acc[4][4][4];
#pragma unroll
    for (int mt = 0; mt < 4; mt++)
#pragma unroll
        for (int nt = 0; nt < 4; nt++)
#pragma unroll
            for (int e = 0; e < 4; e++) acc[mt][nt][e] = 0.0f;

    const uint32_t uS = smem_u32(sb);

    auto load_chunk = [&](int c, int stage) {
        const int kc = c * KC2;
        const uint32_t sdst = uS + 2u * (uint32_t)(stage * GSTAGE);
#pragma unroll
        for (int t = 0; t < 2; t++) {
            const uint32_t db = sdst + 2u * (uint32_t)(t * 128 * GSTR);
            const __half* src = gsrc[t];
#pragma unroll
            for (int i = 0; i < 2; i++) {
                const int idx = tid + 256 * i;
                const int row = idx >> 2;
                const int seg = idx & 3;
                cpa16(db + 2u * (uint32_t)(row * GSTR + seg * 8),
                      src + (size_t)row * NHID + kc + seg * 8);
            }
        }
    };

    const int a_row = lane & 15;
    const int a_koff = (lane >> 4) * 8;
    const int b_row = (lane & 7) + ((lane >> 4) & 1) * 8;
    const int b_koff = ((lane >> 3) & 1) * 8;

    load_chunk(0, 0);
    CP_COMMIT();
    load_chunk(1, 1);
    CP_COMMIT();

    int stg = 0;   // stage holding chunk c
    for (int c = 0; c < NKC2; c++) {
        CP_WAIT1();
        __syncthreads();

        // issue the next+2 load into the free third stage BEFORE compute
        const int lstg = (stg + 2 >= GNSTG) ? stg + 2 - GNSTG : stg + 2;
        if (c + 2 < NKC2) load_chunk(c + 2, lstg);
        CP_COMMIT();

        const uint32_t sstage = uS + 2u * (uint32_t)(stg * GSTAGE);
        const uint32_t uA = sstage;
        const uint32_t uW = sstage + 2u * (128 * GSTR);

#pragma unroll
        for (int k16 = 0; k16 < 2; k16++) {
            const int kel = k16 * 16;
            uint32_t ah[4][4], bh[8];
#pragma unroll
            for (int mt = 0; mt < 4; mt++) {
                const uint32_t off =
                    2u * ((64 * wr + 16 * mt + a_row) * GSTR + kel + a_koff);
                LDSM4(ah[mt][0], ah[mt][1], ah[mt][2], ah[mt][3], uA + off);
            }
#pragma unroll
            for (int np = 0; np < 2; np++) {
                const uint32_t off =
                    2u * ((32 * wc + 16 * np + b_row) * GSTR + kel + b_koff);
                LDSM4(bh[4 * np], bh[4 * np + 1], bh[4 * np + 2], bh[4 * np + 3],
                      uW + off);
            }
#pragma unroll
            for (int mt = 0; mt < 4; mt++)
#pragma unroll
                for (int nt = 0; nt < 4; nt++)
                    mma_f16(acc[mt][nt], ah[mt],
                            &bh[4 * (nt >> 1) + 2 * (nt & 1)]);
        }
        stg = (stg + 1 >= GNSTG) ? 0 : stg + 1;
    }

    // ---- epilogue ----
    const int mrow = (lane >> 2);
    const int ncol = (lane & 3) * 2;
#pragma unroll
    for (int mt = 0; mt < 4; mt++) {
#pragma unroll
        for (int half = 0; half < 2; half++) {
            const int m = m0 + 64 * wr + 16 * mt + mrow + 8 * half;
#pragma unroll
            for (int nt = 0; nt < 4; nt++) {
                const int n = n0 + 32 * wc + 8 * nt + ncol;
                float v0 = acc[mt][nt][2 * half] + bias[n];
                float v1 = acc[mt][nt][2 * half + 1] + bias[n + 1];
                if (PROJ) {
                    *(float2*)&Cout[(size_t)m * NHID + n] = make_float2(v0, v1);
                } else {
                    const int bb = m >> 11;
                    const int s = m & (NS - 1);
                    const int h = n >> 6;
                    const int d = n & (HDIM - 1);
                    const size_t o =
                        (((size_t)(bb * NHEADS + h) * NS + s) * HDIM + d);
                    if (z == 2) {   // V: store fp16
                        *(uint32_t*)&g_vh[o] = pkh(v0, v1);
                    } else {
                        float* dst = (z == 0) ? g_q : g_k;
                        *(float2*)&dst[o] = make_float2(v0, v1);
                    }
                }
            }
        }
    }
}

// ---------------------------------------------------------------------------
// Flash attention, pure fp16 HMMA, CAUSAL WORK PAIRING:
// each CTA processes q-tiles {NQT-1-p, p} -> constant 34 tile-units/CTA,
// grid 256 CTAs = one balanced wave (296 slots).
// Per tile: Q fragments hoisted to registers; 3-stage cp.async KV ring,
// one barrier per tile; exp2-domain softmax; masked-warp skip.
// ---------------------------------------------------------------------------
#define BQ 128
#define NQT (NS / BQ)             // 16
#define BK 64
#define KSTR 72
#define KVSTAGE (2 * 64 * KSTR)   // fp16 elems per stage (kh,vh)
#define ANSTG 3

__global__ __launch_bounds__(256, 2) void attn_mma() {
    extern __shared__ __half sa_[];
    __half* sQh = sa_;                    // 128*72 (staging for Q hoist)
    __half* sKV = sa_ + 128 * KSTR;       // 3 stages of (kh, vh)

    const int h = blockIdx.y;
    const int b = blockIdx.z;
    const int tid = threadIdx.x;
    const int wid = tid >> 5;
    const int lane = tid & 31;

    const size_t bhoff = (size_t)(b * NHEADS + h) * NS * HDIM;
    const __half* kvsrc[2] = {g_kh + bhoff, g_vh + bhoff};

    const uint32_t uQh = smem_u32(sQh);
    const uint32_t uKV = smem_u32(sKV);

    auto load_tile = [&](int kt, int stage) {
        const uint32_t sdst = uKV + 2u * (uint32_t)(stage * KVSTAGE);
        const size_t gb = (size_t)kt * BK * HDIM;
#pragma unroll
        for (int t = 0; t < 2; t++) {
            const __half* src = kvsrc[t] + gb;
            const uint32_t db = sdst + 2u * (uint32_t)(t * 64 * KSTR);
#pragma unroll
            for (int i = 0; i < 2; i++) {
                const int idx = tid + 256 * i;
                const int row = idx >> 3;
                const int seg = idx & 7;
                cpa16(db + 2u * (uint32_t)(row * KSTR + seg * 8),
                      src + row * HDIM + seg * 8);
            }
        }
    };

    const int a_row = lane & 15;
    const int a_koff = (lane >> 4) * 8;
    const int b_row = (lane & 7) + ((lane >> 4) & 1) * 8;
    const int b_koff = ((lane >> 3) & 1) * 8;
    const int v_kr = (lane & 7) + 8 * ((lane >> 3) & 1);
    const int v_nc = 8 * (lane >> 4);
    const int kcbase = 2 * (lane & 3);

    for (int ps = 0; ps < 2; ps++) {
        const int qt = (ps == 0) ? (NQT - 1 - (int)blockIdx.x)
                                 : (int)blockIdx.x;

        // drain any stragglers, protect sQh/sKV reuse across sub-tiles
        CP_WAIT0();
        __syncthreads();

        // ---- stage Q tile to smem ----
        {
            const int row = tid >> 1;
            const int c0 = (tid & 1) * 32;
            const __half* sh =
                g_qh + bhoff + ((size_t)qt * BQ + row) * HDIM + c0;
            __half* dh = sQh + row * KSTR + c0;
#pragma unroll
            for (int j = 0; j < 4; j++)
                *(uint4*)(dh + 8 * j) = *(const uint4*)(sh + 8 * j);
        }

        const int ktmax = 2 * qt + 1;   // >= 1 always
        load_tile(0, 0);
        CP_COMMIT();
        load_tile(1, 1);
        CP_COMMIT();

        // ---- hoist Q fragments to registers ----
        __syncthreads();
        uint32_t qf[4][4];
#pragma unroll
        for (int k16 = 0; k16 < 4; k16++) {
            const uint32_t off =
                2u * ((wid * 16 + a_row) * KSTR + 16 * k16 + a_koff);
            LDSM4(qf[k16][0], qf[k16][1], qf[k16][2], qf[k16][3], uQh + off);
        }

        float o[8][4];
#pragma unroll
        for (int j = 0; j < 8; j++)
#pragma unroll
            for (int e = 0; e < 4; e++) o[j][e] = 0.0f;
        float mi0 = -1e30f, mi1 = -1e30f, li0 = 0.0f, li1 = 0.0f;

        const int qrow0 = qt * BQ + wid * 16 + (lane >> 2);
        const int qrow1 = qrow0 + 8;
        const int wrow_max = qt * BQ + wid * 16 + 15;

        int stg = 0;   // stage holding tile kt
        for (int kt = 0; kt <= ktmax; kt++) {
            CP_WAIT1();
            __syncthreads();

            const int lstg = (stg + 2 >= ANSTG) ? stg + 2 - ANSTG : stg + 2;
            if (kt + 2 <= ktmax) load_tile(kt + 2, lstg);
            CP_COMMIT();

            if (kt * BK <= wrow_max) {
                const uint32_t sstage = uKV + 2u * (uint32_t)(stg * KVSTAGE);
                const uint32_t uKh = sstage;
                const uint32_t uVh = sstage + 2u * (64 * KSTR);

                // ---- S = Q @ K^T (exp2 domain) ----
                float s[8][4];
#pragma unroll
                for (int j = 0; j < 8; j++)
#pragma unroll
                    for (int e = 0; e < 4; e++) s[j][e] = 0.0f;

#pragma unroll
                for (int k16 = 0; k16 < 4; k16++) {
                    const int kel = 16 * k16;
                    uint32_t kh[4][4];
#pragma unroll
                    for (int ng = 0; ng < 4; ng++) {
                        const uint32_t off =
                            2u * ((16 * ng + b_row) * KSTR + kel + b_koff);
                        LDSM4(kh[ng][0], kh[ng][1], kh[ng][2], kh[ng][3],
                              uKh + off);
                    }
#pragma unroll
                    for (int j = 0; j < 8; j++)
                        mma_f16(s[j], qf[k16], &kh[j >> 1][2 * (j & 1)]);
                }

                // ---- causal mask ----
                if (kt * BK + BK - 1 > qrow0) {
#pragma unroll
                    for (int j = 0; j < 8; j++) {
                        const int kc = kt * BK + 8 * j + kcbase;
                        if (kc > qrow0) s[j][0] = -1e30f;
                        if (kc + 1 > qrow0) s[j][1] = -1e30f;
                    }
                }
                if (kt * BK + BK - 1 > qrow1) {
#pragma unroll
                    for (int j = 0; j < 8; j++) {
                        const int kc = kt * BK + 8 * j + kcbase;
                        if (kc > qrow1) s[j][2] = -1e30f;
                        if (kc + 1 > qrow1) s[j][3] = -1e30f;
                    }
                }

                // ---- online softmax (exp2) ----
                float mx0 = s[0][0], mx1 = s[0][2];
#pragma unroll
                for (int j = 0; j < 8; j++) {
                    mx0 = fmaxf(mx0, fmaxf(s[j][0], s[j][1]));
                    mx1 = fmaxf(mx1, fmaxf(s[j][2], s[j][3]));
                }
                mx0 = fmaxf(mx0, __shfl_xor_sync(0xffffffffu, mx0, 1));
                mx0 = fmaxf(mx0, __shfl_xor_sync(0xffffffffu, mx0, 2));
                mx1 = fmaxf(mx1, __shfl_xor_sync(0xffffffffu, mx1, 1));
                mx1 = fmaxf(mx1, __shfl_xor_sync(0xffffffffu, mx1, 2));

                const float mn0 = fmaxf(mi0, mx0);
                const float mn1 = fmaxf(mi1, mx1);
                const float cr0 = ex2f(mi0 - mn0);
                const float cr1 = ex2f(mi1 - mn1);

                float rs0 = 0.0f, rs1 = 0.0f;
#pragma unroll
                for (int j = 0; j < 8; j++) {
                    s[j][0] = ex2f(s[j][0] - mn0);
                    s[j][1] = ex2f(s[j][1] - mn0);
                    s[j][2] = ex2f(s[j][2] - mn1);
                    s[j][3] = ex2f(s[j][3] - mn1);
                    rs0 += s[j][0] + s[j][1];
                    rs1 += s[j][2] + s[j][3];
                }
                rs0 += __shfl_xor_sync(0xffffffffu, rs0, 1);
                rs0 += __shfl_xor_sync(0xffffffffu, rs0, 2);
                rs1 += __shfl_xor_sync(0xffffffffu, rs1, 1);
                rs1 += __shfl_xor_sync(0xffffffffu, rs1, 2);
                li0 = li0 * cr0 + rs0;
                li1 = li1 * cr1 + rs1;
                mi0 = mn0;
                mi1 = mn1;

#pragma unroll
                for (int j = 0; j < 8; j++) {
                    o[j][0] *= cr0;
                    o[j][1] *= cr0;
                    o[j][2] *= cr1;
                    o[j][3] *= cr1;
                }

                // ---- O += P @ V ----
#pragma unroll
                for (int t = 0; t < 4; t++) {
                    uint32_t ph[4];
                    {
                        const float* p0 = s[2 * t];
                        const float* p1 = s[2 * t + 1];
                        ph[0] = pkh(p0[0], p0[1]);
                        ph[1] = pkh(p0[2], p0[3]);
                        ph[2] = pkh(p1[0], p1[1]);
                        ph[3] = pkh(p1[2], p1[3]);
                    }
                    const int kel = 16 * t;
                    uint32_t vh[4][4];
#pragma unroll
                    for (int ng = 0; ng < 4; ng++) {
                        const uint32_t off =
                            2u * ((kel + v_kr) * KSTR + 16 * ng + v_nc);
                        LDSM4T(vh[ng][0], vh[ng][1], vh[ng][2], vh[ng][3],
                               uVh + off);
                    }
#pragma unroll
                    for (int j = 0; j < 8; j++)
                        mma_f16(o[j], ph, &vh[j >> 1][2 * (j & 1)]);
                }
            }
            stg = (stg + 1 >= ANSTG) ? 0 : stg + 1;
        }

        // ---- normalize + store fp16 to g_ao [b, s, h*64+d] ----
        const float inv0 = 1.0f / li0;
        const float inv1 = 1.0f / li1;
        const size_t o0 = ((size_t)b * NS + qrow0) * NHID + h * HDIM;
        const size_t o1 = ((size_t)b * NS + qrow1) * NHID + h * HDIM;
#pragma unroll
        for (int j = 0; j < 8; j++) {
            const int d = 8 * j + kcbase;
            *(uint32_t*)&g_ao[o0 + d] = pkh(o[j][0] * inv0, o[j][1] * inv0);
            *(uint32_t*)&g_ao[o1 + d] = pkh(o[j][2] * inv1, o[j][3] * inv1);
        }
    }
}

// ---------------------------------------------------------------------------
extern "C" void kernel_launch(void* const* d_in, const int* in_sizes, int n_in,
                              void* d_out, int out_size) {
    const float* x  = (const float*)d_in[0];
    const float* Wq = (const float*)d_in[1];
    const float* bq = (const float*)d_in[2];
    const float* Wk = (const float*)d_in[3];
    const float* bk = (const float*)d_in[4];
    const float* Wv = (const float*)d_in[5];
    const float* bv = (const float*)d_in[6];
    const float* Wo = (const float*)d_in[7];
    const float* bo = (const float*)d_in[8];
    float* out = (float*)d_out;

    const int GEMM_SMEM = GNSTG * GSTAGE * 2;                   // 61440 B
    const int ATTN_SMEM = (128 * KSTR + ANSTG * KVSTAGE) * 2;   // 73728 B
    cudaFuncSetAttribute(gemm_mma<0>, cudaFuncAttributeMaxDynamicSharedMemorySize,
                         GEMM_SMEM);
    cudaFuncSetAttribute(gemm_mma<1>, cudaFuncAttributeMaxDynamicSharedMemorySize,
                         GEMM_SMEM);
    cudaFuncSetAttribute(attn_mma, cudaFuncAttributeMaxDynamicSharedMemorySize,
                         ATTN_SMEM);

    rope_table<<<NS * 32 / 256, 256>>>();

    // 4M (x) + 4x1M (weights) elems, 4 per thread
    cvt_all<<<(MM * NHID + 4 * NHID * NHID) / 1024, 256>>>(x, Wq, Wk, Wv, Wo);

    gemm_mma<0><<<dim3(NHID / 128, MM / 128, 3), 256, GEMM_SMEM>>>(bq, bk, bv,
                                                                   nullptr);

    rope_apply<<<2 * NB * NHEADS * NS * 8 / 256, 256>>>();

    attn_mma<<<dim3(NQT / 2, NHEADS, NB), 256, ATTN_SMEM>>>();

    gemm_mma<1><<<dim3(NHID / 128, MM / 128), 256, GEMM_SMEM>>>(bo, nullptr,
                                                                nullptr, out);
}